// round 11
// baseline (speedup 1.0000x reference)
#include <cuda_runtime.h>
#include <cuda_bf16.h>
#include <math.h>
#include <stdint.h>

// ---------------- problem constants ----------------
constexpr int kB = 2;
constexpr int kT = 16;
constexpr int kN = 1024;
constexpr int kC = 2;
constexpr int kCtok = 256;
constexpr int kQ = 320;
constexpr int kI = 512;
constexpr int kCD = 1024;
constexpr int kFF = 1280;
constexpr long kHS = (long)kB * kT * kN * kQ;
constexpr long kTOK = (long)kB * kT * kN;        // 32768

// ---------------- fp32 scratch ----------------
static __device__ float g_hs[kHS];
static __device__ float g_v[(long)kB * kC * kCtok * kI];
static __device__ float g_scores[kTOK * kI];
static __device__ float g_akv[kTOK * kI];
static __device__ float g_vdmax[(long)kB * kCtok * kI];
static __device__ float g_vtokWo[(long)kB * kN * kQ];
static __device__ float g_aq[kTOK * kN];
static __device__ float g_ffb1i[2 * kFF];

// ---------------- bf16 scratch ----------------
static __device__ __nv_bfloat16 b_poset[kHS];
static __device__ __nv_bfloat16 b_ctxperm[(long)kB * 512 * kCD];
static __device__ __nv_bfloat16 b_ctx[(long)kB * kC * kCtok * kCD];
static __device__ __nv_bfloat16 b_WkT[(long)2 * kI * kCD];
static __device__ __nv_bfloat16 b_WvT[(long)2 * kI * kCD];
static __device__ __nv_bfloat16 b_Wanat[(long)2 * kQ * kI];
static __device__ __nv_bfloat16 b_Wqpad[(long)2 * 384 * kI];
static __device__ __nv_bfloat16 b_WoT[(long)2 * kQ * kI];
static __device__ __nv_bfloat16 b_ffw1T[(long)2 * kFF * kQ];
static __device__ __nv_bfloat16 b_ffw2T[(long)kQ * kFF];
static __device__ __nv_bfloat16 b_kP[(long)kB * 512 * kI];
static __device__ __nv_bfloat16 b_vT[(long)kB * kC * kI * kCtok];
static __device__ __nv_bfloat16 b_S[(long)kB * 512 * kQ];
static __device__ __nv_bfloat16 b_GT[(long)2 * kQ * 384];
static __device__ __nv_bfloat16 b_U[kTOK * kQ];
static __device__ __nv_bfloat16 b_scores[kTOK * kI];
static __device__ __nv_bfloat16 b_akv[kTOK * kI];
static __device__ __nv_bfloat16 b_akvWoT[(long)kB * kT * kQ * kN];
static __device__ __nv_bfloat16 b_aq[kTOK * kN];
static __device__ __nv_bfloat16 b_vtok[(long)kB * kN * kI];
static __device__ __nv_bfloat16 b_nh[kHS];
static __device__ __nv_bfloat16 b_gg[kTOK * kFF];

// ---------------- PTX helpers ----------------
__device__ __forceinline__ uint32_t smem_u32(const void* p) {
    return (uint32_t)__cvta_generic_to_shared(p);
}
__device__ __forceinline__ void cp16(uint32_t dst, const void* src, int src_bytes) {
    asm volatile("cp.async.cg.shared.global [%0], [%1], 16, %2;\n"
                 :: "r"(dst), "l"(src), "r"(src_bytes));
}
__device__ __forceinline__ void cp_commit() { asm volatile("cp.async.commit_group;\n"); }
template<int W> __device__ __forceinline__ void cp_wait() {
    asm volatile("cp.async.wait_group %0;\n" :: "n"(W));
}
__device__ __forceinline__ void mma16(float* d, const uint32_t* a, const uint32_t* b) {
    asm volatile(
        "mma.sync.aligned.m16n8k16.row.col.f32.bf16.bf16.f32 "
        "{%0,%1,%2,%3},{%4,%5,%6,%7},{%8,%9},{%0,%1,%2,%3};"
        : "+f"(d[0]), "+f"(d[1]), "+f"(d[2]), "+f"(d[3])
        : "r"(a[0]), "r"(a[1]), "r"(a[2]), "r"(a[3]), "r"(b[0]), "r"(b[1]));
}

// ---------------- bf16 NT tensor-core GEMM ----------------
// C(MxN) = alpha * A(MxK,bf16,row) * B(NxK,bf16,row)^T + epilogues.
// flags: 1 += C ; 2 max C ; 4 += bias[col] ; 8 write bf16 natural Cb ;
//        16 write bf16 transposed Cb ; 32 suppress fp32 write ;
//        256 += aux[((z>>4)*1024 + row)*ldaux + col]   (t-broadcast aux)
//        512 GEGLU pair epilogue (interleaved a/g cols -> Cb col/2, ldcb=N/2)
constexpr int SSTR = 40;

__global__ __launch_bounds__(256, 2)
void bgemm_k(const __nv_bfloat16* __restrict__ A, const __nv_bfloat16* __restrict__ Bm,
             const float* __restrict__ bias, const float* __restrict__ aux,
             float* __restrict__ C, __nv_bfloat16* __restrict__ Cb,
             int M, int N, int K, int lda, int ldb, int ldc, int ldcb, int ldaux,
             long strA, long strB, long strC, long strCb,
             int bDiv, float alpha, int flags)
{
    __shared__ __align__(16) __nv_bfloat16 sA[2][128 * SSTR];
    __shared__ __align__(16) __nv_bfloat16 sB[2][128 * SSTR];

    const int z = blockIdx.z;
    const __nv_bfloat16* Ap = A + (size_t)z * strA;
    const __nv_bfloat16* Bp = Bm + (size_t)(z / bDiv) * strB;
    float* Cp = C + (size_t)z * strC;
    __nv_bfloat16* Cbp = Cb + (size_t)z * strCb;
    const int m0 = blockIdx.y * 128, n0 = blockIdx.x * 128;
    const int tid = threadIdx.x;
    const int lane = tid & 31, warp = tid >> 5;
    const int wm = warp & 1, wn = warp >> 1;
    const int gid = lane >> 2, tig = lane & 3;

    float acc[4][4][4];
    #pragma unroll
    for (int i = 0; i < 4; i++)
        #pragma unroll
        for (int j = 0; j < 4; j++)
            #pragma unroll
            for (int r = 0; r < 4; r++) acc[i][j][r] = 0.f;

    const int kTiles = K >> 5;

    auto load_tile = [&](int buf, int kt) {
        const int k0 = kt << 5;
        #pragma unroll
        for (int j = 0; j < 2; j++) {
            int i = tid + 256 * j;
            int r = i >> 2, c = i & 3;
            cp16(smem_u32(&sA[buf][r * SSTR + c * 8]),
                 Ap + (size_t)(m0 + r) * lda + k0 + c * 8, 16);
        }
        #pragma unroll
        for (int j = 0; j < 2; j++) {
            int i = tid + 256 * j;
            int r = i >> 2, c = i & 3;
            int gn = n0 + r;
            cp16(smem_u32(&sB[buf][r * SSTR + c * 8]),
                 Bp + (size_t)gn * ldb + k0 + c * 8, gn < N ? 16 : 0);
        }
        cp_commit();
    };

    auto compute_tile = [&](int buf) {
        #pragma unroll
        for (int s = 0; s < 2; s++) {
            const int kk = s * 16;
            uint32_t af[4][4], bf[4][2];
            #pragma unroll
            for (int mt = 0; mt < 4; mt++) {
                int rm = wm * 64 + mt * 16;
                const __nv_bfloat16* base = &sA[buf][(rm + gid) * SSTR + kk + 2 * tig];
                af[mt][0] = *(const uint32_t*)(base);
                af[mt][1] = *(const uint32_t*)(base + 8 * SSTR);
                af[mt][2] = *(const uint32_t*)(base + 8);
                af[mt][3] = *(const uint32_t*)(base + 8 * SSTR + 8);
            }
            #pragma unroll
            for (int nt = 0; nt < 4; nt++) {
                int cb = wn * 32 + nt * 8 + gid;
                const __nv_bfloat16* base = &sB[buf][cb * SSTR + kk + 2 * tig];
                bf[nt][0] = *(const uint32_t*)(base);
                bf[nt][1] = *(const uint32_t*)(base + 8);
            }
            #pragma unroll
            for (int mt = 0; mt < 4; mt++)
                #pragma unroll
                for (int nt = 0; nt < 4; nt++)
                    mma16(acc[mt][nt], af[mt], bf[nt]);
        }
    };

    load_tile(0, 0);
    for (int kt = 0; kt < kTiles; kt++) {
        if (kt + 1 < kTiles) {
            load_tile((kt + 1) & 1, kt + 1);
            cp_wait<1>();
        } else {
            cp_wait<0>();
        }
        __syncthreads();
        compute_tile(kt & 1);
        __syncthreads();
    }

    #pragma unroll
    for (int mt = 0; mt < 4; mt++) {
        #pragma unroll
        for (int nt = 0; nt < 4; nt++) {
            int row0 = m0 + wm * 64 + mt * 16 + gid;
            int col0 = n0 + wn * 32 + nt * 8 + tig * 2;
            if (flags & 512) {
                float ba = bias[col0], bg = bias[col0 + 1];
                #pragma unroll
                for (int h = 0; h < 2; h++) {
                    int rr = row0 + h * 8;
                    float a = alpha * acc[mt][nt][2 * h] + ba;
                    float g = alpha * acc[mt][nt][2 * h + 1] + bg;
                    float gg = a * 0.5f * g * (1.f + erff(g * 0.70710678118654752f));
                    Cbp[(size_t)rr * ldcb + (col0 >> 1)] = __float2bfloat16(gg);
                }
                continue;
            }
            #pragma unroll
            for (int r = 0; r < 4; r++) {
                int rr = row0 + (r >> 1) * 8;
                int cc = col0 + (r & 1);
                if (cc >= N) continue;
                float vv = alpha * acc[mt][nt][r];
                size_t off = (size_t)rr * ldc + cc;
                if (flags & 4)   vv += bias[cc];
                if (flags & 256) vv += aux[(((size_t)(z >> 4)) * 1024 + rr) * ldaux + cc];
                if (flags & 1) vv += Cp[off];
                if (flags & 2) vv = fmaxf(vv, Cp[off]);
                if (!(flags & 32)) Cp[off] = vv;
                if (flags & 8)  Cbp[(size_t)rr * ldcb + cc] = __float2bfloat16(vv);
                if (flags & 16) Cbp[(size_t)cc * ldcb + rr] = __float2bfloat16(vv);
            }
        }
    }
}

static void gemm(const __nv_bfloat16* A, const __nv_bfloat16* B, const float* bias,
                 const float* aux, float* C, __nv_bfloat16* Cb,
                 int M, int N, int K, int lda, int ldb, int ldc, int ldcb, int ldaux,
                 long sA, long sB, long sC, long sCb, int bDiv, int batch,
                 float alpha, int flags)
{
    dim3 gr((N + 127) / 128, M / 128, batch);
    bgemm_k<<<gr, 256>>>(A, B, bias, aux, C, Cb, M, N, K,
                         lda, ldb, ldc, ldcb, ldaux,
                         sA, sB, sC, sCb, bDiv, alpha, flags);
}

// ---------------- merged prologue 1: hs copy + pose transpose + ctxperm ----------------
constexpr long P1_S0 = kHS;                 // hs copy
constexpr long P1_S1 = P1_S0 + kHS;         // poset
constexpr long P1_S2 = P1_S1 + (long)kB * 512 * kCD;  // ctxperm
__global__ void pcperm_k(const float* __restrict__ hidden, const float* __restrict__ pose,
                         const float* __restrict__ ctx,
                         float* __restrict__ hs, __nv_bfloat16* __restrict__ poset,
                         __nv_bfloat16* __restrict__ ctxperm)
{
    long idx = (long)blockIdx.x * blockDim.x + threadIdx.x;
    if (idx < P1_S0) {
        hs[idx] = hidden[idx];
    } else if (idx < P1_S1) {
        long i = idx - P1_S0;
        int d = (int)(i % kQ);
        long r = i / kQ;
        int n = (int)(r % kN); r /= kN;
        int t = (int)(r % kT); int b = (int)(r / kT);
        int h = n >> 5, w = n & 31;
        poset[i] = __float2bfloat16(ctx ? pose[(((((size_t)b * kQ + d) * kT + t) * 32 + h) * 32) + w]
                                        : 0.f);
    } else if (idx < P1_S2) {
        long i = idx - P1_S1;
        int k = (int)(i % kCD);
        long r0 = i / kCD;
        int r = (int)(r0 % 512); int b = (int)(r0 / 512);
        int n = ((r & 255) << 1) | (r >> 8);
        ctxperm[i] = __float2bfloat16(ctx[(((size_t)b * kC + (n >> 8)) * kCtok + (n & 255)) * kCD + k]);
    }
}

// ---------------- merged prologue 2: remaining weight/context preps ----------------
constexpr long P2_S0 = (long)kB * kC * kCtok * kCD;          // ctxB
constexpr long P2_S1 = P2_S0 + (long)2 * kCD * kI;           // WvT
constexpr long P2_S2 = P2_S1 + (long)2 * 384 * kI;           // WqP
constexpr long P2_S3 = P2_S2 + (long)2 * kI * kQ;            // WoT
constexpr long P2_S4 = P2_S3 + (long)2 * kFF * kQ;           // fw1T
constexpr long P2_S5 = P2_S4 + 2 * kFF;                      // ffb1i
constexpr long P2_S6 = P2_S5 + (long)kFF * kQ;               // fw2T
__global__ void prep2_k(const float* __restrict__ ctx, const float* __restrict__ Wv,
                        const float* __restrict__ Wq, const float* __restrict__ Wo,
                        const float* __restrict__ ffw1, const float* __restrict__ ffb1,
                        const float* __restrict__ ffw2,
                        __nv_bfloat16* __restrict__ ctxB, __nv_bfloat16* __restrict__ WvT,
                        __nv_bfloat16* __restrict__ WqP, __nv_bfloat16* __restrict__ WoT,
                        __nv_bfloat16* __restrict__ fw1T, float* __restrict__ ffb1i,
                        __nv_bfloat16* __restrict__ fw2T)
{
    long idx = (long)blockIdx.x * blockDim.x + threadIdx.x;
    if (idx < P2_S0) {
        ctxB[idx] = __float2bfloat16(ctx[idx]);
    } else if (idx < P2_S1) {
        long i = idx - P2_S0;
        int r = (int)(i % kCD);
        long q = i / kCD;
        int c = (int)(q % kI);
        int b = (int)(q / kI);
        WvT[i] = __float2bfloat16(Wv[((size_t)b * kCD + r) * kI + c]);
    } else if (idx < P2_S2) {
        long i = idx - P2_S1;
        int c = (int)(i % kI);
        long q = i / kI;
        int r = (int)(q % 384);
        int blk = (int)(q / 384);
        WqP[i] = (r < kQ) ? __float2bfloat16(Wq[((size_t)blk * kQ + r) * kI + c])
                          : __float2bfloat16(0.f);
    } else if (idx < P2_S3) {
        long i = idx - P2_S2;
        int r = (int)(i % kI);
        long q = i / kI;
        int c = (int)(q % kQ);
        int b = (int)(q / kQ);
        WoT[i] = __float2bfloat16(Wo[((size_t)b * kI + r) * kQ + c]);
    } else if (idx < P2_S4) {
        long i = idx - P2_S3;
        int k = (int)(i % kQ);
        int e = (int)(i / kQ);
        int oc = (e & 1) ? (kFF + (e >> 1)) : (e >> 1);
        fw1T[i] = __float2bfloat16(ffw1[(size_t)k * (2 * kFF) + oc]);
    } else if (idx < P2_S5) {
        int e = (int)(idx - P2_S4);
        int oc = (e & 1) ? (kFF + (e >> 1)) : (e >> 1);
        ffb1i[e] = ffb1[oc];
    } else if (idx < P2_S6) {
        long i = idx - P2_S5;
        int r = (int)(i % kFF);
        int c = (int)(i / kFF);
        fw2T[i] = __float2bfloat16(ffw2[(size_t)r * kQ + c]);
    }
}

// ---------------- LayerNorm (bf16 out) ----------------
__global__ void ln_k(const float* __restrict__ x, const float* __restrict__ w,
                     const float* __restrict__ b, __nv_bfloat16* __restrict__ y, int cols)
{
    int row = blockIdx.x;
    const float* xp = x + (size_t)row * cols;
    float s1 = 0.f, s2 = 0.f;
    for (int i = threadIdx.x; i < cols; i += blockDim.x) {
        float v = xp[i]; s1 += v; s2 += v * v;
    }
    __shared__ float r1[256], r2[256];
    r1[threadIdx.x] = s1; r2[threadIdx.x] = s2;
    __syncthreads();
    for (int s = 128; s > 0; s >>= 1) {
        if (threadIdx.x < s) { r1[threadIdx.x] += r1[threadIdx.x + s]; r2[threadIdx.x] += r2[threadIdx.x + s]; }
        __syncthreads();
    }
    float mean = r1[0] / cols;
    float var = r2[0] / cols - mean * mean;
    float rstd = rsqrtf(var + 1e-5f);
    __nv_bfloat16* yp = y + (size_t)row * cols;
    for (int i = threadIdx.x; i < cols; i += blockDim.x)
        yp[i] = __float2bfloat16((xp[i] - mean) * rstd * w[i] + b[i]);
}

// ---------------- softmax kv groups (256 cols, + agent_bias[m,nc2]) -> bf16 ----------------
__global__ void softmax_kv_k(const float* __restrict__ s, const float* __restrict__ abias,
                             __nv_bfloat16* __restrict__ ob)
{
    int gr = blockIdx.x;
    int c2 = blockIdx.y;
    int m = gr & 1023;
    const float* p = s + (size_t)gr * 512 + c2 * 256;
    __nv_bfloat16* po = ob + (size_t)gr * 512 + c2 * 256;
    int tid = threadIdx.x;
    float v = p[tid] + abias[(size_t)m * 256 + tid];
    __shared__ float red[256];
    red[tid] = v; __syncthreads();
    for (int st = 128; st; st >>= 1) { if (tid < st) red[tid] = fmaxf(red[tid], red[tid + st]); __syncthreads(); }
    float mx = red[0]; __syncthreads();
    float e = __expf(v - mx);
    red[tid] = e; __syncthreads();
    for (int st = 128; st; st >>= 1) { if (tid < st) red[tid] += red[tid + st]; __syncthreads(); }
    po[tid] = __float2bfloat16(e / red[0]);
}

// ---------------- softmax query rows (1024 cols, + query_bias[n,m]) -> bf16 ----------------
__global__ void softmax_aq_k(const float* __restrict__ s, const float* __restrict__ qbias,
                             __nv_bfloat16* __restrict__ ob)
{
    int gr = blockIdx.x;
    int n = gr & 1023;
    const float* p = s + (size_t)gr * 1024;
    __nv_bfloat16* po = ob + (size_t)gr * 1024;
    const float* bp = qbias + (size_t)n * 1024;
    int tid = threadIdx.x;
    float v[4];
    float mx = -1e30f;
    #pragma unroll
    for (int k = 0; k < 4; k++) { v[k] = p[tid + k * 256] + bp[tid + k * 256]; mx = fmaxf(mx, v[k]); }
    __shared__ float red[256];
    red[tid] = mx; __syncthreads();
    for (int st = 128; st; st >>= 1) { if (tid < st) red[tid] = fmaxf(red[tid], red[tid + st]); __syncthreads(); }
    mx = red[0]; __syncthreads();
    float sum = 0.f;
    #pragma unroll
    for (int k = 0; k < 4; k++) { v[k] = __expf(v[k] - mx); sum += v[k]; }
    red[tid] = sum; __syncthreads();
    for (int st = 128; st; st >>= 1) { if (tid < st) red[tid] += red[tid + st]; __syncthreads(); }
    float inv = 1.f / red[0];
    #pragma unroll
    for (int k = 0; k < 4; k++) po[tid + k * 256] = __float2bfloat16(v[k] * inv);
}

// ---------------- conv (Wa natural -> bf16) ----------------
__global__ void conv_k(const float* __restrict__ s, __nv_bfloat16* __restrict__ d, long n)
{
    long idx = (long)blockIdx.x * blockDim.x + threadIdx.x;
    if (idx < n) d[idx] = __float2bfloat16(s[idx]);
}

// ---------------- transpose convert (Wk) ----------------
__global__ void tconv_k(const float* __restrict__ s, __nv_bfloat16* __restrict__ d,
                        int R, int Cc, int batch)
{
    long n = (long)R * Cc * batch;
    long idx = (long)blockIdx.x * blockDim.x + threadIdx.x;
    if (idx >= n) return;
    int r = (int)(idx % R);
    long q = idx / R;
    int c = (int)(q % Cc);
    int b = (int)(q / Cc);
    d[idx] = __float2bfloat16(s[((size_t)b * R + r) * Cc + c]);
}

// ---------------- depthwise 3x3 conv + frame max + bias ----------------
__global__ void dwconv_k(const float* __restrict__ v, const float* __restrict__ wgt,
                         const float* __restrict__ bias, float* __restrict__ out)
{
    int pix = blockIdx.x & 255;
    int b = blockIdx.x >> 8;
    int e = threadIdx.x;
    int h = pix >> 4, w = pix & 15;
    float wv[9];
    #pragma unroll
    for (int t9 = 0; t9 < 9; t9++) wv[t9] = wgt[e * 9 + t9];
    float best = -1e30f;
    #pragma unroll
    for (int c = 0; c < 2; c++) {
        float s = 0.f;
        #pragma unroll
        for (int dh = -1; dh <= 1; dh++)
            #pragma unroll
            for (int dw = -1; dw <= 1; dw++) {
                int hh = h + dh, ww = w + dw;
                if (hh < 0 || hh > 15 || ww < 0 || ww > 15) continue;
                s += v[((size_t)(b * kC + c) * kCtok + hh * 16 + ww) * kI + e] * wv[(dh + 1) * 3 + (dw + 1)];
            }
        best = fmaxf(best, s);
    }
    out[((size_t)b * kCtok + pix) * kI + e] = best + bias[e];
}

// ---------------- bilinear x2 upsample -> bf16 ----------------
__global__ void upsample_k(const float* __restrict__ vd, __nv_bfloat16* __restrict__ vtok)
{
    int opix = blockIdx.x & 1023;
    int b = blockIdx.x >> 10;
    int e = threadIdx.x;
    int y = opix >> 5, x = opix & 31;
    int py = y >> 1, px = x >> 1;
    int y0, y1, x0, x1; float wy0, wy1, wx0, wx1;
    if (y & 1) { y0 = py; y1 = min(py + 1, 15); wy0 = 0.75f; wy1 = 0.25f; }
    else       { y0 = max(py - 1, 0); y1 = py;  wy0 = 0.25f; wy1 = 0.75f; }
    if (x & 1) { x0 = px; x1 = min(px + 1, 15); wx0 = 0.75f; wx1 = 0.25f; }
    else       { x0 = max(px - 1, 0); x1 = px;  wx0 = 0.25f; wx1 = 0.75f; }
    const float* base = vd + (size_t)b * kCtok * kI;
    float r = wy0 * wx0 * base[(size_t)(y0 * 16 + x0) * kI + e]
            + wy0 * wx1 * base[(size_t)(y0 * 16 + x1) * kI + e]
            + wy1 * wx0 * base[(size_t)(y1 * 16 + x0) * kI + e]
            + wy1 * wx1 * base[(size_t)(y1 * 16 + x1) * kI + e];
    vtok[((size_t)b * kN + opix) * kI + e] = __float2bfloat16(r);
}

// ---------------- launch ----------------
extern "C" void kernel_launch(void* const* d_in, const int* in_sizes, int n_in,
                              void* d_out, int out_size)
{
    const float* hidden     = (const float*)d_in[0];
    const float* context    = (const float*)d_in[1];
    const float* pose       = (const float*)d_in[2];
    const float* Wq         = (const float*)d_in[3];
    const float* Wk         = (const float*)d_in[4];
    const float* Wv         = (const float*)d_in[5];
    const float* Wa         = (const float*)d_in[6];
    const float* agent_bias = (const float*)d_in[7];
    const float* query_bias = (const float*)d_in[8];
    const float* dwc_w      = (const float*)d_in[9];
    const float* dwc_b      = (const float*)d_in[10];
    const float* Wo         = (const float*)d_in[11];
    const float* norm_w     = (const float*)d_in[12];
    const float* norm_b     = (const float*)d_in[13];
    const float* ffln_w     = (const float*)d_in[14];
    const float* ffln_b     = (const float*)d_in[15];
    const float* ff_w1      = (const float*)d_in[16];
    const float* ff_b1      = (const float*)d_in[17];
    const float* ff_w2      = (const float*)d_in[18];
    const float* ff_b2      = (const float*)d_in[19];

    float *hs, *vP, *scoresP, *akvP, *vdP, *vtokWoP, *aqP, *ffb1iP;
    cudaGetSymbolAddress((void**)&hs, g_hs);
    cudaGetSymbolAddress((void**)&vP, g_v);
    cudaGetSymbolAddress((void**)&scoresP, g_scores);
    cudaGetSymbolAddress((void**)&akvP, g_akv);
    cudaGetSymbolAddress((void**)&vdP, g_vdmax);
    cudaGetSymbolAddress((void**)&vtokWoP, g_vtokWo);
    cudaGetSymbolAddress((void**)&aqP, g_aq);
    cudaGetSymbolAddress((void**)&ffb1iP, g_ffb1i);

    __nv_bfloat16 *posetB, *ctxpermB, *ctxB, *WkT, *WvT, *WaN, *WqP, *WoT, *fw1T, *fw2T,
                  *kPB, *vTB, *SB, *GTB, *UB, *scoresB, *akvB, *akvWoT, *aqB, *vtokB, *nhB, *ggB;
    cudaGetSymbolAddress((void**)&posetB, b_poset);
    cudaGetSymbolAddress((void**)&ctxpermB, b_ctxperm);
    cudaGetSymbolAddress((void**)&ctxB, b_ctx);
    cudaGetSymbolAddress((void**)&WkT, b_WkT);
    cudaGetSymbolAddress((void**)&WvT, b_WvT);
    cudaGetSymbolAddress((void**)&WaN, b_Wanat);
    cudaGetSymbolAddress((void**)&WqP, b_Wqpad);
    cudaGetSymbolAddress((void**)&WoT, b_WoT);
    cudaGetSymbolAddress((void**)&fw1T, b_ffw1T);
    cudaGetSymbolAddress((void**)&fw2T, b_ffw2T);
    cudaGetSymbolAddress((void**)&kPB, b_kP);
    cudaGetSymbolAddress((void**)&vTB, b_vT);
    cudaGetSymbolAddress((void**)&SB, b_S);
    cudaGetSymbolAddress((void**)&GTB, b_GT);
    cudaGetSymbolAddress((void**)&UB, b_U);
    cudaGetSymbolAddress((void**)&scoresB, b_scores);
    cudaGetSymbolAddress((void**)&akvB, b_akv);
    cudaGetSymbolAddress((void**)&akvWoT, b_akvWoT);
    cudaGetSymbolAddress((void**)&aqB, b_aq);
    cudaGetSymbolAddress((void**)&vtokB, b_vtok);
    cudaGetSymbolAddress((void**)&nhB, b_nh);
    cudaGetSymbolAddress((void**)&ggB, b_gg);

    const float SCALE = 0.125f;
    auto cdiv = [](long a, long b) { return (int)((a + b - 1) / b); };

    // --- per-blk chains ---
    auto head = [&](int blk) {   // kP -> S -> scores
        const __nv_bfloat16* WkT_b = WkT + (size_t)blk * kI * kCD;
        const __nv_bfloat16* WaN_b = WaN + (size_t)blk * kQ * kI;
        gemm(ctxpermB, WkT_b, nullptr, nullptr, nullptr, kPB,
             512, kI, kCD, kCD, kCD, 0, kI, 0,
             512L * kCD, 0, 0, 512L * kI, 1, kB, 1.f, 8 | 32);
        gemm(kPB, WaN_b, nullptr, nullptr, nullptr, SB,
             512, kQ, kI, kI, kI, 0, kQ, 0,
             512L * kI, 0, 0, 512L * kQ, 1, kB, 1.f, 8 | 32);
        gemm(posetB, SB, nullptr, nullptr, scoresP, nullptr,
             kN, 512, kQ, kQ, kQ, 512, 0, 0,
             (long)kN * kQ, 512L * kQ, (long)kN * 512, 0, kT, kB * kT, SCALE, 0);
    };
    auto rest = [&](int blk) {
        const __nv_bfloat16* WaN_b = WaN + (size_t)blk * kQ * kI;
        const __nv_bfloat16* WqP_b = WqP + (size_t)blk * 384 * kI;
        const __nv_bfloat16* WoT_b = WoT + (size_t)blk * kQ * kI;
        __nv_bfloat16* GT_b = GTB + (size_t)blk * kQ * 384;
        const float* ab_b = agent_bias + (size_t)blk * kN * kCtok;
        const float* qb_b = query_bias + (size_t)blk * kN * kN;
        const float* dw_b = dwc_w + (size_t)blk * kI * 9;
        const float* db_b = dwc_b + (size_t)blk * kI;

        softmax_kv_k<<<dim3(kB * kT * kN, 2), 256>>>(scoresP, ab_b, scoresB);
        // G^T = (Wq_pad @ Wa^T)^T
        gemm(WqP_b, WaN_b, nullptr, nullptr, nullptr, GT_b,
             384, kQ, kI, kI, kI, 0, 384, 0,
             0, 0, 0, 0, 1, 1, 1.f, 16 | 32);
        // v proj
        gemm(ctxB, WvT + (size_t)blk * kI * kCD, nullptr, nullptr, vP, vTB,
             kCtok, kI, kCD, kCD, kCD, kI, kCtok, 0,
             (long)kCtok * kCD, 0, (long)kCtok * kI, (long)kI * kCtok, 1, kB * kC, 1.f, 16);
        // agent_kv
        gemm(scoresB, vTB, nullptr, nullptr, akvP, nullptr,
             kN, kI, kCtok, 512, kCtok, kI, 0, 0,
             (long)kN * 512, (long)kC * kI * kCtok, (long)kN * kI, 0, kT, kB * kT, 1.f, 0);
        gemm(scoresB + 256, vTB + (size_t)kI * kCtok, nullptr, nullptr, akvP, akvB,
             kN, kI, kCtok, 512, kCtok, kI, kI, 0,
             (long)kN * 512, (long)kC * kI * kCtok, (long)kN * kI, (long)kN * kI, kT, kB * kT,
             1.f, 2 | 8 | 32);
        // akvWo^T
        gemm(akvB, WoT_b, nullptr, nullptr, akvP, akvWoT,
             kN, kQ, kI, kI, kI, kQ, kN, 0,
             (long)kN * kI, 0, 0, (long)kQ * kN, 1, kB * kT, 1.f, 16 | 32);
        // dwconv + upsample + vtokWo
        dwconv_k<<<kB * kCtok, kI>>>(vP, dw_b, db_b, vdP);
        upsample_k<<<kB * kN, kI>>>(vdP, vtokB);
        gemm(vtokB, WoT_b, nullptr, nullptr, vtokWoP, nullptr,
             kN, kQ, kI, kI, kI, kQ, 0, 0,
             (long)kN * kI, 0, (long)kN * kQ, 0, 1, kB, 1.f, 0);
        // LN + U + aq + softmax + final
        ln_k<<<(int)kTOK, 256>>>(hs, norm_w, norm_b, nhB, kQ);
        gemm(nhB, GT_b, nullptr, nullptr, nullptr, UB,
             (int)kTOK, kQ, kQ, kQ, 384, 0, kQ, 0,
             0, 0, 0, 0, 1, 1, 1.f, 8 | 32);
        gemm(UB, posetB, nullptr, nullptr, aqP, nullptr,
             kN, kN, kQ, kQ, kQ, kN, 0, 0,
             (long)kN * kQ, (long)kN * kQ, (long)kN * kN, 0, 1, kB * kT, SCALE, 0);
        softmax_aq_k<<<(int)kTOK, 256>>>(aqP, qb_b, aqB);
        gemm(aqB, akvWoT, nullptr, vtokWoP, hs, nullptr,
             kN, kQ, kN, kN, kN, kQ, 0, kQ,
             (long)kN * kN, (long)kQ * kN, (long)kN * kQ, 0, 1, kB * kT,
             1.f, 1 | 256);
    };

    // launch 1: merged hs copy + pose transpose + ctxperm
    pcperm_k<<<cdiv(P1_S2, 256), 256>>>(hidden, pose, context, hs, posetB, ctxpermB);
    // launch 2-3: the two preps scores needs
    tconv_k<<<cdiv((long)2 * kCD * kI, 256), 256>>>(Wk, WkT, kCD, kI, 2);
    conv_k<<<cdiv((long)2 * kQ * kI, 256), 256>>>(Wa, WaN, (long)2 * kQ * kI);
    // launches 4-6: kP, S, scores (blk0) — #6 is the profiled scores GEMM
    head(0);
    // launch 7: all remaining preps, merged
    prep2_k<<<cdiv(P2_S6, 256), 256>>>(context, Wv, Wq, Wo, ff_w1, ff_b1, ff_w2,
                                       ctxB, WvT, WqP, WoT, fw1T, ffb1iP, fw2T);
    rest(0);
    head(1);
    rest(1);

    // ---- FF ----
    ln_k<<<(int)kTOK, 256>>>(hs, ffln_w, ffln_b, nhB, kQ);
    gemm(nhB, fw1T, ffb1iP, nullptr, nullptr, ggB,
         (int)kTOK, 2 * kFF, kQ, kQ, kQ, 0, kFF, 0,
         0, 0, 0, 0, 1, 1, 1.f, 4 | 32 | 512);
    gemm(ggB, fw2T, ff_b2, nullptr, hs, nullptr,
         (int)kTOK, kQ, kFF, kFF, kFF, kQ, 0, 0,
         0, 0, 0, 0, 1, 1, 1.f, 1 | 4);

    cudaMemcpyAsync(d_out, hs, sizeof(float) * kHS, cudaMemcpyDeviceToDevice, 0);
}

// round 12
// speedup vs baseline: 1.0783x; 1.0783x over previous
#include <cuda_runtime.h>
#include <cuda_bf16.h>
#include <math.h>
#include <stdint.h>

// ---------------- problem constants ----------------
constexpr int kB = 2;
constexpr int kT = 16;
constexpr int kN = 1024;
constexpr int kC = 2;
constexpr int kCtok = 256;
constexpr int kQ = 320;
constexpr int kI = 512;
constexpr int kCD = 1024;
constexpr int kFF = 1280;
constexpr long kHS = (long)kB * kT * kN * kQ;
constexpr long kTOK = (long)kB * kT * kN;        // 32768

// ---------------- fp32 scratch (hs-free side doubled over blk) ----------------
static __device__ float g_hs[kHS];
static __device__ float g_v[(long)2 * kB * kC * kCtok * kI];
static __device__ float g_scores[(long)2 * kTOK * kI];
static __device__ float g_akv[(long)2 * kTOK * kI];
static __device__ float g_vdmax[(long)2 * kB * kCtok * kI];
static __device__ float g_vtokWo[(long)2 * kB * kN * kQ];
static __device__ float g_aq[kTOK * kN];
static __device__ float g_ffb1i[2 * kFF];

// ---------------- bf16 scratch ----------------
static __device__ __nv_bfloat16 b_poset[kHS];
static __device__ __nv_bfloat16 b_ctxperm[(long)kB * 512 * kCD];
static __device__ __nv_bfloat16 b_ctx[(long)kB * kC * kCtok * kCD];
static __device__ __nv_bfloat16 b_WkT[(long)2 * kI * kCD];
static __device__ __nv_bfloat16 b_WvT[(long)2 * kI * kCD];
static __device__ __nv_bfloat16 b_Wanat[(long)2 * kQ * kI];
static __device__ __nv_bfloat16 b_Wqpad[(long)2 * 384 * kI];
static __device__ __nv_bfloat16 b_WoT[(long)2 * kQ * kI];
static __device__ __nv_bfloat16 b_ffw1T[(long)2 * kFF * kQ];
static __device__ __nv_bfloat16 b_ffw2T[(long)kQ * kFF];
static __device__ __nv_bfloat16 b_kP[(long)2 * kB * 512 * kI];
static __device__ __nv_bfloat16 b_vT[(long)2 * kB * kC * kI * kCtok];
static __device__ __nv_bfloat16 b_S[(long)2 * kB * 512 * kQ];
static __device__ __nv_bfloat16 b_GT[(long)2 * kQ * 384];
static __device__ __nv_bfloat16 b_U[kTOK * kQ];
static __device__ __nv_bfloat16 b_scores[(long)2 * kTOK * kI];
static __device__ __nv_bfloat16 b_akv[(long)2 * kTOK * kI];
static __device__ __nv_bfloat16 b_akvWoT[(long)2 * kB * kT * kQ * kN];
static __device__ __nv_bfloat16 b_aq[kTOK * kN];
static __device__ __nv_bfloat16 b_vtok[(long)2 * kB * kN * kI];
static __device__ __nv_bfloat16 b_nh[kHS];
static __device__ __nv_bfloat16 b_gg[kTOK * kFF];

// ---------------- PTX helpers ----------------
__device__ __forceinline__ uint32_t smem_u32(const void* p) {
    return (uint32_t)__cvta_generic_to_shared(p);
}
__device__ __forceinline__ void cp16(uint32_t dst, const void* src, int src_bytes) {
    asm volatile("cp.async.cg.shared.global [%0], [%1], 16, %2;\n"
                 :: "r"(dst), "l"(src), "r"(src_bytes));
}
__device__ __forceinline__ void cp_commit() { asm volatile("cp.async.commit_group;\n"); }
template<int W> __device__ __forceinline__ void cp_wait() {
    asm volatile("cp.async.wait_group %0;\n" :: "n"(W));
}
__device__ __forceinline__ void mma16(float* d, const uint32_t* a, const uint32_t* b) {
    asm volatile(
        "mma.sync.aligned.m16n8k16.row.col.f32.bf16.bf16.f32 "
        "{%0,%1,%2,%3},{%4,%5,%6,%7},{%8,%9},{%0,%1,%2,%3};"
        : "+f"(d[0]), "+f"(d[1]), "+f"(d[2]), "+f"(d[3])
        : "r"(a[0]), "r"(a[1]), "r"(a[2]), "r"(a[3]), "r"(b[0]), "r"(b[1]));
}

// ---------------- bf16 NT tensor-core GEMM ----------------
// C(MxN) = alpha * A(MxK,bf16,row) * B(NxK,bf16,row)^T + epilogues.
// Batch: A index = aMod ? (z % aMod) : z ;  B index = z / bDiv ; C/Cb index = z.
// flags: 1 += C ; 2 max C ; 4 += bias[col] ; 8 bf16 natural Cb ; 16 bf16 transposed Cb ;
//        32 suppress fp32 write ; 256 += aux[((z>>4)*1024+row)*ldaux+col] ;
//        512 GEGLU pair epilogue (interleaved a/g cols -> Cb col/2, ldcb=N/2)
constexpr int SSTR = 40;

__global__ __launch_bounds__(256, 2)
void bgemm_k(const __nv_bfloat16* __restrict__ A, const __nv_bfloat16* __restrict__ Bm,
             const float* __restrict__ bias, const float* __restrict__ aux,
             float* __restrict__ C, __nv_bfloat16* __restrict__ Cb,
             int M, int N, int K, int lda, int ldb, int ldc, int ldcb, int ldaux,
             long strA, long strB, long strC, long strCb,
             int aMod, int bDiv, float alpha, int flags)
{
    __shared__ __align__(16) __nv_bfloat16 sA[2][128 * SSTR];
    __shared__ __align__(16) __nv_bfloat16 sB[2][128 * SSTR];

    const int z = blockIdx.z;
    const int za = aMod ? (z % aMod) : z;
    const __nv_bfloat16* Ap = A + (size_t)za * strA;
    const __nv_bfloat16* Bp = Bm + (size_t)(z / bDiv) * strB;
    float* Cp = C + (size_t)z * strC;
    __nv_bfloat16* Cbp = Cb + (size_t)z * strCb;
    const int m0 = blockIdx.y * 128, n0 = blockIdx.x * 128;
    const int tid = threadIdx.x;
    const int lane = tid & 31, warp = tid >> 5;
    const int wm = warp & 1, wn = warp >> 1;
    const int gid = lane >> 2, tig = lane & 3;

    float acc[4][4][4];
    #pragma unroll
    for (int i = 0; i < 4; i++)
        #pragma unroll
        for (int j = 0; j < 4; j++)
            #pragma unroll
            for (int r = 0; r < 4; r++) acc[i][j][r] = 0.f;

    const int kTiles = K >> 5;

    auto load_tile = [&](int buf, int kt) {
        const int k0 = kt << 5;
        #pragma unroll
        for (int j = 0; j < 2; j++) {
            int i = tid + 256 * j;
            int r = i >> 2, c = i & 3;
            cp16(smem_u32(&sA[buf][r * SSTR + c * 8]),
                 Ap + (size_t)(m0 + r) * lda + k0 + c * 8, 16);
        }
        #pragma unroll
        for (int j = 0; j < 2; j++) {
            int i = tid + 256 * j;
            int r = i >> 2, c = i & 3;
            int gn = n0 + r;
            cp16(smem_u32(&sB[buf][r * SSTR + c * 8]),
                 Bp + (size_t)gn * ldb + k0 + c * 8, gn < N ? 16 : 0);
        }
        cp_commit();
    };

    auto compute_tile = [&](int buf) {
        #pragma unroll
        for (int s = 0; s < 2; s++) {
            const int kk = s * 16;
            uint32_t af[4][4], bf[4][2];
            #pragma unroll
            for (int mt = 0; mt < 4; mt++) {
                int rm = wm * 64 + mt * 16;
                const __nv_bfloat16* base = &sA[buf][(rm + gid) * SSTR + kk + 2 * tig];
                af[mt][0] = *(const uint32_t*)(base);
                af[mt][1] = *(const uint32_t*)(base + 8 * SSTR);
                af[mt][2] = *(const uint32_t*)(base + 8);
                af[mt][3] = *(const uint32_t*)(base + 8 * SSTR + 8);
            }
            #pragma unroll
            for (int nt = 0; nt < 4; nt++) {
                int cb = wn * 32 + nt * 8 + gid;
                const __nv_bfloat16* base = &sB[buf][cb * SSTR + kk + 2 * tig];
                bf[nt][0] = *(const uint32_t*)(base);
                bf[nt][1] = *(const uint32_t*)(base + 8);
            }
            #pragma unroll
            for (int mt = 0; mt < 4; mt++)
                #pragma unroll
                for (int nt = 0; nt < 4; nt++)
                    mma16(acc[mt][nt], af[mt], bf[nt]);
        }
    };

    load_tile(0, 0);
    for (int kt = 0; kt < kTiles; kt++) {
        if (kt + 1 < kTiles) {
            load_tile((kt + 1) & 1, kt + 1);
            cp_wait<1>();
        } else {
            cp_wait<0>();
        }
        __syncthreads();
        compute_tile(kt & 1);
        __syncthreads();
    }

    #pragma unroll
    for (int mt = 0; mt < 4; mt++) {
        #pragma unroll
        for (int nt = 0; nt < 4; nt++) {
            int row0 = m0 + wm * 64 + mt * 16 + gid;
            int col0 = n0 + wn * 32 + nt * 8 + tig * 2;
            if (flags & 512) {
                float ba = bias[col0], bg = bias[col0 + 1];
                #pragma unroll
                for (int h = 0; h < 2; h++) {
                    int rr = row0 + h * 8;
                    float a = alpha * acc[mt][nt][2 * h] + ba;
                    float g = alpha * acc[mt][nt][2 * h + 1] + bg;
                    float gg = a * 0.5f * g * (1.f + erff(g * 0.70710678118654752f));
                    Cbp[(size_t)rr * ldcb + (col0 >> 1)] = __float2bfloat16(gg);
                }
                continue;
            }
            #pragma unroll
            for (int r = 0; r < 4; r++) {
                int rr = row0 + (r >> 1) * 8;
                int cc = col0 + (r & 1);
                if (cc >= N) continue;
                float vv = alpha * acc[mt][nt][r];
                size_t off = (size_t)rr * ldc + cc;
                if (flags & 4)   vv += bias[cc];
                if (flags & 256) vv += aux[(((size_t)(z >> 4)) * 1024 + rr) * ldaux + cc];
                if (flags & 1) vv += Cp[off];
                if (flags & 2) vv = fmaxf(vv, Cp[off]);
                if (!(flags & 32)) Cp[off] = vv;
                if (flags & 8)  Cbp[(size_t)rr * ldcb + cc] = __float2bfloat16(vv);
                if (flags & 16) Cbp[(size_t)cc * ldcb + rr] = __float2bfloat16(vv);
            }
        }
    }
}

static void gemm(const __nv_bfloat16* A, const __nv_bfloat16* B, const float* bias,
                 const float* aux, float* C, __nv_bfloat16* Cb,
                 int M, int N, int K, int lda, int ldb, int ldc, int ldcb, int ldaux,
                 long sA, long sB, long sC, long sCb, int aMod, int bDiv, int batch,
                 float alpha, int flags)
{
    dim3 gr((N + 127) / 128, M / 128, batch);
    bgemm_k<<<gr, 256>>>(A, B, bias, aux, C, Cb, M, N, K,
                         lda, ldb, ldc, ldcb, ldaux,
                         sA, sB, sC, sCb, aMod, bDiv, alpha, flags);
}

// ---------------- merged prologue 1: hs copy + pose transpose + ctxperm ----------------
constexpr long P1_S0 = kHS;
constexpr long P1_S1 = P1_S0 + kHS;
constexpr long P1_S2 = P1_S1 + (long)kB * 512 * kCD;
__global__ void pcperm_k(const float* __restrict__ hidden, const float* __restrict__ pose,
                         const float* __restrict__ ctx,
                         float* __restrict__ hs, __nv_bfloat16* __restrict__ poset,
                         __nv_bfloat16* __restrict__ ctxperm)
{
    long idx = (long)blockIdx.x * blockDim.x + threadIdx.x;
    if (idx < P1_S0) {
        hs[idx] = hidden[idx];
    } else if (idx < P1_S1) {
        long i = idx - P1_S0;
        int d = (int)(i % kQ);
        long r = i / kQ;
        int n = (int)(r % kN); r /= kN;
        int t = (int)(r % kT); int b = (int)(r / kT);
        int h = n >> 5, w = n & 31;
        poset[i] = __float2bfloat16(pose[(((((size_t)b * kQ + d) * kT + t) * 32 + h) * 32) + w]);
    } else if (idx < P1_S2) {
        long i = idx - P1_S1;
        int k = (int)(i % kCD);
        long r0 = i / kCD;
        int r = (int)(r0 % 512); int b = (int)(r0 / 512);
        int n = ((r & 255) << 1) | (r >> 8);
        ctxperm[i] = __float2bfloat16(ctx[(((size_t)b * kC + (n >> 8)) * kCtok + (n & 255)) * kCD + k]);
    }
}

// ---------------- merged prologue 2: all weight/context preps ----------------
constexpr long Q_S0 = (long)kB * kC * kCtok * kCD;   // ctxB
constexpr long Q_S1 = Q_S0 + (long)2 * kCD * kI;     // WkT
constexpr long Q_S2 = Q_S1 + (long)2 * kQ * kI;      // WaN
constexpr long Q_S3 = Q_S2 + (long)2 * kCD * kI;     // WvT
constexpr long Q_S4 = Q_S3 + (long)2 * 384 * kI;     // WqP
constexpr long Q_S5 = Q_S4 + (long)2 * kI * kQ;      // WoT
constexpr long Q_S6 = Q_S5 + (long)2 * kFF * kQ;     // fw1T
constexpr long Q_S7 = Q_S6 + 2 * kFF;                // ffb1i
constexpr long Q_S8 = Q_S7 + (long)kFF * kQ;         // fw2T
__global__ void prep_k(const float* __restrict__ ctx, const float* __restrict__ Wk,
                       const float* __restrict__ Wa, const float* __restrict__ Wv,
                       const float* __restrict__ Wq, const float* __restrict__ Wo,
                       const float* __restrict__ ffw1, const float* __restrict__ ffb1,
                       const float* __restrict__ ffw2,
                       __nv_bfloat16* __restrict__ ctxB, __nv_bfloat16* __restrict__ WkT,
                       __nv_bfloat16* __restrict__ WaN, __nv_bfloat16* __restrict__ WvT,
                       __nv_bfloat16* __restrict__ WqP, __nv_bfloat16* __restrict__ WoT,
                       __nv_bfloat16* __restrict__ fw1T, float* __restrict__ ffb1i,
                       __nv_bfloat16* __restrict__ fw2T)
{
    long idx = (long)blockIdx.x * blockDim.x + threadIdx.x;
    if (idx < Q_S0) {
        ctxB[idx] = __float2bfloat16(ctx[idx]);
    } else if (idx < Q_S1) {
        long i = idx - Q_S0;
        int r = (int)(i % kCD);
        long q = i / kCD;
        int c = (int)(q % kI);
        int b = (int)(q / kI);
        WkT[i] = __float2bfloat16(Wk[((size_t)b * kCD + r) * kI + c]);
    } else if (idx < Q_S2) {
        long i = idx - Q_S1;
        WaN[i] = __float2bfloat16(Wa[i]);
    } else if (idx < Q_S3) {
        long i = idx - Q_S2;
        int r = (int)(i % kCD);
        long q = i / kCD;
        int c = (int)(q % kI);
        int b = (int)(q / kI);
        WvT[i] = __float2bfloat16(Wv[((size_t)b * kCD + r) * kI + c]);
    } else if (idx < Q_S4) {
        long i = idx - Q_S3;
        int c = (int)(i % kI);
        long q = i / kI;
        int r = (int)(q % 384);
        int blk = (int)(q / 384);
        WqP[i] = (r < kQ) ? __float2bfloat16(Wq[((size_t)blk * kQ + r) * kI + c])
                          : __float2bfloat16(0.f);
    } else if (idx < Q_S5) {
        long i = idx - Q_S4;
        int r = (int)(i % kI);
        long q = i / kI;
        int c = (int)(q % kQ);
        int b = (int)(q / kQ);
        WoT[i] = __float2bfloat16(Wo[((size_t)b * kI + r) * kQ + c]);
    } else if (idx < Q_S6) {
        long i = idx - Q_S5;
        int k = (int)(i % kQ);
        int e = (int)(i / kQ);
        int oc = (e & 1) ? (kFF + (e >> 1)) : (e >> 1);
        fw1T[i] = __float2bfloat16(ffw1[(size_t)k * (2 * kFF) + oc]);
    } else if (idx < Q_S7) {
        int e = (int)(idx - Q_S6);
        int oc = (e & 1) ? (kFF + (e >> 1)) : (e >> 1);
        ffb1i[e] = ffb1[oc];
    } else if (idx < Q_S8) {
        long i = idx - Q_S7;
        int r = (int)(i % kFF);
        int c = (int)(i / kFF);
        fw2T[i] = __float2bfloat16(ffw2[(size_t)r * kQ + c]);
    }
}

// ---------------- LayerNorm (bf16 out) ----------------
__global__ void ln_k(const float* __restrict__ x, const float* __restrict__ w,
                     const float* __restrict__ b, __nv_bfloat16* __restrict__ y, int cols)
{
    int row = blockIdx.x;
    const float* xp = x + (size_t)row * cols;
    float s1 = 0.f, s2 = 0.f;
    for (int i = threadIdx.x; i < cols; i += blockDim.x) {
        float v = xp[i]; s1 += v; s2 += v * v;
    }
    __shared__ float r1[256], r2[256];
    r1[threadIdx.x] = s1; r2[threadIdx.x] = s2;
    __syncthreads();
    for (int s = 128; s > 0; s >>= 1) {
        if (threadIdx.x < s) { r1[threadIdx.x] += r1[threadIdx.x + s]; r2[threadIdx.x] += r2[threadIdx.x + s]; }
        __syncthreads();
    }
    float mean = r1[0] / cols;
    float var = r2[0] / cols - mean * mean;
    float rstd = rsqrtf(var + 1e-5f);
    __nv_bfloat16* yp = y + (size_t)row * cols;
    for (int i = threadIdx.x; i < cols; i += blockDim.x)
        yp[i] = __float2bfloat16((xp[i] - mean) * rstd * w[i] + b[i]);
}

// ---------------- softmax kv groups, both blocks (256 cols + agent_bias) -> bf16 ----------------
__global__ void softmax_kv_k(const float* __restrict__ s, const float* __restrict__ abias,
                             __nv_bfloat16* __restrict__ ob)
{
    int gr = blockIdx.x;                 // [0, 2*kTOK)
    int c2 = blockIdx.y;
    int blk = gr >> 15;
    int m = gr & 1023;
    const float* p = s + (size_t)gr * 512 + c2 * 256;
    __nv_bfloat16* po = ob + (size_t)gr * 512 + c2 * 256;
    int tid = threadIdx.x;
    float v = p[tid] + abias[((size_t)blk * kN + m) * 256 + tid];
    __shared__ float red[256];
    red[tid] = v; __syncthreads();
    for (int st = 128; st; st >>= 1) { if (tid < st) red[tid] = fmaxf(red[tid], red[tid + st]); __syncthreads(); }
    float mx = red[0]; __syncthreads();
    float e = __expf(v - mx);
    red[tid] = e; __syncthreads();
    for (int st = 128; st; st >>= 1) { if (tid < st) red[tid] += red[tid + st]; __syncthreads(); }
    po[tid] = __float2bfloat16(e / red[0]);
}

// ---------------- softmax query rows (1024 cols, + query_bias[n,m]) -> bf16 ----------------
__global__ void softmax_aq_k(const float* __restrict__ s, const float* __restrict__ qbias,
                             __nv_bfloat16* __restrict__ ob)
{
    int gr = blockIdx.x;
    int n = gr & 1023;
    const float* p = s + (size_t)gr * 1024;
    __nv_bfloat16* po = ob + (size_t)gr * 1024;
    const float* bp = qbias + (size_t)n * 1024;
    int tid = threadIdx.x;
    float v[4];
    float mx = -1e30f;
    #pragma unroll
    for (int k = 0; k < 4; k++) { v[k] = p[tid + k * 256] + bp[tid + k * 256]; mx = fmaxf(mx, v[k]); }
    __shared__ float red[256];
    red[tid] = mx; __syncthreads();
    for (int st = 128; st; st >>= 1) { if (tid < st) red[tid] = fmaxf(red[tid], red[tid + st]); __syncthreads(); }
    mx = red[0]; __syncthreads();
    float sum = 0.f;
    #pragma unroll
    for (int k = 0; k < 4; k++) { v[k] = __expf(v[k] - mx); sum += v[k]; }
    red[tid] = sum; __syncthreads();
    for (int st = 128; st; st >>= 1) { if (tid < st) red[tid] += red[tid + st]; __syncthreads(); }
    float inv = 1.f / red[0];
    #pragma unroll
    for (int k = 0; k < 4; k++) po[tid + k * 256] = __float2bfloat16(v[k] * inv);
}

// ---------------- depthwise 3x3 conv + frame max + bias (both blocks) ----------------
__global__ void dwconv_k(const float* __restrict__ v, const float* __restrict__ wgt,
                         const float* __restrict__ bias, float* __restrict__ out)
{
    int pix = blockIdx.x & 255;
    int b = (blockIdx.x >> 8) & 1;
    int blk = blockIdx.x >> 9;
    int e = threadIdx.x;
    int h = pix >> 4, w = pix & 15;
    const float* wp = wgt + (size_t)blk * kI * 9;
    float wv[9];
    #pragma unroll
    for (int t9 = 0; t9 < 9; t9++) wv[t9] = wp[e * 9 + t9];
    float best = -1e30f;
    #pragma unroll
    for (int c = 0; c < 2; c++) {
        float s = 0.f;
        #pragma unroll
        for (int dh = -1; dh <= 1; dh++)
            #pragma unroll
            for (int dw = -1; dw <= 1; dw++) {
                int hh = h + dh, ww = w + dw;
                if (hh < 0 || hh > 15 || ww < 0 || ww > 15) continue;
                s += v[(((size_t)(blk * kB + b) * kC + c) * kCtok + hh * 16 + ww) * kI + e]
                     * wv[(dh + 1) * 3 + (dw + 1)];
            }
        best = fmaxf(best, s);
    }
    out[((size_t)(blk * kB + b) * kCtok + pix) * kI + e] = best + bias[(size_t)blk * kI + e];
}

// ---------------- bilinear x2 upsample -> bf16 (both blocks) ----------------
__global__ void upsample_k(const float* __restrict__ vd, __nv_bfloat16* __restrict__ vtok)
{
    int opix = blockIdx.x & 1023;
    int bb = blockIdx.x >> 10;           // blk*kB + b
    int e = threadIdx.x;
    int y = opix >> 5, x = opix & 31;
    int py = y >> 1, px = x >> 1;
    int y0, y1, x0, x1; float wy0, wy1, wx0, wx1;
    if (y & 1) { y0 = py; y1 = min(py + 1, 15); wy0 = 0.75f; wy1 = 0.25f; }
    else       { y0 = max(py - 1, 0); y1 = py;  wy0 = 0.25f; wy1 = 0.75f; }
    if (x & 1) { x0 = px; x1 = min(px + 1, 15); wx0 = 0.75f; wx1 = 0.25f; }
    else       { x0 = max(px - 1, 0); x1 = px;  wx0 = 0.25f; wx1 = 0.75f; }
    const float* base = vd + (size_t)bb * kCtok * kI;
    float r = wy0 * wx0 * base[(size_t)(y0 * 16 + x0) * kI + e]
            + wy0 * wx1 * base[(size_t)(y0 * 16 + x1) * kI + e]
            + wy1 * wx0 * base[(size_t)(y1 * 16 + x0) * kI + e]
            + wy1 * wx1 * base[(size_t)(y1 * 16 + x1) * kI + e];
    vtok[((size_t)bb * kN + opix) * kI + e] = __float2bfloat16(r);
}

// ---------------- launch ----------------
extern "C" void kernel_launch(void* const* d_in, const int* in_sizes, int n_in,
                              void* d_out, int out_size)
{
    const float* hidden     = (const float*)d_in[0];
    const float* context    = (const float*)d_in[1];
    const float* pose       = (const float*)d_in[2];
    const float* Wq         = (const float*)d_in[3];
    const float* Wk         = (const float*)d_in[4];
    const float* Wv         = (const float*)d_in[5];
    const float* Wa         = (const float*)d_in[6];
    const float* agent_bias = (const float*)d_in[7];
    const float* query_bias = (const float*)d_in[8];
    const float* dwc_w      = (const float*)d_in[9];
    const float* dwc_b      = (const float*)d_in[10];
    const float* Wo         = (const float*)d_in[11];
    const float* norm_w     = (const float*)d_in[12];
    const float* norm_b     = (const float*)d_in[13];
    const float* ffln_w     = (const float*)d_in[14];
    const float* ffln_b     = (const float*)d_in[15];
    const float* ff_w1      = (const float*)d_in[16];
    const float* ff_b1      = (const float*)d_in[17];
    const float* ff_w2      = (const float*)d_in[18];
    const float* ff_b2      = (const float*)d_in[19];

    float *hs, *vP, *scoresP, *akvP, *vdP, *vtokWoP, *aqP, *ffb1iP;
    cudaGetSymbolAddress((void**)&hs, g_hs);
    cudaGetSymbolAddress((void**)&vP, g_v);
    cudaGetSymbolAddress((void**)&scoresP, g_scores);
    cudaGetSymbolAddress((void**)&akvP, g_akv);
    cudaGetSymbolAddress((void**)&vdP, g_vdmax);
    cudaGetSymbolAddress((void**)&vtokWoP, g_vtokWo);
    cudaGetSymbolAddress((void**)&aqP, g_aq);
    cudaGetSymbolAddress((void**)&ffb1iP, g_ffb1i);

    __nv_bfloat16 *posetB, *ctxpermB, *ctxB, *WkT, *WvT, *WaN, *WqP, *WoT, *fw1T, *fw2T,
                  *kPB, *vTB, *SB, *GTB, *UB, *scoresB, *akvB, *akvWoT, *aqB, *vtokB, *nhB, *ggB;
    cudaGetSymbolAddress((void**)&posetB, b_poset);
    cudaGetSymbolAddress((void**)&ctxpermB, b_ctxperm);
    cudaGetSymbolAddress((void**)&ctxB, b_ctx);
    cudaGetSymbolAddress((void**)&WkT, b_WkT);
    cudaGetSymbolAddress((void**)&WvT, b_WvT);
    cudaGetSymbolAddress((void**)&WaN, b_Wanat);
    cudaGetSymbolAddress((void**)&WqP, b_Wqpad);
    cudaGetSymbolAddress((void**)&WoT, b_WoT);
    cudaGetSymbolAddress((void**)&fw1T, b_ffw1T);
    cudaGetSymbolAddress((void**)&fw2T, b_ffw2T);
    cudaGetSymbolAddress((void**)&kPB, b_kP);
    cudaGetSymbolAddress((void**)&vTB, b_vT);
    cudaGetSymbolAddress((void**)&SB, b_S);
    cudaGetSymbolAddress((void**)&GTB, b_GT);
    cudaGetSymbolAddress((void**)&UB, b_U);
    cudaGetSymbolAddress((void**)&scoresB, b_scores);
    cudaGetSymbolAddress((void**)&akvB, b_akv);
    cudaGetSymbolAddress((void**)&akvWoT, b_akvWoT);
    cudaGetSymbolAddress((void**)&aqB, b_aq);
    cudaGetSymbolAddress((void**)&vtokB, b_vtok);
    cudaGetSymbolAddress((void**)&nhB, b_nh);
    cudaGetSymbolAddress((void**)&ggB, b_gg);

    const float SCALE = 0.125f;
    auto cdiv = [](long a, long b) { return (int)((a + b - 1) / b); };

    // ===== Phase A: everything independent of hs, both blocks batched =====
    pcperm_k<<<cdiv(P1_S2, 256), 256>>>(hidden, pose, context, hs, posetB, ctxpermB);
    prep_k<<<cdiv(Q_S8, 256), 256>>>(context, Wk, Wa, Wv, Wq, Wo, ff_w1, ff_b1, ff_w2,
                                     ctxB, WkT, WaN, WvT, WqP, WoT, fw1T, ffb1iP, fw2T);

    // kP[blk][b] : z = blk*2+b ; A = ctxperm[b] (aMod=2) ; B = WkT[blk] (bDiv=2)
    gemm(ctxpermB, WkT, nullptr, nullptr, nullptr, kPB,
         512, kI, kCD, kCD, kCD, 0, kI, 0,
         512L * kCD, (long)kI * kCD, 0, 512L * kI, 2, 2, 4, 1.f, 8 | 32);
    // S[blk][b] = kP @ Wa[blk]^T : z direct A ; B = WaN[blk] (bDiv=2)
    gemm(kPB, WaN, nullptr, nullptr, nullptr, SB,
         512, kQ, kI, kI, kI, 0, kQ, 0,
         512L * kI, (long)kQ * kI, 0, 512L * kQ, 0, 2, 4, 1.f, 8 | 32);
    // G^T[blk] = (WqP[blk] @ WaN[blk]^T)^T
    gemm(WqP, WaN, nullptr, nullptr, nullptr, GTB,
         384, kQ, kI, kI, kI, 0, 384, 0,
         (long)384 * kI, (long)kQ * kI, 0, (long)kQ * 384, 0, 1, 2, 1.f, 16 | 32);
    // v proj [blk][b][c] : z = blk*4 + b*2 + c ; A = ctxB[b*2+c] (aMod=4) ; B = WvT[blk] (bDiv=4)
    gemm(ctxB, WvT, nullptr, nullptr, vP, vTB,
         kCtok, kI, kCD, kCD, kCD, kI, kCtok, 0,
         (long)kCtok * kCD, (long)kI * kCD, (long)kCtok * kI, (long)kI * kCtok, 4, 4, 8, 1.f, 16);
    // scores[blk][b][t] : z = blk*32 + b*16 + t ; A = poset[b*16+t] (aMod=32) ; B = S[z/16]
    gemm(posetB, SB, nullptr, nullptr, scoresP, nullptr,
         kN, 512, kQ, kQ, kQ, 512, 0, 0,
         (long)kN * kQ, 512L * kQ, (long)kN * 512, 0, 32, 16, 64, SCALE, 0);
    softmax_kv_k<<<dim3(2 * (int)kTOK, 2), 256>>>(scoresP, agent_bias, scoresB);
    // agent_kv : z = blk*32 + b*16 + t ; B = vT[z/16] (bDiv=16)
    gemm(scoresB, vTB, nullptr, nullptr, akvP, nullptr,
         kN, kI, kCtok, 512, kCtok, kI, 0, 0,
         (long)kN * 512, (long)kC * kI * kCtok, (long)kN * kI, 0, 0, 16, 64, 1.f, 0);
    gemm(scoresB + 256, vTB + (size_t)kI * kCtok, nullptr, nullptr, akvP, akvB,
         kN, kI, kCtok, 512, kCtok, kI, kI, 0,
         (long)kN * 512, (long)kC * kI * kCtok, (long)kN * kI, (long)kN * kI, 0, 16, 64,
         1.f, 2 | 8 | 32);
    // akvWo^T : z ; B = WoT[blk] = z/32
    gemm(akvB, WoT, nullptr, nullptr, akvP, akvWoT,
         kN, kQ, kI, kI, kI, kQ, kN, 0,
         (long)kN * kI, (long)kQ * kI, 0, (long)kQ * kN, 0, 32, 64, 1.f, 16 | 32);
    // dwconv + upsample + vtokWo, both blocks
    dwconv_k<<<2 * kB * kCtok, kI>>>(vP, dwc_w, dwc_b, vdP);
    upsample_k<<<2 * kB * kN, kI>>>(vdP, vtokB);
    gemm(vtokB, WoT, nullptr, nullptr, vtokWoP, nullptr,
         kN, kQ, kI, kI, kI, kQ, 0, 0,
         (long)kN * kI, (long)kQ * kI, (long)kN * kQ, 0, 0, 2, 4, 1.f, 0);

    // ===== Phase B: hs-dependent chain, sequential over blocks =====
    for (int blk = 0; blk < 2; blk++) {
        const __nv_bfloat16* GT_b = GTB + (size_t)blk * kQ * 384;
        const float* qb_b = query_bias + (size_t)blk * kN * kN;

        ln_k<<<(int)kTOK, 256>>>(hs, norm_w, norm_b, nhB, kQ);
        gemm(nhB, GT_b, nullptr, nullptr, nullptr, UB,
             (int)kTOK, kQ, kQ, kQ, 384, 0, kQ, 0,
             0, 0, 0, 0, 0, 1, 1, 1.f, 8 | 32);
        gemm(UB, posetB, nullptr, nullptr, aqP, nullptr,
             kN, kN, kQ, kQ, kQ, kN, 0, 0,
             (long)kN * kQ, (long)kN * kQ, (long)kN * kN, 0, 0, 1, kB * kT, SCALE, 0);
        softmax_aq_k<<<(int)kTOK, 256>>>(aqP, qb_b, aqB);
        gemm(aqB, akvWoT + (size_t)blk * kB * kT * kQ * kN, nullptr,
             vtokWoP + (size_t)blk * kB * kN * kQ, hs, nullptr,
             kN, kQ, kN, kN, kN, kQ, 0, kQ,
             (long)kN * kN, (long)kQ * kN, (long)kN * kQ, 0, 0, 1, kB * kT,
             1.f, 1 | 256);
    }

    // ---- FF: LN -> fused FF1+GEGLU -> FF2, residual ----
    ln_k<<<(int)kTOK, 256>>>(hs, ffln_w, ffln_b, nhB, kQ);
    gemm(nhB, fw1T, ffb1iP, nullptr, nullptr, ggB,
         (int)kTOK, 2 * kFF, kQ, kQ, kQ, 0, kFF, 0,
         0, 0, 0, 0, 0, 1, 1, 1.f, 4 | 32 | 512);
    gemm(ggB, fw2T, ff_b2, nullptr, hs, nullptr,
         (int)kTOK, kQ, kFF, kFF, kFF, kQ, 0, 0,
         0, 0, 0, 0, 0, 1, 1, 1.f, 1 | 4);

    cudaMemcpyAsync(d_out, hs, sizeof(float) * kHS, cudaMemcpyDeviceToDevice, 0);
}

// round 13
// speedup vs baseline: 1.1231x; 1.0415x over previous
#include <cuda_runtime.h>
#include <cuda_bf16.h>
#include <math.h>
#include <stdint.h>

// ---------------- problem constants ----------------
constexpr int kB = 2;
constexpr int kT = 16;
constexpr int kN = 1024;
constexpr int kC = 2;
constexpr int kCtok = 256;
constexpr int kQ = 320;
constexpr int kI = 512;
constexpr int kCD = 1024;
constexpr int kFF = 1280;
constexpr long kHS = (long)kB * kT * kN * kQ;
constexpr long kTOK = (long)kB * kT * kN;        // 32768

// ---------------- streams/events (created once at program init; no allocs in bench calls) ----------------
static cudaStream_t g_s2 = [] { cudaStream_t s; cudaStreamCreate(&s); return s; }();
static cudaEvent_t g_e0 = [] { cudaEvent_t e; cudaEventCreateWithFlags(&e, cudaEventDisableTiming); return e; }();
static cudaEvent_t g_e1 = [] { cudaEvent_t e; cudaEventCreateWithFlags(&e, cudaEventDisableTiming); return e; }();

// ---------------- fp32 scratch ----------------
static __device__ float g_hs[kHS];
static __device__ float g_v[(long)2 * kB * kC * kCtok * kI];
static __device__ float g_scores[(long)2 * kTOK * kI];
static __device__ float g_akv[(long)2 * kTOK * kI];
static __device__ float g_vdmax[(long)2 * kB * kCtok * kI];
static __device__ float g_vtokWo[(long)2 * kB * kN * kQ];
static __device__ float g_aq[kTOK * kN];
static __device__ float g_ffb1i[2 * kFF];

// ---------------- bf16 scratch ----------------
static __device__ __nv_bfloat16 b_poset[kHS];
static __device__ __nv_bfloat16 b_ctxperm[(long)kB * 512 * kCD];
static __device__ __nv_bfloat16 b_ctx[(long)kB * kC * kCtok * kCD];
static __device__ __nv_bfloat16 b_WkT[(long)2 * kI * kCD];
static __device__ __nv_bfloat16 b_WvT[(long)2 * kI * kCD];
static __device__ __nv_bfloat16 b_Wanat[(long)2 * kQ * kI];
static __device__ __nv_bfloat16 b_Wqpad[(long)2 * 384 * kI];
static __device__ __nv_bfloat16 b_WoT[(long)2 * kQ * kI];
static __device__ __nv_bfloat16 b_ffw1T[(long)2 * kFF * kQ];
static __device__ __nv_bfloat16 b_ffw2T[(long)kQ * kFF];
static __device__ __nv_bfloat16 b_kP[(long)2 * kB * 512 * kI];
static __device__ __nv_bfloat16 b_vT[(long)2 * kB * kC * kI * kCtok];
static __device__ __nv_bfloat16 b_S[(long)2 * kB * 512 * kQ];
static __device__ __nv_bfloat16 b_GT[(long)2 * kQ * 384];
static __device__ __nv_bfloat16 b_U[kTOK * kQ];
static __device__ __nv_bfloat16 b_scores[(long)2 * kTOK * kI];
static __device__ __nv_bfloat16 b_akv[(long)2 * kTOK * kI];
static __device__ __nv_bfloat16 b_akvWoT[(long)2 * kB * kT * kQ * kN];
static __device__ __nv_bfloat16 b_aq[kTOK * kN];
static __device__ __nv_bfloat16 b_vtok[(long)2 * kB * kN * kI];
static __device__ __nv_bfloat16 b_nh[kHS];
static __device__ __nv_bfloat16 b_gg[kTOK * kFF];

// ---------------- PTX helpers ----------------
__device__ __forceinline__ uint32_t smem_u32(const void* p) {
    return (uint32_t)__cvta_generic_to_shared(p);
}
__device__ __forceinline__ void cp16(uint32_t dst, const void* src, int src_bytes) {
    asm volatile("cp.async.cg.shared.global [%0], [%1], 16, %2;\n"
                 :: "r"(dst), "l"(src), "r"(src_bytes));
}
__device__ __forceinline__ void cp_commit() { asm volatile("cp.async.commit_group;\n"); }
template<int W> __device__ __forceinline__ void cp_wait() {
    asm volatile("cp.async.wait_group %0;\n" :: "n"(W));
}
__device__ __forceinline__ void mma16(float* d, const uint32_t* a, const uint32_t* b) {
    asm volatile(
        "mma.sync.aligned.m16n8k16.row.col.f32.bf16.bf16.f32 "
        "{%0,%1,%2,%3},{%4,%5,%6,%7},{%8,%9},{%0,%1,%2,%3};"
        : "+f"(d[0]), "+f"(d[1]), "+f"(d[2]), "+f"(d[3])
        : "r"(a[0]), "r"(a[1]), "r"(a[2]), "r"(a[3]), "r"(b[0]), "r"(b[1]));
}

// ---------------- bf16 NT tensor-core GEMM ----------------
// C(MxN) = alpha * A(MxK,bf16,row) * B(NxK,bf16,row)^T + epilogues.
// Batch: A index = aMod ? (z % aMod) : z ;  B index = z / bDiv ; C/Cb index = z.
// flags: 1 += C ; 2 max C ; 4 += bias[col] ; 8 bf16 natural Cb ; 16 bf16 transposed Cb ;
//        32 suppress fp32 write ; 256 += aux[((z>>4)*1024+row)*ldaux+col] ;
//        512 GEGLU pair epilogue (interleaved a/g cols -> Cb col/2, ldcb=N/2)
constexpr int SSTR = 40;

__global__ __launch_bounds__(256, 2)
void bgemm_k(const __nv_bfloat16* __restrict__ A, const __nv_bfloat16* __restrict__ Bm,
             const float* __restrict__ bias, const float* __restrict__ aux,
             float* __restrict__ C, __nv_bfloat16* __restrict__ Cb,
             int M, int N, int K, int lda, int ldb, int ldc, int ldcb, int ldaux,
             long strA, long strB, long strC, long strCb,
             int aMod, int bDiv, float alpha, int flags)
{
    __shared__ __align__(16) __nv_bfloat16 sA[2][128 * SSTR];
    __shared__ __align__(16) __nv_bfloat16 sB[2][128 * SSTR];

    const int z = blockIdx.z;
    const int za = aMod ? (z % aMod) : z;
    const __nv_bfloat16* Ap = A + (size_t)za * strA;
    const __nv_bfloat16* Bp = Bm + (size_t)(z / bDiv) * strB;
    float* Cp = C + (size_t)z * strC;
    __nv_bfloat16* Cbp = Cb + (size_t)z * strCb;
    const int m0 = blockIdx.y * 128, n0 = blockIdx.x * 128;
    const int tid = threadIdx.x;
    const int lane = tid & 31, warp = tid >> 5;
    const int wm = warp & 1, wn = warp >> 1;
    const int gid = lane >> 2, tig = lane & 3;

    float acc[4][4][4];
    #pragma unroll
    for (int i = 0; i < 4; i++)
        #pragma unroll
        for (int j = 0; j < 4; j++)
            #pragma unroll
            for (int r = 0; r < 4; r++) acc[i][j][r] = 0.f;

    const int kTiles = K >> 5;

    auto load_tile = [&](int buf, int kt) {
        const int k0 = kt << 5;
        #pragma unroll
        for (int j = 0; j < 2; j++) {
            int i = tid + 256 * j;
            int r = i >> 2, c = i & 3;
            cp16(smem_u32(&sA[buf][r * SSTR + c * 8]),
                 Ap + (size_t)(m0 + r) * lda + k0 + c * 8, 16);
        }
        #pragma unroll
        for (int j = 0; j < 2; j++) {
            int i = tid + 256 * j;
            int r = i >> 2, c = i & 3;
            int gn = n0 + r;
            cp16(smem_u32(&sB[buf][r * SSTR + c * 8]),
                 Bp + (size_t)gn * ldb + k0 + c * 8, gn < N ? 16 : 0);
        }
        cp_commit();
    };

    auto compute_tile = [&](int buf) {
        #pragma unroll
        for (int s = 0; s < 2; s++) {
            const int kk = s * 16;
            uint32_t af[4][4], bf[4][2];
            #pragma unroll
            for (int mt = 0; mt < 4; mt++) {
                int rm = wm * 64 + mt * 16;
                const __nv_bfloat16* base = &sA[buf][(rm + gid) * SSTR + kk + 2 * tig];
                af[mt][0] = *(const uint32_t*)(base);
                af[mt][1] = *(const uint32_t*)(base + 8 * SSTR);
                af[mt][2] = *(const uint32_t*)(base + 8);
                af[mt][3] = *(const uint32_t*)(base + 8 * SSTR + 8);
            }
            #pragma unroll
            for (int nt = 0; nt < 4; nt++) {
                int cb = wn * 32 + nt * 8 + gid;
                const __nv_bfloat16* base = &sB[buf][cb * SSTR + kk + 2 * tig];
                bf[nt][0] = *(const uint32_t*)(base);
                bf[nt][1] = *(const uint32_t*)(base + 8);
            }
            #pragma unroll
            for (int mt = 0; mt < 4; mt++)
                #pragma unroll
                for (int nt = 0; nt < 4; nt++)
                    mma16(acc[mt][nt], af[mt], bf[nt]);
        }
    };

    load_tile(0, 0);
    for (int kt = 0; kt < kTiles; kt++) {
        if (kt + 1 < kTiles) {
            load_tile((kt + 1) & 1, kt + 1);
            cp_wait<1>();
        } else {
            cp_wait<0>();
        }
        __syncthreads();
        compute_tile(kt & 1);
        __syncthreads();
    }

    #pragma unroll
    for (int mt = 0; mt < 4; mt++) {
        #pragma unroll
        for (int nt = 0; nt < 4; nt++) {
            int row0 = m0 + wm * 64 + mt * 16 + gid;
            int col0 = n0 + wn * 32 + nt * 8 + tig * 2;
            if (flags & 512) {
                float ba = bias[col0], bg = bias[col0 + 1];
                #pragma unroll
                for (int h = 0; h < 2; h++) {
                    int rr = row0 + h * 8;
                    float a = alpha * acc[mt][nt][2 * h] + ba;
                    float g = alpha * acc[mt][nt][2 * h + 1] + bg;
                    float gg = a * 0.5f * g * (1.f + erff(g * 0.70710678118654752f));
                    Cbp[(size_t)rr * ldcb + (col0 >> 1)] = __float2bfloat16(gg);
                }
                continue;
            }
            #pragma unroll
            for (int r = 0; r < 4; r++) {
                int rr = row0 + (r >> 1) * 8;
                int cc = col0 + (r & 1);
                if (cc >= N) continue;
                float vv = alpha * acc[mt][nt][r];
                size_t off = (size_t)rr * ldc + cc;
                if (flags & 4)   vv += bias[cc];
                if (flags & 256) vv += aux[(((size_t)(z >> 4)) * 1024 + rr) * ldaux + cc];
                if (flags & 1) vv += Cp[off];
                if (flags & 2) vv = fmaxf(vv, Cp[off]);
                if (!(flags & 32)) Cp[off] = vv;
                if (flags & 8)  Cbp[(size_t)rr * ldcb + cc] = __float2bfloat16(vv);
                if (flags & 16) Cbp[(size_t)cc * ldcb + rr] = __float2bfloat16(vv);
            }
        }
    }
}

static void gemm(const __nv_bfloat16* A, const __nv_bfloat16* B, const float* bias,
                 const float* aux, float* C, __nv_bfloat16* Cb,
                 int M, int N, int K, int lda, int ldb, int ldc, int ldcb, int ldaux,
                 long sA, long sB, long sC, long sCb, int aMod, int bDiv, int batch,
                 float alpha, int flags, cudaStream_t st = 0)
{
    dim3 gr((N + 127) / 128, M / 128, batch);
    bgemm_k<<<gr, 256, 0, st>>>(A, B, bias, aux, C, Cb, M, N, K,
                                lda, ldb, ldc, ldcb, ldaux,
                                sA, sB, sC, sCb, aMod, bDiv, alpha, flags);
}

// ---------------- merged prologue 1 ----------------
constexpr long P1_S0 = kHS;
constexpr long P1_S1 = P1_S0 + kHS;
constexpr long P1_S2 = P1_S1 + (long)kB * 512 * kCD;
__global__ void pcperm_k(const float* __restrict__ hidden, const float* __restrict__ pose,
                         const float* __restrict__ ctx,
                         float* __restrict__ hs, __nv_bfloat16* __restrict__ poset,
                         __nv_bfloat16* __restrict__ ctxperm)
{
    long idx = (long)blockIdx.x * blockDim.x + threadIdx.x;
    if (idx < P1_S0) {
        hs[idx] = hidden[idx];
    } else if (idx < P1_S1) {
        long i = idx - P1_S0;
        int d = (int)(i % kQ);
        long r = i / kQ;
        int n = (int)(r % kN); r /= kN;
        int t = (int)(r % kT); int b = (int)(r / kT);
        int h = n >> 5, w = n & 31;
        poset[i] = __float2bfloat16(pose[(((((size_t)b * kQ + d) * kT + t) * 32 + h) * 32) + w]);
    } else if (idx < P1_S2) {
        long i = idx - P1_S1;
        int k = (int)(i % kCD);
        long r0 = i / kCD;
        int r = (int)(r0 % 512); int b = (int)(r0 / 512);
        int n = ((r & 255) << 1) | (r >> 8);
        ctxperm[i] = __float2bfloat16(ctx[(((size_t)b * kC + (n >> 8)) * kCtok + (n & 255)) * kCD + k]);
    }
}

// ---------------- merged prologue 2 ----------------
constexpr long Q_S0 = (long)kB * kC * kCtok * kCD;
constexpr long Q_S1 = Q_S0 + (long)2 * kCD * kI;
constexpr long Q_S2 = Q_S1 + (long)2 * kQ * kI;
constexpr long Q_S3 = Q_S2 + (long)2 * kCD * kI;
constexpr long Q_S4 = Q_S3 + (long)2 * 384 * kI;
constexpr long Q_S5 = Q_S4 + (long)2 * kI * kQ;
constexpr long Q_S6 = Q_S5 + (long)2 * kFF * kQ;
constexpr long Q_S7 = Q_S6 + 2 * kFF;
constexpr long Q_S8 = Q_S7 + (long)kFF * kQ;
__global__ void prep_k(const float* __restrict__ ctx, const float* __restrict__ Wk,
                       const float* __restrict__ Wa, const float* __restrict__ Wv,
                       const float* __restrict__ Wq, const float* __restrict__ Wo,
                       const float* __restrict__ ffw1, const float* __restrict__ ffb1,
                       const float* __restrict__ ffw2,
                       __nv_bfloat16* __restrict__ ctxB, __nv_bfloat16* __restrict__ WkT,
                       __nv_bfloat16* __restrict__ WaN, __nv_bfloat16* __restrict__ WvT,
                       __nv_bfloat16* __restrict__ WqP, __nv_bfloat16* __restrict__ WoT,
                       __nv_bfloat16* __restrict__ fw1T, float* __restrict__ ffb1i,
                       __nv_bfloat16* __restrict__ fw2T)
{
    long idx = (long)blockIdx.x * blockDim.x + threadIdx.x;
    if (idx < Q_S0) {
        ctxB[idx] = __float2bfloat16(ctx[idx]);
    } else if (idx < Q_S1) {
        long i = idx - Q_S0;
        int r = (int)(i % kCD);
        long q = i / kCD;
        int c = (int)(q % kI);
        int b = (int)(q / kI);
        WkT[i] = __float2bfloat16(Wk[((size_t)b * kCD + r) * kI + c]);
    } else if (idx < Q_S2) {
        long i = idx - Q_S1;
        WaN[i] = __float2bfloat16(Wa[i]);
    } else if (idx < Q_S3) {
        long i = idx - Q_S2;
        int r = (int)(i % kCD);
        long q = i / kCD;
        int c = (int)(q % kI);
        int b = (int)(q / kI);
        WvT[i] = __float2bfloat16(Wv[((size_t)b * kCD + r) * kI + c]);
    } else if (idx < Q_S4) {
        long i = idx - Q_S3;
        int c = (int)(i % kI);
        long q = i / kI;
        int r = (int)(q % 384);
        int blk = (int)(q / 384);
        WqP[i] = (r < kQ) ? __float2bfloat16(Wq[((size_t)blk * kQ + r) * kI + c])
                          : __float2bfloat16(0.f);
    } else if (idx < Q_S5) {
        long i = idx - Q_S4;
        int r = (int)(i % kI);
        long q = i / kI;
        int c = (int)(q % kQ);
        int b = (int)(q / kQ);
        WoT[i] = __float2bfloat16(Wo[((size_t)b * kI + r) * kQ + c]);
    } else if (idx < Q_S6) {
        long i = idx - Q_S5;
        int k = (int)(i % kQ);
        int e = (int)(i / kQ);
        int oc = (e & 1) ? (kFF + (e >> 1)) : (e >> 1);
        fw1T[i] = __float2bfloat16(ffw1[(size_t)k * (2 * kFF) + oc]);
    } else if (idx < Q_S7) {
        int e = (int)(idx - Q_S6);
        int oc = (e & 1) ? (kFF + (e >> 1)) : (e >> 1);
        ffb1i[e] = ffb1[oc];
    } else if (idx < Q_S8) {
        long i = idx - Q_S7;
        int r = (int)(i % kFF);
        int c = (int)(i / kFF);
        fw2T[i] = __float2bfloat16(ffw2[(size_t)r * kQ + c]);
    }
}

// ---------------- LayerNorm (bf16 out) ----------------
__global__ void ln_k(const float* __restrict__ x, const float* __restrict__ w,
                     const float* __restrict__ b, __nv_bfloat16* __restrict__ y, int cols)
{
    int row = blockIdx.x;
    const float* xp = x + (size_t)row * cols;
    float s1 = 0.f, s2 = 0.f;
    for (int i = threadIdx.x; i < cols; i += blockDim.x) {
        float v = xp[i]; s1 += v; s2 += v * v;
    }
    __shared__ float r1[256], r2[256];
    r1[threadIdx.x] = s1; r2[threadIdx.x] = s2;
    __syncthreads();
    for (int s = 128; s > 0; s >>= 1) {
        if (threadIdx.x < s) { r1[threadIdx.x] += r1[threadIdx.x + s]; r2[threadIdx.x] += r2[threadIdx.x + s]; }
        __syncthreads();
    }
    float mean = r1[0] / cols;
    float var = r2[0] / cols - mean * mean;
    float rstd = rsqrtf(var + 1e-5f);
    __nv_bfloat16* yp = y + (size_t)row * cols;
    for (int i = threadIdx.x; i < cols; i += blockDim.x)
        yp[i] = __float2bfloat16((xp[i] - mean) * rstd * w[i] + b[i]);
}

// ---------------- softmax kv groups, both blocks ----------------
__global__ void softmax_kv_k(const float* __restrict__ s, const float* __restrict__ abias,
                             __nv_bfloat16* __restrict__ ob)
{
    int gr = blockIdx.x;
    int c2 = blockIdx.y;
    int blk = gr >> 15;
    int m = gr & 1023;
    const float* p = s + (size_t)gr * 512 + c2 * 256;
    __nv_bfloat16* po = ob + (size_t)gr * 512 + c2 * 256;
    int tid = threadIdx.x;
    float v = p[tid] + abias[((size_t)blk * kN + m) * 256 + tid];
    __shared__ float red[256];
    red[tid] = v; __syncthreads();
    for (int st = 128; st; st >>= 1) { if (tid < st) red[tid] = fmaxf(red[tid], red[tid + st]); __syncthreads(); }
    float mx = red[0]; __syncthreads();
    float e = __expf(v - mx);
    red[tid] = e; __syncthreads();
    for (int st = 128; st; st >>= 1) { if (tid < st) red[tid] += red[tid + st]; __syncthreads(); }
    po[tid] = __float2bfloat16(e / red[0]);
}

// ---------------- softmax query rows ----------------
__global__ void softmax_aq_k(const float* __restrict__ s, const float* __restrict__ qbias,
                             __nv_bfloat16* __restrict__ ob)
{
    int gr = blockIdx.x;
    int n = gr & 1023;
    const float* p = s + (size_t)gr * 1024;
    __nv_bfloat16* po = ob + (size_t)gr * 1024;
    const float* bp = qbias + (size_t)n * 1024;
    int tid = threadIdx.x;
    float v[4];
    float mx = -1e30f;
    #pragma unroll
    for (int k = 0; k < 4; k++) { v[k] = p[tid + k * 256] + bp[tid + k * 256]; mx = fmaxf(mx, v[k]); }
    __shared__ float red[256];
    red[tid] = mx; __syncthreads();
    for (int st = 128; st; st >>= 1) { if (tid < st) red[tid] = fmaxf(red[tid], red[tid + st]); __syncthreads(); }
    mx = red[0]; __syncthreads();
    float sum = 0.f;
    #pragma unroll
    for (int k = 0; k < 4; k++) { v[k] = __expf(v[k] - mx); sum += v[k]; }
    red[tid] = sum; __syncthreads();
    for (int st = 128; st; st >>= 1) { if (tid < st) red[tid] += red[tid + st]; __syncthreads(); }
    float inv = 1.f / red[0];
    #pragma unroll
    for (int k = 0; k < 4; k++) po[tid + k * 256] = __float2bfloat16(v[k] * inv);
}

// ---------------- dwconv (both blocks) ----------------
__global__ void dwconv_k(const float* __restrict__ v, const float* __restrict__ wgt,
                         const float* __restrict__ bias, float* __restrict__ out)
{
    int pix = blockIdx.x & 255;
    int b = (blockIdx.x >> 8) & 1;
    int blk = blockIdx.x >> 9;
    int e = threadIdx.x;
    int h = pix >> 4, w = pix & 15;
    const float* wp = wgt + (size_t)blk * kI * 9;
    float wv[9];
    #pragma unroll
    for (int t9 = 0; t9 < 9; t9++) wv[t9] = wp[e * 9 + t9];
    float best = -1e30f;
    #pragma unroll
    for (int c = 0; c < 2; c++) {
        float s = 0.f;
        #pragma unroll
        for (int dh = -1; dh <= 1; dh++)
            #pragma unroll
            for (int dw = -1; dw <= 1; dw++) {
                int hh = h + dh, ww = w + dw;
                if (hh < 0 || hh > 15 || ww < 0 || ww > 15) continue;
                s += v[(((size_t)(blk * kB + b) * kC + c) * kCtok + hh * 16 + ww) * kI + e]
                     * wv[(dh + 1) * 3 + (dw + 1)];
            }
        best = fmaxf(best, s);
    }
    out[((size_t)(blk * kB + b) * kCtok + pix) * kI + e] = best + bias[(size_t)blk * kI + e];
}

// ---------------- bilinear x2 upsample -> bf16 (both blocks) ----------------
__global__ void upsample_k(const float* __restrict__ vd, __nv_bfloat16* __restrict__ vtok)
{
    int opix = blockIdx.x & 1023;
    int bb = blockIdx.x >> 10;
    int e = threadIdx.x;
    int y = opix >> 5, x = opix & 31;
    int py = y >> 1, px = x >> 1;
    int y0, y1, x0, x1; float wy0, wy1, wx0, wx1;
    if (y & 1) { y0 = py; y1 = min(py + 1, 15); wy0 = 0.75f; wy1 = 0.25f; }
    else       { y0 = max(py - 1, 0); y1 = py;  wy0 = 0.25f; wy1 = 0.75f; }
    if (x & 1) { x0 = px; x1 = min(px + 1, 15); wx0 = 0.75f; wx1 = 0.25f; }
    else       { x0 = max(px - 1, 0); x1 = px;  wx0 = 0.25f; wx1 = 0.75f; }
    const float* base = vd + (size_t)bb * kCtok * kI;
    float r = wy0 * wx0 * base[(size_t)(y0 * 16 + x0) * kI + e]
            + wy0 * wx1 * base[(size_t)(y0 * 16 + x1) * kI + e]
            + wy1 * wx0 * base[(size_t)(y1 * 16 + x0) * kI + e]
            + wy1 * wx1 * base[(size_t)(y1 * 16 + x1) * kI + e];
    vtok[((size_t)bb * kN + opix) * kI + e] = __float2bfloat16(r);
}

// ---------------- launch ----------------
extern "C" void kernel_launch(void* const* d_in, const int* in_sizes, int n_in,
                              void* d_out, int out_size)
{
    const float* hidden     = (const float*)d_in[0];
    const float* context    = (const float*)d_in[1];
    const float* pose       = (const float*)d_in[2];
    const float* Wq         = (const float*)d_in[3];
    const float* Wk         = (const float*)d_in[4];
    const float* Wv         = (const float*)d_in[5];
    const float* Wa         = (const float*)d_in[6];
    const float* agent_bias = (const float*)d_in[7];
    const float* query_bias = (const float*)d_in[8];
    const float* dwc_w      = (const float*)d_in[9];
    const float* dwc_b      = (const float*)d_in[10];
    const float* Wo         = (const float*)d_in[11];
    const float* norm_w     = (const float*)d_in[12];
    const float* norm_b     = (const float*)d_in[13];
    const float* ffln_w     = (const float*)d_in[14];
    const float* ffln_b     = (const float*)d_in[15];
    const float* ff_w1      = (const float*)d_in[16];
    const float* ff_b1      = (const float*)d_in[17];
    const float* ff_w2      = (const float*)d_in[18];
    const float* ff_b2      = (const float*)d_in[19];

    float *hs, *vP, *scoresP, *akvP, *vdP, *vtokWoP, *aqP, *ffb1iP;
    cudaGetSymbolAddress((void**)&hs, g_hs);
    cudaGetSymbolAddress((void**)&vP, g_v);
    cudaGetSymbolAddress((void**)&scoresP, g_scores);
    cudaGetSymbolAddress((void**)&akvP, g_akv);
    cudaGetSymbolAddress((void**)&vdP, g_vdmax);
    cudaGetSymbolAddress((void**)&vtokWoP, g_vtokWo);
    cudaGetSymbolAddress((void**)&aqP, g_aq);
    cudaGetSymbolAddress((void**)&ffb1iP, g_ffb1i);

    __nv_bfloat16 *posetB, *ctxpermB, *ctxB, *WkT, *WvT, *WaN, *WqP, *WoT, *fw1T, *fw2T,
                  *kPB, *vTB, *SB, *GTB, *UB, *scoresB, *akvB, *akvWoT, *aqB, *vtokB, *nhB, *ggB;
    cudaGetSymbolAddress((void**)&posetB, b_poset);
    cudaGetSymbolAddress((void**)&ctxpermB, b_ctxperm);
    cudaGetSymbolAddress((void**)&ctxB, b_ctx);
    cudaGetSymbolAddress((void**)&WkT, b_WkT);
    cudaGetSymbolAddress((void**)&WvT, b_WvT);
    cudaGetSymbolAddress((void**)&WaN, b_Wanat);
    cudaGetSymbolAddress((void**)&WqP, b_Wqpad);
    cudaGetSymbolAddress((void**)&WoT, b_WoT);
    cudaGetSymbolAddress((void**)&fw1T, b_ffw1T);
    cudaGetSymbolAddress((void**)&fw2T, b_ffw2T);
    cudaGetSymbolAddress((void**)&kPB, b_kP);
    cudaGetSymbolAddress((void**)&vTB, b_vT);
    cudaGetSymbolAddress((void**)&SB, b_S);
    cudaGetSymbolAddress((void**)&GTB, b_GT);
    cudaGetSymbolAddress((void**)&UB, b_U);
    cudaGetSymbolAddress((void**)&scoresB, b_scores);
    cudaGetSymbolAddress((void**)&akvB, b_akv);
    cudaGetSymbolAddress((void**)&akvWoT, b_akvWoT);
    cudaGetSymbolAddress((void**)&aqB, b_aq);
    cudaGetSymbolAddress((void**)&vtokB, b_vtok);
    cudaGetSymbolAddress((void**)&nhB, b_nh);
    cudaGetSymbolAddress((void**)&ggB, b_gg);

    const float SCALE = 0.125f;
    auto cdiv = [](long a, long b) { return (int)((a + b - 1) / b); };

    // ===== shared prologue =====
    pcperm_k<<<cdiv(P1_S2, 256), 256>>>(hidden, pose, context, hs, posetB, ctxpermB);
    prep_k<<<cdiv(Q_S8, 256), 256>>>(context, Wk, Wa, Wv, Wq, Wo, ff_w1, ff_b1, ff_w2,
                                     ctxB, WkT, WaN, WvT, WqP, WoT, fw1T, ffb1iP, fw2T);

    // fork: stream 2 runs the hs-side blk0 chain (GT -> ln -> U0 -> aq0 -> softmax0)
    cudaEventRecord(g_e0, 0);
    cudaStreamWaitEvent(g_s2, g_e0, 0);

    gemm(WqP, WaN, nullptr, nullptr, nullptr, GTB,
         384, kQ, kI, kI, kI, 0, 384, 0,
         (long)384 * kI, (long)kQ * kI, 0, (long)kQ * 384, 0, 1, 2, 1.f, 16 | 32, g_s2);
    ln_k<<<(int)kTOK, 256, 0, g_s2>>>(hs, norm_w, norm_b, nhB, kQ);
    gemm(nhB, GTB, nullptr, nullptr, nullptr, UB,
         (int)kTOK, kQ, kQ, kQ, 384, 0, kQ, 0,
         0, 0, 0, 0, 0, 1, 1, 1.f, 8 | 32, g_s2);
    gemm(UB, posetB, nullptr, nullptr, aqP, nullptr,
         kN, kN, kQ, kQ, kQ, kN, 0, 0,
         (long)kN * kQ, (long)kN * kQ, (long)kN * kN, 0, 0, 1, kB * kT, SCALE, 0, g_s2);
    softmax_aq_k<<<(int)kTOK, 256, 0, g_s2>>>(aqP, query_bias, aqB);
    cudaEventRecord(g_e1, g_s2);

    // ===== main stream: kv side, both blocks batched =====
    gemm(ctxpermB, WkT, nullptr, nullptr, nullptr, kPB,
         512, kI, kCD, kCD, kCD, 0, kI, 0,
         512L * kCD, (long)kI * kCD, 0, 512L * kI, 2, 2, 4, 1.f, 8 | 32);
    gemm(kPB, WaN, nullptr, nullptr, nullptr, SB,
         512, kQ, kI, kI, kI, 0, kQ, 0,
         512L * kI, (long)kQ * kI, 0, 512L * kQ, 0, 2, 4, 1.f, 8 | 32);
    gemm(posetB, SB, nullptr, nullptr, scoresP, nullptr,
         kN, 512, kQ, kQ, kQ, 512, 0, 0,
         (long)kN * kQ, 512L * kQ, (long)kN * 512, 0, 32, 16, 64, SCALE, 0);
    softmax_kv_k<<<dim3(2 * (int)kTOK, 2), 256>>>(scoresP, agent_bias, scoresB);
    gemm(ctxB, WvT, nullptr, nullptr, vP, vTB,
         kCtok, kI, kCD, kCD, kCD, kI, kCtok, 0,
         (long)kCtok * kCD, (long)kI * kCD, (long)kCtok * kI, (long)kI * kCtok, 4, 4, 8, 1.f, 16);
    gemm(scoresB, vTB, nullptr, nullptr, akvP, nullptr,
         kN, kI, kCtok, 512, kCtok, kI, 0, 0,
         (long)kN * 512, (long)kC * kI * kCtok, (long)kN * kI, 0, 0, 16, 64, 1.f, 0);
    gemm(scoresB + 256, vTB + (size_t)kI * kCtok, nullptr, nullptr, akvP, akvB,
         kN, kI, kCtok, 512, kCtok, kI, kI, 0,
         (long)kN * 512, (long)kC * kI * kCtok, (long)kN * kI, (long)kN * kI, 0, 16, 64,
         1.f, 2 | 8 | 32);
    gemm(akvB, WoT, nullptr, nullptr, akvP, akvWoT,
         kN, kQ, kI, kI, kI, kQ, kN, 0,
         (long)kN * kI, (long)kQ * kI, 0, (long)kQ * kN, 0, 32, 64, 1.f, 16 | 32);
    dwconv_k<<<2 * kB * kCtok, kI>>>(vP, dwc_w, dwc_b, vdP);
    upsample_k<<<2 * kB * kN, kI>>>(vdP, vtokB);
    gemm(vtokB, WoT, nullptr, nullptr, vtokWoP, nullptr,
         kN, kQ, kI, kI, kI, kQ, 0, 0,
         (long)kN * kI, (long)kQ * kI, (long)kN * kQ, 0, 0, 2, 4, 1.f, 0);

    // join: blk0 final needs aqB (s2) + akvWoT/vtokWo (main)
    cudaStreamWaitEvent(0, g_e1, 0);

    // ===== Phase B blk0 final, then full blk1 chain =====
    gemm(aqB, akvWoT, nullptr, vtokWoP, hs, nullptr,
         kN, kQ, kN, kN, kN, kQ, 0, kQ,
         (long)kN * kN, (long)kQ * kN, (long)kN * kQ, 0, 0, 1, kB * kT,
         1.f, 1 | 256);

    {
        const __nv_bfloat16* GT_b = GTB + (size_t)kQ * 384;
        const float* qb_b = query_bias + (size_t)kN * kN;
        ln_k<<<(int)kTOK, 256>>>(hs, norm_w, norm_b, nhB, kQ);
        gemm(nhB, GT_b, nullptr, nullptr, nullptr, UB,
             (int)kTOK, kQ, kQ, kQ, 384, 0, kQ, 0,
             0, 0, 0, 0, 0, 1, 1, 1.f, 8 | 32);
        gemm(UB, posetB, nullptr, nullptr, aqP, nullptr,
             kN, kN, kQ, kQ, kQ, kN, 0, 0,
             (long)kN * kQ, (long)kN * kQ, (long)kN * kN, 0, 0, 1, kB * kT, SCALE, 0);
        softmax_aq_k<<<(int)kTOK, 256>>>(aqP, qb_b, aqB);
        gemm(aqB, akvWoT + (size_t)kB * kT * kQ * kN, nullptr,
             vtokWoP + (size_t)kB * kN * kQ, hs, nullptr,
             kN, kQ, kN, kN, kN, kQ, 0, kQ,
             (long)kN * kN, (long)kQ * kN, (long)kN * kQ, 0, 0, 1, kB * kT,
             1.f, 1 | 256);
    }

    // ---- FF ----
    ln_k<<<(int)kTOK, 256>>>(hs, ffln_w, ffln_b, nhB, kQ);
    gemm(nhB, fw1T, ffb1iP, nullptr, nullptr, ggB,
         (int)kTOK, 2 * kFF, kQ, kQ, kQ, 0, kFF, 0,
         0, 0, 0, 0, 0, 1, 1, 1.f, 4 | 32 | 512);
    gemm(ggB, fw2T, ff_b2, nullptr, hs, nullptr,
         (int)kTOK, kQ, kFF, kFF, kFF, kQ, 0, 0,
         0, 0, 0, 0, 0, 1, 1, 1.f, 1 | 4);

    cudaMemcpyAsync(d_out, hs, sizeof(float) * kHS, cudaMemcpyDeviceToDevice, 0);
}

// round 14
// speedup vs baseline: 1.1736x; 1.0450x over previous
#include <cuda_runtime.h>
#include <cuda_bf16.h>
#include <math.h>
#include <stdint.h>

// ---------------- problem constants ----------------
constexpr int kB = 2;
constexpr int kT = 16;
constexpr int kN = 1024;
constexpr int kC = 2;
constexpr int kCtok = 256;
constexpr int kQ = 320;
constexpr int kI = 512;
constexpr int kCD = 1024;
constexpr int kFF = 1280;
constexpr long kHS = (long)kB * kT * kN * kQ;
constexpr long kTOK = (long)kB * kT * kN;        // 32768

// ---------------- streams/events (created once at program init) ----------------
static cudaStream_t g_s2 = [] { cudaStream_t s; cudaStreamCreate(&s); return s; }();
static cudaEvent_t g_e0 = [] { cudaEvent_t e; cudaEventCreateWithFlags(&e, cudaEventDisableTiming); return e; }();
static cudaEvent_t g_e1 = [] { cudaEvent_t e; cudaEventCreateWithFlags(&e, cudaEventDisableTiming); return e; }();

// ---------------- fp32 scratch ----------------
static __device__ float g_hs[kHS];
static __device__ float g_v[(long)2 * kB * kC * kCtok * kI];
static __device__ float g_scores[(long)2 * kTOK * kI];
static __device__ float g_akv[(long)2 * kTOK * kI];
static __device__ float g_vdmax[(long)2 * kB * kCtok * kI];
static __device__ float g_vtokWo[(long)2 * kB * kN * kQ];
static __device__ float g_aq[kTOK * kN];
static __device__ float g_ffb1i[2 * kFF];

// ---------------- bf16 scratch ----------------
static __device__ __nv_bfloat16 b_poset[kHS];
static __device__ __nv_bfloat16 b_ctxperm[(long)kB * 512 * kCD];
static __device__ __nv_bfloat16 b_ctx[(long)kB * kC * kCtok * kCD];
static __device__ __nv_bfloat16 b_WkT[(long)2 * kI * kCD];
static __device__ __nv_bfloat16 b_WvT[(long)2 * kI * kCD];
static __device__ __nv_bfloat16 b_Wanat[(long)2 * kQ * kI];
static __device__ __nv_bfloat16 b_Wqpad[(long)2 * 384 * kI];
static __device__ __nv_bfloat16 b_WoT[(long)2 * kQ * kI];
static __device__ __nv_bfloat16 b_ffw1T[(long)2 * kFF * kQ];
static __device__ __nv_bfloat16 b_ffw2T[(long)kQ * kFF];
static __device__ __nv_bfloat16 b_kP[(long)2 * kB * 512 * kI];
static __device__ __nv_bfloat16 b_vT[(long)2 * kB * kC * kI * kCtok];
static __device__ __nv_bfloat16 b_S[(long)2 * kB * 512 * kQ];
static __device__ __nv_bfloat16 b_GT[(long)2 * kQ * 384];
static __device__ __nv_bfloat16 b_U[kTOK * kQ];
static __device__ __nv_bfloat16 b_scores[(long)2 * kTOK * kI];
static __device__ __nv_bfloat16 b_akv[(long)2 * kTOK * kI];
static __device__ __nv_bfloat16 b_akvWoT[(long)2 * kB * kT * kQ * kN];
static __device__ __nv_bfloat16 b_aq[kTOK * kN];
static __device__ __nv_bfloat16 b_vtok[(long)2 * kB * kN * kI];
static __device__ __nv_bfloat16 b_nh[kHS];
static __device__ __nv_bfloat16 b_gg[kTOK * kFF];

// ---------------- PTX helpers ----------------
__device__ __forceinline__ uint32_t smem_u32(const void* p) {
    return (uint32_t)__cvta_generic_to_shared(p);
}
__device__ __forceinline__ void cp16(uint32_t dst, const void* src, int src_bytes) {
    asm volatile("cp.async.cg.shared.global [%0], [%1], 16, %2;\n"
                 :: "r"(dst), "l"(src), "r"(src_bytes));
}
__device__ __forceinline__ void cp_commit() { asm volatile("cp.async.commit_group;\n"); }
template<int W> __device__ __forceinline__ void cp_wait() {
    asm volatile("cp.async.wait_group %0;\n" :: "n"(W));
}
__device__ __forceinline__ void mma16(float* d, const uint32_t* a, const uint32_t* b) {
    asm volatile(
        "mma.sync.aligned.m16n8k16.row.col.f32.bf16.bf16.f32 "
        "{%0,%1,%2,%3},{%4,%5,%6,%7},{%8,%9},{%0,%1,%2,%3};"
        : "+f"(d[0]), "+f"(d[1]), "+f"(d[2]), "+f"(d[3])
        : "r"(a[0]), "r"(a[1]), "r"(a[2]), "r"(a[3]), "r"(b[0]), "r"(b[1]));
}

// ---------------- bf16 NT tensor-core GEMM ----------------
// C(MxN) = alpha * A(MxK,bf16,row) * B(NxK,bf16,row)^T + epilogues.
// Batch: A index = aMod ? (z % aMod) : z ;  B index = z / bDiv ; C/Cb index = z.
// flags: 1 += C ; 2 max C ; 4 += bias[col] ; 8 bf16 natural Cb ; 16 bf16 transposed Cb ;
//        32 suppress fp32 write ; 256 += aux[((z>>4)*1024+row)*ldaux+col] ;
//        512 GEGLU pair epilogue ; 1024 write fp32 result to C2 (not Cp)
constexpr int SSTR = 40;

__global__ __launch_bounds__(256, 2)
void bgemm_k(const __nv_bfloat16* __restrict__ A, const __nv_bfloat16* __restrict__ Bm,
             const float* __restrict__ bias, const float* __restrict__ aux,
             float* __restrict__ C, __nv_bfloat16* __restrict__ Cb,
             float* __restrict__ C2,
             int M, int N, int K, int lda, int ldb, int ldc, int ldcb, int ldaux,
             long strA, long strB, long strC, long strCb,
             int aMod, int bDiv, float alpha, int flags)
{
    __shared__ __align__(16) __nv_bfloat16 sA[2][128 * SSTR];
    __shared__ __align__(16) __nv_bfloat16 sB[2][128 * SSTR];

    const int z = blockIdx.z;
    const int za = aMod ? (z % aMod) : z;
    const __nv_bfloat16* Ap = A + (size_t)za * strA;
    const __nv_bfloat16* Bp = Bm + (size_t)(z / bDiv) * strB;
    float* Cp = C + (size_t)z * strC;
    __nv_bfloat16* Cbp = Cb + (size_t)z * strCb;
    const int m0 = blockIdx.y * 128, n0 = blockIdx.x * 128;
    const int tid = threadIdx.x;
    const int lane = tid & 31, warp = tid >> 5;
    const int wm = warp & 1, wn = warp >> 1;
    const int gid = lane >> 2, tig = lane & 3;

    float acc[4][4][4];
    #pragma unroll
    for (int i = 0; i < 4; i++)
        #pragma unroll
        for (int j = 0; j < 4; j++)
            #pragma unroll
            for (int r = 0; r < 4; r++) acc[i][j][r] = 0.f;

    const int kTiles = K >> 5;

    auto load_tile = [&](int buf, int kt) {
        const int k0 = kt << 5;
        #pragma unroll
        for (int j = 0; j < 2; j++) {
            int i = tid + 256 * j;
            int r = i >> 2, c = i & 3;
            cp16(smem_u32(&sA[buf][r * SSTR + c * 8]),
                 Ap + (size_t)(m0 + r) * lda + k0 + c * 8, 16);
        }
        #pragma unroll
        for (int j = 0; j < 2; j++) {
            int i = tid + 256 * j;
            int r = i >> 2, c = i & 3;
            int gn = n0 + r;
            cp16(smem_u32(&sB[buf][r * SSTR + c * 8]),
                 Bp + (size_t)gn * ldb + k0 + c * 8, gn < N ? 16 : 0);
        }
        cp_commit();
    };

    auto compute_tile = [&](int buf) {
        #pragma unroll
        for (int s = 0; s < 2; s++) {
            const int kk = s * 16;
            uint32_t af[4][4], bf[4][2];
            #pragma unroll
            for (int mt = 0; mt < 4; mt++) {
                int rm = wm * 64 + mt * 16;
                const __nv_bfloat16* base = &sA[buf][(rm + gid) * SSTR + kk + 2 * tig];
                af[mt][0] = *(const uint32_t*)(base);
                af[mt][1] = *(const uint32_t*)(base + 8 * SSTR);
                af[mt][2] = *(const uint32_t*)(base + 8);
                af[mt][3] = *(const uint32_t*)(base + 8 * SSTR + 8);
            }
            #pragma unroll
            for (int nt = 0; nt < 4; nt++) {
                int cb = wn * 32 + nt * 8 + gid;
                const __nv_bfloat16* base = &sB[buf][cb * SSTR + kk + 2 * tig];
                bf[nt][0] = *(const uint32_t*)(base);
                bf[nt][1] = *(const uint32_t*)(base + 8);
            }
            #pragma unroll
            for (int mt = 0; mt < 4; mt++)
                #pragma unroll
                for (int nt = 0; nt < 4; nt++)
                    mma16(acc[mt][nt], af[mt], bf[nt]);
        }
    };

    load_tile(0, 0);
    for (int kt = 0; kt < kTiles; kt++) {
        if (kt + 1 < kTiles) {
            load_tile((kt + 1) & 1, kt + 1);
            cp_wait<1>();
        } else {
            cp_wait<0>();
        }
        __syncthreads();
        compute_tile(kt & 1);
        __syncthreads();
    }

    #pragma unroll
    for (int mt = 0; mt < 4; mt++) {
        #pragma unroll
        for (int nt = 0; nt < 4; nt++) {
            int row0 = m0 + wm * 64 + mt * 16 + gid;
            int col0 = n0 + wn * 32 + nt * 8 + tig * 2;
            if (flags & 512) {
                float ba = bias[col0], bg = bias[col0 + 1];
                #pragma unroll
                for (int h = 0; h < 2; h++) {
                    int rr = row0 + h * 8;
                    float a = alpha * acc[mt][nt][2 * h] + ba;
                    float g = alpha * acc[mt][nt][2 * h + 1] + bg;
                    float gg = a * 0.5f * g * (1.f + erff(g * 0.70710678118654752f));
                    Cbp[(size_t)rr * ldcb + (col0 >> 1)] = __float2bfloat16(gg);
                }
                continue;
            }
            #pragma unroll
            for (int r = 0; r < 4; r++) {
                int rr = row0 + (r >> 1) * 8;
                int cc = col0 + (r & 1);
                if (cc >= N) continue;
                float vv = alpha * acc[mt][nt][r];
                size_t off = (size_t)rr * ldc + cc;
                if (flags & 4)   vv += bias[cc];
                if (flags & 256) vv += aux[(((size_t)(z >> 4)) * 1024 + rr) * ldaux + cc];
                if (flags & 1) vv += Cp[off];
                if (flags & 2) vv = fmaxf(vv, Cp[off]);
                if (flags & 1024) C2[off] = vv;
                else if (!(flags & 32)) Cp[off] = vv;
                if (flags & 8)  Cbp[(size_t)rr * ldcb + cc] = __float2bfloat16(vv);
                if (flags & 16) Cbp[(size_t)cc * ldcb + rr] = __float2bfloat16(vv);
            }
        }
    }
}

static void gemm(const __nv_bfloat16* A, const __nv_bfloat16* B, const float* bias,
                 const float* aux, float* C, __nv_bfloat16* Cb,
                 int M, int N, int K, int lda, int ldb, int ldc, int ldcb, int ldaux,
                 long sA, long sB, long sC, long sCb, int aMod, int bDiv, int batch,
                 float alpha, int flags, cudaStream_t st = 0, float* C2 = nullptr)
{
    dim3 gr((N + 127) / 128, M / 128, batch);
    bgemm_k<<<gr, 256, 0, st>>>(A, B, bias, aux, C, Cb, C2, M, N, K,
                                lda, ldb, ldc, ldcb, ldaux,
                                sA, sB, sC, sCb, aMod, bDiv, alpha, flags);
}

// ---------------- merged prologue 1 ----------------
constexpr long P1_S0 = kHS;
constexpr long P1_S1 = P1_S0 + kHS;
constexpr long P1_S2 = P1_S1 + (long)kB * 512 * kCD;
__global__ void pcperm_k(const float* __restrict__ hidden, const float* __restrict__ pose,
                         const float* __restrict__ ctx,
                         float* __restrict__ hs, __nv_bfloat16* __restrict__ poset,
                         __nv_bfloat16* __restrict__ ctxperm)
{
    long idx = (long)blockIdx.x * blockDim.x + threadIdx.x;
    if (idx < P1_S0) {
        hs[idx] = hidden[idx];
    } else if (idx < P1_S1) {
        long i = idx - P1_S0;
        int d = (int)(i % kQ);
        long r = i / kQ;
        int n = (int)(r % kN); r /= kN;
        int t = (int)(r % kT); int b = (int)(r / kT);
        int h = n >> 5, w = n & 31;
        poset[i] = __float2bfloat16(pose[(((((size_t)b * kQ + d) * kT + t) * 32 + h) * 32) + w]);
    } else if (idx < P1_S2) {
        long i = idx - P1_S1;
        int k = (int)(i % kCD);
        long r0 = i / kCD;
        int r = (int)(r0 % 512); int b = (int)(r0 / 512);
        int n = ((r & 255) << 1) | (r >> 8);
        ctxperm[i] = __float2bfloat16(ctx[(((size_t)b * kC + (n >> 8)) * kCtok + (n & 255)) * kCD + k]);
    }
}

// ---------------- merged prologue 2 ----------------
constexpr long Q_S0 = (long)kB * kC * kCtok * kCD;
constexpr long Q_S1 = Q_S0 + (long)2 * kCD * kI;
constexpr long Q_S2 = Q_S1 + (long)2 * kQ * kI;
constexpr long Q_S3 = Q_S2 + (long)2 * kCD * kI;
constexpr long Q_S4 = Q_S3 + (long)2 * 384 * kI;
constexpr long Q_S5 = Q_S4 + (long)2 * kI * kQ;
constexpr long Q_S6 = Q_S5 + (long)2 * kFF * kQ;
constexpr long Q_S7 = Q_S6 + 2 * kFF;
constexpr long Q_S8 = Q_S7 + (long)kFF * kQ;
__global__ void prep_k(const float* __restrict__ ctx, const float* __restrict__ Wk,
                       const float* __restrict__ Wa, const float* __restrict__ Wv,
                       const float* __restrict__ Wq, const float* __restrict__ Wo,
                       const float* __restrict__ ffw1, const float* __restrict__ ffb1,
                       const float* __restrict__ ffw2,
                       __nv_bfloat16* __restrict__ ctxB, __nv_bfloat16* __restrict__ WkT,
                       __nv_bfloat16* __restrict__ WaN, __nv_bfloat16* __restrict__ WvT,
                       __nv_bfloat16* __restrict__ WqP, __nv_bfloat16* __restrict__ WoT,
                       __nv_bfloat16* __restrict__ fw1T, float* __restrict__ ffb1i,
                       __nv_bfloat16* __restrict__ fw2T)
{
    long idx = (long)blockIdx.x * blockDim.x + threadIdx.x;
    if (idx < Q_S0) {
        ctxB[idx] = __float2bfloat16(ctx[idx]);
    } else if (idx < Q_S1) {
        long i = idx - Q_S0;
        int r = (int)(i % kCD);
        long q = i / kCD;
        int c = (int)(q % kI);
        int b = (int)(q / kI);
        WkT[i] = __float2bfloat16(Wk[((size_t)b * kCD + r) * kI + c]);
    } else if (idx < Q_S2) {
        long i = idx - Q_S1;
        WaN[i] = __float2bfloat16(Wa[i]);
    } else if (idx < Q_S3) {
        long i = idx - Q_S2;
        int r = (int)(i % kCD);
        long q = i / kCD;
        int c = (int)(q % kI);
        int b = (int)(q / kI);
        WvT[i] = __float2bfloat16(Wv[((size_t)b * kCD + r) * kI + c]);
    } else if (idx < Q_S4) {
        long i = idx - Q_S3;
        int c = (int)(i % kI);
        long q = i / kI;
        int r = (int)(q % 384);
        int blk = (int)(q / 384);
        WqP[i] = (r < kQ) ? __float2bfloat16(Wq[((size_t)blk * kQ + r) * kI + c])
                          : __float2bfloat16(0.f);
    } else if (idx < Q_S5) {
        long i = idx - Q_S4;
        int r = (int)(i % kI);
        long q = i / kI;
        int c = (int)(q % kQ);
        int b = (int)(q / kQ);
        WoT[i] = __float2bfloat16(Wo[((size_t)b * kI + r) * kQ + c]);
    } else if (idx < Q_S6) {
        long i = idx - Q_S5;
        int k = (int)(i % kQ);
        int e = (int)(i / kQ);
        int oc = (e & 1) ? (kFF + (e >> 1)) : (e >> 1);
        fw1T[i] = __float2bfloat16(ffw1[(size_t)k * (2 * kFF) + oc]);
    } else if (idx < Q_S7) {
        int e = (int)(idx - Q_S6);
        int oc = (e & 1) ? (kFF + (e >> 1)) : (e >> 1);
        ffb1i[e] = ffb1[oc];
    } else if (idx < Q_S8) {
        long i = idx - Q_S7;
        int r = (int)(i % kFF);
        int c = (int)(i / kFF);
        fw2T[i] = __float2bfloat16(ffw2[(size_t)r * kQ + c]);
    }
}

// ---------------- LayerNorm: warp-per-row, float4 I/O (cols = kQ = 320) ----------------
__global__ void ln_k(const float* __restrict__ x, const float* __restrict__ w,
                     const float* __restrict__ b, __nv_bfloat16* __restrict__ y)
{
    int row = blockIdx.x * 8 + (threadIdx.x >> 5);
    int lane = threadIdx.x & 31;
    const float4* xp = (const float4*)(x + (size_t)row * kQ);
    float4 v[3];
    float s1 = 0.f, s2 = 0.f;
    #pragma unroll
    for (int i = 0; i < 3; i++) {
        int idx = lane + 32 * i;
        if (idx < 80) {
            v[i] = xp[idx];
            s1 += v[i].x + v[i].y + v[i].z + v[i].w;
            s2 += v[i].x * v[i].x + v[i].y * v[i].y + v[i].z * v[i].z + v[i].w * v[i].w;
        }
    }
    #pragma unroll
    for (int o = 16; o; o >>= 1) {
        s1 += __shfl_xor_sync(0xffffffffu, s1, o);
        s2 += __shfl_xor_sync(0xffffffffu, s2, o);
    }
    float mean = s1 / kQ;
    float rstd = rsqrtf(s2 / kQ - mean * mean + 1e-5f);
    __nv_bfloat162* yp = (__nv_bfloat162*)(y + (size_t)row * kQ);
    const float4* wp = (const float4*)w;
    const float4* bp = (const float4*)b;
    #pragma unroll
    for (int i = 0; i < 3; i++) {
        int idx = lane + 32 * i;
        if (idx < 80) {
            float4 wv = wp[idx], bv = bp[idx];
            float o0 = (v[i].x - mean) * rstd * wv.x + bv.x;
            float o1 = (v[i].y - mean) * rstd * wv.y + bv.y;
            float o2 = (v[i].z - mean) * rstd * wv.z + bv.z;
            float o3 = (v[i].w - mean) * rstd * wv.w + bv.w;
            yp[idx * 2]     = __floats2bfloat162_rn(o0, o1);
            yp[idx * 2 + 1] = __floats2bfloat162_rn(o2, o3);
        }
    }
}

// ---------------- softmax kv groups, both blocks ----------------
__global__ void softmax_kv_k(const float* __restrict__ s, const float* __restrict__ abias,
                             __nv_bfloat16* __restrict__ ob)
{
    int gr = blockIdx.x;
    int c2 = blockIdx.y;
    int blk = gr >> 15;
    int m = gr & 1023;
    const float* p = s + (size_t)gr * 512 + c2 * 256;
    __nv_bfloat16* po = ob + (size_t)gr * 512 + c2 * 256;
    int tid = threadIdx.x;
    float v = p[tid] + abias[((size_t)blk * kN + m) * 256 + tid];
    __shared__ float red[256];
    red[tid] = v; __syncthreads();
    for (int st = 128; st; st >>= 1) { if (tid < st) red[tid] = fmaxf(red[tid], red[tid + st]); __syncthreads(); }
    float mx = red[0]; __syncthreads();
    float e = __expf(v - mx);
    red[tid] = e; __syncthreads();
    for (int st = 128; st; st >>= 1) { if (tid < st) red[tid] += red[tid + st]; __syncthreads(); }
    po[tid] = __float2bfloat16(e / red[0]);
}

// ---------------- softmax query rows ----------------
__global__ void softmax_aq_k(const float* __restrict__ s, const float* __restrict__ qbias,
                             __nv_bfloat16* __restrict__ ob)
{
    int gr = blockIdx.x;
    int n = gr & 1023;
    const float* p = s + (size_t)gr * 1024;
    __nv_bfloat16* po = ob + (size_t)gr * 1024;
    const float* bp = qbias + (size_t)n * 1024;
    int tid = threadIdx.x;
    float v[4];
    float mx = -1e30f;
    #pragma unroll
    for (int k = 0; k < 4; k++) { v[k] = p[tid + k * 256] + bp[tid + k * 256]; mx = fmaxf(mx, v[k]); }
    __shared__ float red[256];
    red[tid] = mx; __syncthreads();
    for (int st = 128; st; st >>= 1) { if (tid < st) red[tid] = fmaxf(red[tid], red[tid + st]); __syncthreads(); }
    mx = red[0]; __syncthreads();
    float sum = 0.f;
    #pragma unroll
    for (int k = 0; k < 4; k++) { v[k] = __expf(v[k] - mx); sum += v[k]; }
    red[tid] = sum; __syncthreads();
    for (int st = 128; st; st >>= 1) { if (tid < st) red[tid] += red[tid + st]; __syncthreads(); }
    float inv = 1.f / red[0];
    #pragma unroll
    for (int k = 0; k < 4; k++) po[tid + k * 256] = __float2bfloat16(v[k] * inv);
}

// ---------------- dwconv (both blocks) ----------------
__global__ void dwconv_k(const float* __restrict__ v, const float* __restrict__ wgt,
                         const float* __restrict__ bias, float* __restrict__ out)
{
    int pix = blockIdx.x & 255;
    int b = (blockIdx.x >> 8) & 1;
    int blk = blockIdx.x >> 9;
    int e = threadIdx.x;
    int h = pix >> 4, w = pix & 15;
    const float* wp = wgt + (size_t)blk * kI * 9;
    float wv[9];
    #pragma unroll
    for (int t9 = 0; t9 < 9; t9++) wv[t9] = wp[e * 9 + t9];
    float best = -1e30f;
    #pragma unroll
    for (int c = 0; c < 2; c++) {
        float s = 0.f;
        #pragma unroll
        for (int dh = -1; dh <= 1; dh++)
            #pragma unroll
            for (int dw = -1; dw <= 1; dw++) {
                int hh = h + dh, ww = w + dw;
                if (hh < 0 || hh > 15 || ww < 0 || ww > 15) continue;
                s += v[(((size_t)(blk * kB + b) * kC + c) * kCtok + hh * 16 + ww) * kI + e]
                     * wv[(dh + 1) * 3 + (dw + 1)];
            }
        best = fmaxf(best, s);
    }
    out[((size_t)(blk * kB + b) * kCtok + pix) * kI + e] = best + bias[(size_t)blk * kI + e];
}

// ---------------- bilinear x2 upsample -> bf16 (both blocks) ----------------
__global__ void upsample_k(const float* __restrict__ vd, __nv_bfloat16* __restrict__ vtok)
{
    int opix = blockIdx.x & 1023;
    int bb = blockIdx.x >> 10;
    int e = threadIdx.x;
    int y = opix >> 5, x = opix & 31;
    int py = y >> 1, px = x >> 1;
    int y0, y1, x0, x1; float wy0, wy1, wx0, wx1;
    if (y & 1) { y0 = py; y1 = min(py + 1, 15); wy0 = 0.75f; wy1 = 0.25f; }
    else       { y0 = max(py - 1, 0); y1 = py;  wy0 = 0.25f; wy1 = 0.75f; }
    if (x & 1) { x0 = px; x1 = min(px + 1, 15); wx0 = 0.75f; wx1 = 0.25f; }
    else       { x0 = max(px - 1, 0); x1 = px;  wx0 = 0.25f; wx1 = 0.75f; }
    const float* base = vd + (size_t)bb * kCtok * kI;
    float r = wy0 * wx0 * base[(size_t)(y0 * 16 + x0) * kI + e]
            + wy0 * wx1 * base[(size_t)(y0 * 16 + x1) * kI + e]
            + wy1 * wx0 * base[(size_t)(y1 * 16 + x0) * kI + e]
            + wy1 * wx1 * base[(size_t)(y1 * 16 + x1) * kI + e];
    vtok[((size_t)bb * kN + opix) * kI + e] = __float2bfloat16(r);
}

// ---------------- launch ----------------
extern "C" void kernel_launch(void* const* d_in, const int* in_sizes, int n_in,
                              void* d_out, int out_size)
{
    const float* hidden     = (const float*)d_in[0];
    const float* context    = (const float*)d_in[1];
    const float* pose       = (const float*)d_in[2];
    const float* Wq         = (const float*)d_in[3];
    const float* Wk         = (const float*)d_in[4];
    const float* Wv         = (const float*)d_in[5];
    const float* Wa         = (const float*)d_in[6];
    const float* agent_bias = (const float*)d_in[7];
    const float* query_bias = (const float*)d_in[8];
    const float* dwc_w      = (const float*)d_in[9];
    const float* dwc_b      = (const float*)d_in[10];
    const float* Wo         = (const float*)d_in[11];
    const float* norm_w     = (const float*)d_in[12];
    const float* norm_b     = (const float*)d_in[13];
    const float* ffln_w     = (const float*)d_in[14];
    const float* ffln_b     = (const float*)d_in[15];
    const float* ff_w1      = (const float*)d_in[16];
    const float* ff_b1      = (const float*)d_in[17];
    const float* ff_w2      = (const float*)d_in[18];
    const float* ff_b2      = (const float*)d_in[19];

    float *hs, *vP, *scoresP, *akvP, *vdP, *vtokWoP, *aqP, *ffb1iP;
    cudaGetSymbolAddress((void**)&hs, g_hs);
    cudaGetSymbolAddress((void**)&vP, g_v);
    cudaGetSymbolAddress((void**)&scoresP, g_scores);
    cudaGetSymbolAddress((void**)&akvP, g_akv);
    cudaGetSymbolAddress((void**)&vdP, g_vdmax);
    cudaGetSymbolAddress((void**)&vtokWoP, g_vtokWo);
    cudaGetSymbolAddress((void**)&aqP, g_aq);
    cudaGetSymbolAddress((void**)&ffb1iP, g_ffb1i);

    __nv_bfloat16 *posetB, *ctxpermB, *ctxB, *WkT, *WvT, *WaN, *WqP, *WoT, *fw1T, *fw2T,
                  *kPB, *vTB, *SB, *GTB, *UB, *scoresB, *akvB, *akvWoT, *aqB, *vtokB, *nhB, *ggB;
    cudaGetSymbolAddress((void**)&posetB, b_poset);
    cudaGetSymbolAddress((void**)&ctxpermB, b_ctxperm);
    cudaGetSymbolAddress((void**)&ctxB, b_ctx);
    cudaGetSymbolAddress((void**)&WkT, b_WkT);
    cudaGetSymbolAddress((void**)&WvT, b_WvT);
    cudaGetSymbolAddress((void**)&WaN, b_Wanat);
    cudaGetSymbolAddress((void**)&WqP, b_Wqpad);
    cudaGetSymbolAddress((void**)&WoT, b_WoT);
    cudaGetSymbolAddress((void**)&fw1T, b_ffw1T);
    cudaGetSymbolAddress((void**)&fw2T, b_ffw2T);
    cudaGetSymbolAddress((void**)&kPB, b_kP);
    cudaGetSymbolAddress((void**)&vTB, b_vT);
    cudaGetSymbolAddress((void**)&SB, b_S);
    cudaGetSymbolAddress((void**)&GTB, b_GT);
    cudaGetSymbolAddress((void**)&UB, b_U);
    cudaGetSymbolAddress((void**)&scoresB, b_scores);
    cudaGetSymbolAddress((void**)&akvB, b_akv);
    cudaGetSymbolAddress((void**)&akvWoT, b_akvWoT);
    cudaGetSymbolAddress((void**)&aqB, b_aq);
    cudaGetSymbolAddress((void**)&vtokB, b_vtok);
    cudaGetSymbolAddress((void**)&nhB, b_nh);
    cudaGetSymbolAddress((void**)&ggB, b_gg);

    const float SCALE = 0.125f;
    auto cdiv = [](long a, long b) { return (int)((a + b - 1) / b); };

    // ===== shared prologue =====
    pcperm_k<<<cdiv(P1_S2, 256), 256>>>(hidden, pose, context, hs, posetB, ctxpermB);
    prep_k<<<cdiv(Q_S8, 256), 256>>>(context, Wk, Wa, Wv, Wq, Wo, ff_w1, ff_b1, ff_w2,
                                     ctxB, WkT, WaN, WvT, WqP, WoT, fw1T, ffb1iP, fw2T);

    // fork: stream 2 runs the hs-side blk0 chain
    cudaEventRecord(g_e0, 0);
    cudaStreamWaitEvent(g_s2, g_e0, 0);

    gemm(WqP, WaN, nullptr, nullptr, nullptr, GTB,
         384, kQ, kI, kI, kI, 0, 384, 0,
         (long)384 * kI, (long)kQ * kI, 0, (long)kQ * 384, 0, 1, 2, 1.f, 16 | 32, g_s2);
    ln_k<<<(int)(kTOK / 8), 256, 0, g_s2>>>(hs, norm_w, norm_b, nhB);
    gemm(nhB, GTB, nullptr, nullptr, nullptr, UB,
         (int)kTOK, kQ, kQ, kQ, 384, 0, kQ, 0,
         0, 0, 0, 0, 0, 1, 1, 1.f, 8 | 32, g_s2);
    gemm(UB, posetB, nullptr, nullptr, aqP, nullptr,
         kN, kN, kQ, kQ, kQ, kN, 0, 0,
         (long)kN * kQ, (long)kN * kQ, (long)kN * kN, 0, 0, 1, kB * kT, SCALE, 0, g_s2);
    softmax_aq_k<<<(int)kTOK, 256, 0, g_s2>>>(aqP, query_bias, aqB);
    cudaEventRecord(g_e1, g_s2);

    // ===== main stream: kv side, both blocks batched =====
    gemm(ctxpermB, WkT, nullptr, nullptr, nullptr, kPB,
         512, kI, kCD, kCD, kCD, 0, kI, 0,
         512L * kCD, (long)kI * kCD, 0, 512L * kI, 2, 2, 4, 1.f, 8 | 32);
    gemm(kPB, WaN, nullptr, nullptr, nullptr, SB,
         512, kQ, kI, kI, kI, 0, kQ, 0,
         512L * kI, (long)kQ * kI, 0, 512L * kQ, 0, 2, 4, 1.f, 8 | 32);
    gemm(posetB, SB, nullptr, nullptr, scoresP, nullptr,
         kN, 512, kQ, kQ, kQ, 512, 0, 0,
         (long)kN * kQ, 512L * kQ, (long)kN * 512, 0, 32, 16, 64, SCALE, 0);
    softmax_kv_k<<<dim3(2 * (int)kTOK, 2), 256>>>(scoresP, agent_bias, scoresB);
    gemm(ctxB, WvT, nullptr, nullptr, vP, vTB,
         kCtok, kI, kCD, kCD, kCD, kI, kCtok, 0,
         (long)kCtok * kCD, (long)kI * kCD, (long)kCtok * kI, (long)kI * kCtok, 4, 4, 8, 1.f, 16);
    gemm(scoresB, vTB, nullptr, nullptr, akvP, nullptr,
         kN, kI, kCtok, 512, kCtok, kI, 0, 0,
         (long)kN * 512, (long)kC * kI * kCtok, (long)kN * kI, 0, 0, 16, 64, 1.f, 0);
    gemm(scoresB + 256, vTB + (size_t)kI * kCtok, nullptr, nullptr, akvP, akvB,
         kN, kI, kCtok, 512, kCtok, kI, kI, 0,
         (long)kN * 512, (long)kC * kI * kCtok, (long)kN * kI, (long)kN * kI, 0, 16, 64,
         1.f, 2 | 8 | 32);
    gemm(akvB, WoT, nullptr, nullptr, akvP, akvWoT,
         kN, kQ, kI, kI, kI, kQ, kN, 0,
         (long)kN * kI, (long)kQ * kI, 0, (long)kQ * kN, 0, 32, 64, 1.f, 16 | 32);
    dwconv_k<<<2 * kB * kCtok, kI>>>(vP, dwc_w, dwc_b, vdP);
    upsample_k<<<2 * kB * kN, kI>>>(vdP, vtokB);
    gemm(vtokB, WoT, nullptr, nullptr, vtokWoP, nullptr,
         kN, kQ, kI, kI, kI, kQ, 0, 0,
         (long)kN * kI, (long)kQ * kI, (long)kN * kQ, 0, 0, 2, 4, 1.f, 0);

    // join
    cudaStreamWaitEvent(0, g_e1, 0);

    // ===== Phase B blk0 final, then full blk1 chain =====
    gemm(aqB, akvWoT, nullptr, vtokWoP, hs, nullptr,
         kN, kQ, kN, kN, kN, kQ, 0, kQ,
         (long)kN * kN, (long)kQ * kN, (long)kN * kQ, 0, 0, 1, kB * kT,
         1.f, 1 | 256);

    {
        const __nv_bfloat16* GT_b = GTB + (size_t)kQ * 384;
        const float* qb_b = query_bias + (size_t)kN * kN;
        ln_k<<<(int)(kTOK / 8), 256>>>(hs, norm_w, norm_b, nhB);
        gemm(nhB, GT_b, nullptr, nullptr, nullptr, UB,
             (int)kTOK, kQ, kQ, kQ, 384, 0, kQ, 0,
             0, 0, 0, 0, 0, 1, 1, 1.f, 8 | 32);
        gemm(UB, posetB, nullptr, nullptr, aqP, nullptr,
             kN, kN, kQ, kQ, kQ, kN, 0, 0,
             (long)kN * kQ, (long)kN * kQ, (long)kN * kN, 0, 0, 1, kB * kT, SCALE, 0);
        softmax_aq_k<<<(int)kTOK, 256>>>(aqP, qb_b, aqB);
        gemm(aqB, akvWoT + (size_t)kB * kT * kQ * kN, nullptr,
             vtokWoP + (size_t)kB * kN * kQ, hs, nullptr,
             kN, kQ, kN, kN, kN, kQ, 0, kQ,
             (long)kN * kN, (long)kQ * kN, (long)kN * kQ, 0, 0, 1, kB * kT,
             1.f, 1 | 256);
    }

    // ---- FF: LN -> fused FF1+GEGLU -> FF2 writes d_out directly ----
    ln_k<<<(int)(kTOK / 8), 256>>>(hs, ffln_w, ffln_b, nhB);
    gemm(nhB, fw1T, ffb1iP, nullptr, nullptr, ggB,
         (int)kTOK, 2 * kFF, kQ, kQ, kQ, 0, kFF, 0,
         0, 0, 0, 0, 0, 1, 1, 1.f, 4 | 32 | 512);
    gemm(ggB, fw2T, ff_b2, nullptr, hs, nullptr,
         (int)kTOK, kQ, kFF, kFF, kFF, kQ, 0, 0,
         0, 0, 0, 0, 0, 1, 1, 1.f, 1 | 4 | 1024, 0, (float*)d_out);
}

// round 15
// speedup vs baseline: 1.2977x; 1.1058x over previous
#include <cuda_runtime.h>
#include <cuda_bf16.h>
#include <math.h>
#include <stdint.h>

// ---------------- problem constants ----------------
constexpr int kB = 2;
constexpr int kT = 16;
constexpr int kN = 1024;
constexpr int kC = 2;
constexpr int kCtok = 256;
constexpr int kQ = 320;
constexpr int kI = 512;
constexpr int kCD = 1024;
constexpr int kFF = 1280;
constexpr long kHS = (long)kB * kT * kN * kQ;
constexpr long kTOK = (long)kB * kT * kN;        // 32768

// ---------------- streams/events (created once at program init) ----------------
static cudaStream_t g_s2 = [] { cudaStream_t s; cudaStreamCreate(&s); return s; }();
static cudaEvent_t g_e0 = [] { cudaEvent_t e; cudaEventCreateWithFlags(&e, cudaEventDisableTiming); return e; }();
static cudaEvent_t g_e1 = [] { cudaEvent_t e; cudaEventCreateWithFlags(&e, cudaEventDisableTiming); return e; }();

// ---------------- fp32 scratch ----------------
static __device__ float g_hs[kHS];
static __device__ float g_v[(long)2 * kB * kC * kCtok * kI];
static __device__ float g_scores[(long)2 * kTOK * kI];
static __device__ float g_akv[(long)2 * kTOK * kI];
static __device__ float g_vdmax[(long)2 * kB * kCtok * kI];
static __device__ float g_vtokWo[(long)2 * kB * kN * kQ];
static __device__ float g_aq[kTOK * kN];
static __device__ float g_ffb1i[2 * kFF];

// ---------------- bf16 scratch ----------------
static __device__ __nv_bfloat16 b_poset[kHS];
static __device__ __nv_bfloat16 b_ctxperm[(long)kB * 512 * kCD];
static __device__ __nv_bfloat16 b_ctx[(long)kB * kC * kCtok * kCD];
static __device__ __nv_bfloat16 b_WkT[(long)2 * kI * kCD];
static __device__ __nv_bfloat16 b_WvT[(long)2 * kI * kCD];
static __device__ __nv_bfloat16 b_Wanat[(long)2 * kQ * kI];
static __device__ __nv_bfloat16 b_Wqpad[(long)2 * 384 * kI];
static __device__ __nv_bfloat16 b_WoT[(long)2 * kQ * kI];
static __device__ __nv_bfloat16 b_ffw1T[(long)2 * kFF * kQ];
static __device__ __nv_bfloat16 b_ffw2T[(long)kQ * kFF];
static __device__ __nv_bfloat16 b_kP[(long)2 * kB * 512 * kI];
static __device__ __nv_bfloat16 b_vT[(long)2 * kB * kC * kI * kCtok];
static __device__ __nv_bfloat16 b_S[(long)2 * kB * 512 * kQ];
static __device__ __nv_bfloat16 b_GT[(long)2 * kQ * 384];
static __device__ __nv_bfloat16 b_U[kTOK * kQ];
static __device__ __nv_bfloat16 b_scores[(long)2 * kTOK * kI];
static __device__ __nv_bfloat16 b_akv[(long)2 * kTOK * kI];
static __device__ __nv_bfloat16 b_akvWoT[(long)2 * kB * kT * kQ * kN];
static __device__ __nv_bfloat16 b_aq[kTOK * kN];
static __device__ __nv_bfloat16 b_vtok[(long)2 * kB * kN * kI];
static __device__ __nv_bfloat16 b_nh[kHS];
static __device__ __nv_bfloat16 b_gg[kTOK * kFF];

// ---------------- PTX helpers ----------------
__device__ __forceinline__ uint32_t smem_u32(const void* p) {
    return (uint32_t)__cvta_generic_to_shared(p);
}
__device__ __forceinline__ void cp16(uint32_t dst, const void* src, int src_bytes) {
    asm volatile("cp.async.cg.shared.global [%0], [%1], 16, %2;\n"
                 :: "r"(dst), "l"(src), "r"(src_bytes));
}
__device__ __forceinline__ void cp_commit() { asm volatile("cp.async.commit_group;\n"); }
template<int W> __device__ __forceinline__ void cp_wait() {
    asm volatile("cp.async.wait_group %0;\n" :: "n"(W));
}
__device__ __forceinline__ void ldsm4(uint32_t& r0, uint32_t& r1, uint32_t& r2, uint32_t& r3,
                                      uint32_t addr) {
    asm volatile("ldmatrix.sync.aligned.m8n8.x4.shared.b16 {%0,%1,%2,%3}, [%4];"
                 : "=r"(r0), "=r"(r1), "=r"(r2), "=r"(r3) : "r"(addr));
}
__device__ __forceinline__ void mma16(float* d, const uint32_t* a, const uint32_t* b) {
    asm volatile(
        "mma.sync.aligned.m16n8k16.row.col.f32.bf16.bf16.f32 "
        "{%0,%1,%2,%3},{%4,%5,%6,%7},{%8,%9},{%0,%1,%2,%3};"
        : "+f"(d[0]), "+f"(d[1]), "+f"(d[2]), "+f"(d[3])
        : "r"(a[0]), "r"(a[1]), "r"(a[2]), "r"(a[3]), "r"(b[0]), "r"(b[1]));
}

// ---------------- bf16 NT tensor-core GEMM (XOR-swizzled smem + ldmatrix, 2-stage) ----------------
// C(MxN) = alpha * A(MxK,bf16,row) * B(NxK,bf16,row)^T + epilogues.
// Batch: A index = aMod ? (z % aMod) : z ;  B index = z / bDiv ; C/Cb index = z.
// flags: 1 += C ; 2 max C ; 4 += bias[col] ; 8 bf16 natural Cb ; 16 bf16 transposed Cb ;
//        32 suppress fp32 write ; 256 += aux[((z>>4)*1024+row)*ldaux+col] ;
//        512 GEGLU pair epilogue ; 1024 write fp32 result to C2 (not Cp)
// smem: per k-tile row r (128 rows), 32 bf16 = four 16B chunks; chunk c at c ^ ((r>>1)&3).
constexpr int ROWE = 32;

__global__ __launch_bounds__(256, 2)
void bgemm_k(const __nv_bfloat16* __restrict__ A, const __nv_bfloat16* __restrict__ Bm,
             const float* __restrict__ bias, const float* __restrict__ aux,
             float* __restrict__ C, __nv_bfloat16* __restrict__ Cb,
             float* __restrict__ C2,
             int M, int N, int K, int lda, int ldb, int ldc, int ldcb, int ldaux,
             long strA, long strB, long strC, long strCb,
             int aMod, int bDiv, float alpha, int flags)
{
    __shared__ __align__(16) __nv_bfloat16 sA[2][128 * ROWE];
    __shared__ __align__(16) __nv_bfloat16 sB[2][128 * ROWE];

    const int z = blockIdx.z;
    const int za = aMod ? (z % aMod) : z;
    const __nv_bfloat16* Ap = A + (size_t)za * strA;
    const __nv_bfloat16* Bp = Bm + (size_t)(z / bDiv) * strB;
    float* Cp = C + (size_t)z * strC;
    __nv_bfloat16* Cbp = Cb + (size_t)z * strCb;
    const int m0 = blockIdx.y * 128, n0 = blockIdx.x * 128;
    const int tid = threadIdx.x;
    const int lane = tid & 31, warp = tid >> 5;
    const int wm = warp & 1, wn = warp >> 1;      // 2x4 warps; warp tile 64x32
    const int gid = lane >> 2, tig = lane & 3;

    // ldmatrix lane coordinates
    const int a_r = lane & 15;            // row within 16-row tile
    const int a_ch = lane >> 4;           // 0/1 -> chunk offset within k16
    const int b_r = ((lane >> 4) & 1) * 8 + (lane & 7);
    const int b_ch = (lane >> 3) & 1;

    const uint32_t aAddr0 = smem_u32(&sA[0][0]);
    const uint32_t bAddr0 = smem_u32(&sB[0][0]);

    float acc[4][4][4];
    #pragma unroll
    for (int i = 0; i < 4; i++)
        #pragma unroll
        for (int j = 0; j < 4; j++)
            #pragma unroll
            for (int r = 0; r < 4; r++) acc[i][j][r] = 0.f;

    const int kTiles = K >> 5;

    auto load_tile = [&](int buf, int kt) {
        const int k0 = kt << 5;
        __nv_bfloat16* sa = &sA[buf][0];
        __nv_bfloat16* sb = &sB[buf][0];
        #pragma unroll
        for (int j = 0; j < 2; j++) {
            int i = tid + 256 * j;
            int r = i >> 2, c = i & 3;
            int dc = c ^ ((r >> 1) & 3);
            cp16(smem_u32(&sa[r * ROWE + dc * 8]),
                 Ap + (size_t)(m0 + r) * lda + k0 + c * 8, 16);
        }
        #pragma unroll
        for (int j = 0; j < 2; j++) {
            int i = tid + 256 * j;
            int r = i >> 2, c = i & 3;
            int dc = c ^ ((r >> 1) & 3);
            int gn = n0 + r;
            cp16(smem_u32(&sb[r * ROWE + dc * 8]),
                 Bp + (size_t)gn * ldb + k0 + c * 8, gn < N ? 16 : 0);
        }
        cp_commit();
    };

    auto compute_tile = [&](int buf) {
        const uint32_t aBase = aAddr0 + (uint32_t)buf * 128 * ROWE * 2;
        const uint32_t bBase = bAddr0 + (uint32_t)buf * 128 * ROWE * 2;
        #pragma unroll
        for (int s = 0; s < 2; s++) {
            const int kc = s * 2;                 // chunk base for this k16
            uint32_t af[4][4], bf[4][2];
            #pragma unroll
            for (int mt = 0; mt < 4; mt++) {
                int row = wm * 64 + mt * 16 + a_r;
                int ch = (kc + a_ch) ^ ((row >> 1) & 3);
                uint32_t addr = aBase + (uint32_t)((row * ROWE + ch * 8) * 2);
                ldsm4(af[mt][0], af[mt][1], af[mt][2], af[mt][3], addr);
            }
            #pragma unroll
            for (int j = 0; j < 2; j++) {
                int row = wn * 32 + j * 16 + b_r;
                int ch = (kc + b_ch) ^ ((row >> 1) & 3);
                uint32_t addr = bBase + (uint32_t)((row * ROWE + ch * 8) * 2);
                ldsm4(bf[2 * j][0], bf[2 * j][1], bf[2 * j + 1][0], bf[2 * j + 1][1], addr);
            }
            #pragma unroll
            for (int mt = 0; mt < 4; mt++)
                #pragma unroll
                for (int nt = 0; nt < 4; nt++)
                    mma16(acc[mt][nt], af[mt], bf[nt]);
        }
    };

    load_tile(0, 0);
    for (int kt = 0; kt < kTiles; kt++) {
        if (kt + 1 < kTiles) {
            load_tile((kt + 1) & 1, kt + 1);
            cp_wait<1>();
        } else {
            cp_wait<0>();
        }
        __syncthreads();
        compute_tile(kt & 1);
        __syncthreads();
    }

    #pragma unroll
    for (int mt = 0; mt < 4; mt++) {
        #pragma unroll
        for (int nt = 0; nt < 4; nt++) {
            int row0 = m0 + wm * 64 + mt * 16 + gid;
            int col0 = n0 + wn * 32 + nt * 8 + tig * 2;
            if (flags & 512) {
                float ba = bias[col0], bg = bias[col0 + 1];
                #pragma unroll
                for (int h = 0; h < 2; h++) {
                    int rr = row0 + h * 8;
                    float a = alpha * acc[mt][nt][2 * h] + ba;
                    float g = alpha * acc[mt][nt][2 * h + 1] + bg;
                    float gg = a * 0.5f * g * (1.f + erff(g * 0.70710678118654752f));
                    Cbp[(size_t)rr * ldcb + (col0 >> 1)] = __float2bfloat16(gg);
                }
                continue;
            }
            #pragma unroll
            for (int r = 0; r < 4; r++) {
                int rr = row0 + (r >> 1) * 8;
                int cc = col0 + (r & 1);
                if (cc >= N) continue;
                float vv = alpha * acc[mt][nt][r];
                size_t off = (size_t)rr * ldc + cc;
                if (flags & 4)   vv += bias[cc];
                if (flags & 256) vv += aux[(((size_t)(z >> 4)) * 1024 + rr) * ldaux + cc];
                if (flags & 1) vv += Cp[off];
                if (flags & 2) vv = fmaxf(vv, Cp[off]);
                if (flags & 1024) C2[off] = vv;
                else if (!(flags & 32)) Cp[off] = vv;
                if (flags & 8)  Cbp[(size_t)rr * ldcb + cc] = __float2bfloat16(vv);
                if (flags & 16) Cbp[(size_t)cc * ldcb + rr] = __float2bfloat16(vv);
            }
        }
    }
}

static void gemm(const __nv_bfloat16* A, const __nv_bfloat16* B, const float* bias,
                 const float* aux, float* C, __nv_bfloat16* Cb,
                 int M, int N, int K, int lda, int ldb, int ldc, int ldcb, int ldaux,
                 long sA, long sB, long sC, long sCb, int aMod, int bDiv, int batch,
                 float alpha, int flags, cudaStream_t st = 0, float* C2 = nullptr)
{
    dim3 gr((N + 127) / 128, M / 128, batch);
    bgemm_k<<<gr, 256, 0, st>>>(A, B, bias, aux, C, Cb, C2, M, N, K,
                                lda, ldb, ldc, ldcb, ldaux,
                                sA, sB, sC, sCb, aMod, bDiv, alpha, flags);
}

// ---------------- merged prologue 1 ----------------
constexpr long P1_S0 = kHS;
constexpr long P1_S1 = P1_S0 + kHS;
constexpr long P1_S2 = P1_S1 + (long)kB * 512 * kCD;
__global__ void pcperm_k(const float* __restrict__ hidden, const float* __restrict__ pose,
                         const float* __restrict__ ctx,
                         float* __restrict__ hs, __nv_bfloat16* __restrict__ poset,
                         __nv_bfloat16* __restrict__ ctxperm)
{
    long idx = (long)blockIdx.x * blockDim.x + threadIdx.x;
    if (idx < P1_S0) {
        hs[idx] = hidden[idx];
    } else if (idx < P1_S1) {
        long i = idx - P1_S0;
        int d = (int)(i % kQ);
        long r = i / kQ;
        int n = (int)(r % kN); r /= kN;
        int t = (int)(r % kT); int b = (int)(r / kT);
        int h = n >> 5, w = n & 31;
        poset[i] = __float2bfloat16(pose[(((((size_t)b * kQ + d) * kT + t) * 32 + h) * 32) + w]);
    } else if (idx < P1_S2) {
        long i = idx - P1_S1;
        int k = (int)(i % kCD);
        long r0 = i / kCD;
        int r = (int)(r0 % 512); int b = (int)(r0 / 512);
        int n = ((r & 255) << 1) | (r >> 8);
        ctxperm[i] = __float2bfloat16(ctx[(((size_t)b * kC + (n >> 8)) * kCtok + (n & 255)) * kCD + k]);
    }
}

// ---------------- merged prologue 2 ----------------
constexpr long Q_S0 = (long)kB * kC * kCtok * kCD;
constexpr long Q_S1 = Q_S0 + (long)2 * kCD * kI;
constexpr long Q_S2 = Q_S1 + (long)2 * kQ * kI;
constexpr long Q_S3 = Q_S2 + (long)2 * kCD * kI;
constexpr long Q_S4 = Q_S3 + (long)2 * 384 * kI;
constexpr long Q_S5 = Q_S4 + (long)2 * kI * kQ;
constexpr long Q_S6 = Q_S5 + (long)2 * kFF * kQ;
constexpr long Q_S7 = Q_S6 + 2 * kFF;
constexpr long Q_S8 = Q_S7 + (long)kFF * kQ;
__global__ void prep_k(const float* __restrict__ ctx, const float* __restrict__ Wk,
                       const float* __restrict__ Wa, const float* __restrict__ Wv,
                       const float* __restrict__ Wq, const float* __restrict__ Wo,
                       const float* __restrict__ ffw1, const float* __restrict__ ffb1,
                       const float* __restrict__ ffw2,
                       __nv_bfloat16* __restrict__ ctxB, __nv_bfloat16* __restrict__ WkT,
                       __nv_bfloat16* __restrict__ WaN, __nv_bfloat16* __restrict__ WvT,
                       __nv_bfloat16* __restrict__ WqP, __nv_bfloat16* __restrict__ WoT,
                       __nv_bfloat16* __restrict__ fw1T, float* __restrict__ ffb1i,
                       __nv_bfloat16* __restrict__ fw2T)
{
    long idx = (long)blockIdx.x * blockDim.x + threadIdx.x;
    if (idx < Q_S0) {
        ctxB[idx] = __float2bfloat16(ctx[idx]);
    } else if (idx < Q_S1) {
        long i = idx - Q_S0;
        int r = (int)(i % kCD);
        long q = i / kCD;
        int c = (int)(q % kI);
        int b = (int)(q / kI);
        WkT[i] = __float2bfloat16(Wk[((size_t)b * kCD + r) * kI + c]);
    } else if (idx < Q_S2) {
        long i = idx - Q_S1;
        WaN[i] = __float2bfloat16(Wa[i]);
    } else if (idx < Q_S3) {
        long i = idx - Q_S2;
        int r = (int)(i % kCD);
        long q = i / kCD;
        int c = (int)(q % kI);
        int b = (int)(q / kI);
        WvT[i] = __float2bfloat16(Wv[((size_t)b * kCD + r) * kI + c]);
    } else if (idx < Q_S4) {
        long i = idx - Q_S3;
        int c = (int)(i % kI);
        long q = i / kI;
        int r = (int)(q % 384);
        int blk = (int)(q / 384);
        WqP[i] = (r < kQ) ? __float2bfloat16(Wq[((size_t)blk * kQ + r) * kI + c])
                          : __float2bfloat16(0.f);
    } else if (idx < Q_S5) {
        long i = idx - Q_S4;
        int r = (int)(i % kI);
        long q = i / kI;
        int c = (int)(q % kQ);
        int b = (int)(q / kQ);
        WoT[i] = __float2bfloat16(Wo[((size_t)b * kI + r) * kQ + c]);
    } else if (idx < Q_S6) {
        long i = idx - Q_S5;
        int k = (int)(i % kQ);
        int e = (int)(i / kQ);
        int oc = (e & 1) ? (kFF + (e >> 1)) : (e >> 1);
        fw1T[i] = __float2bfloat16(ffw1[(size_t)k * (2 * kFF) + oc]);
    } else if (idx < Q_S7) {
        int e = (int)(idx - Q_S6);
        int oc = (e & 1) ? (kFF + (e >> 1)) : (e >> 1);
        ffb1i[e] = ffb1[oc];
    } else if (idx < Q_S8) {
        long i = idx - Q_S7;
        int r = (int)(i % kFF);
        int c = (int)(i / kFF);
        fw2T[i] = __float2bfloat16(ffw2[(size_t)r * kQ + c]);
    }
}

// ---------------- LayerNorm: warp-per-row, float4 I/O ----------------
__global__ void ln_k(const float* __restrict__ x, const float* __restrict__ w,
                     const float* __restrict__ b, __nv_bfloat16* __restrict__ y)
{
    int row = blockIdx.x * 8 + (threadIdx.x >> 5);
    int lane = threadIdx.x & 31;
    const float4* xp = (const float4*)(x + (size_t)row * kQ);
    float4 v[3];
    float s1 = 0.f, s2 = 0.f;
    #pragma unroll
    for (int i = 0; i < 3; i++) {
        int idx = lane + 32 * i;
        if (idx < 80) {
            v[i] = xp[idx];
            s1 += v[i].x + v[i].y + v[i].z + v[i].w;
            s2 += v[i].x * v[i].x + v[i].y * v[i].y + v[i].z * v[i].z + v[i].w * v[i].w;
        }
    }
    #pragma unroll
    for (int o = 16; o; o >>= 1) {
        s1 += __shfl_xor_sync(0xffffffffu, s1, o);
        s2 += __shfl_xor_sync(0xffffffffu, s2, o);
    }
    float mean = s1 / kQ;
    float rstd = rsqrtf(s2 / kQ - mean * mean + 1e-5f);
    __nv_bfloat162* yp = (__nv_bfloat162*)(y + (size_t)row * kQ);
    const float4* wp = (const float4*)w;
    const float4* bp = (const float4*)b;
    #pragma unroll
    for (int i = 0; i < 3; i++) {
        int idx = lane + 32 * i;
        if (idx < 80) {
            float4 wv = wp[idx], bv = bp[idx];
            float o0 = (v[i].x - mean) * rstd * wv.x + bv.x;
            float o1 = (v[i].y - mean) * rstd * wv.y + bv.y;
            float o2 = (v[i].z - mean) * rstd * wv.z + bv.z;
            float o3 = (v[i].w - mean) * rstd * wv.w + bv.w;
            yp[idx * 2]     = __floats2bfloat162_rn(o0, o1);
            yp[idx * 2 + 1] = __floats2bfloat162_rn(o2, o3);
        }
    }
}

// ---------------- softmax kv groups, both blocks ----------------
__global__ void softmax_kv_k(const float* __restrict__ s, const float* __restrict__ abias,
                             __nv_bfloat16* __restrict__ ob)
{
    int gr = blockIdx.x;
    int c2 = blockIdx.y;
    int blk = gr >> 15;
    int m = gr & 1023;
    const float* p = s + (size_t)gr * 512 + c2 * 256;
    __nv_bfloat16* po = ob + (size_t)gr * 512 + c2 * 256;
    int tid = threadIdx.x;
    float v = p[tid] + abias[((size_t)blk * kN + m) * 256 + tid];
    __shared__ float red[256];
    red[tid] = v; __syncthreads();
    for (int st = 128; st; st >>= 1) { if (tid < st) red[tid] = fmaxf(red[tid], red[tid + st]); __syncthreads(); }
    float mx = red[0]; __syncthreads();
    float e = __expf(v - mx);
    red[tid] = e; __syncthreads();
    for (int st = 128; st; st >>= 1) { if (tid < st) red[tid] += red[tid + st]; __syncthreads(); }
    po[tid] = __float2bfloat16(e / red[0]);
}

// ---------------- softmax query rows ----------------
__global__ void softmax_aq_k(const float* __restrict__ s, const float* __restrict__ qbias,
                             __nv_bfloat16* __restrict__ ob)
{
    int gr = blockIdx.x;
    int n = gr & 1023;
    const float* p = s + (size_t)gr * 1024;
    __nv_bfloat16* po = ob + (size_t)gr * 1024;
    const float* bp = qbias + (size_t)n * 1024;
    int tid = threadIdx.x;
    float v[4];
    float mx = -1e30f;
    #pragma unroll
    for (int k = 0; k < 4; k++) { v[k] = p[tid + k * 256] + bp[tid + k * 256]; mx = fmaxf(mx, v[k]); }
    __shared__ float red[256];
    red[tid] = mx; __syncthreads();
    for (int st = 128; st; st >>= 1) { if (tid < st) red[tid] = fmaxf(red[tid], red[tid + st]); __syncthreads(); }
    mx = red[0]; __syncthreads();
    float sum = 0.f;
    #pragma unroll
    for (int k = 0; k < 4; k++) { v[k] = __expf(v[k] - mx); sum += v[k]; }
    red[tid] = sum; __syncthreads();
    for (int st = 128; st; st >>= 1) { if (tid < st) red[tid] += red[tid + st]; __syncthreads(); }
    float inv = 1.f / red[0];
    #pragma unroll
    for (int k = 0; k < 4; k++) po[tid + k * 256] = __float2bfloat16(v[k] * inv);
}

// ---------------- dwconv (both blocks) ----------------
__global__ void dwconv_k(const float* __restrict__ v, const float* __restrict__ wgt,
                         const float* __restrict__ bias, float* __restrict__ out)
{
    int pix = blockIdx.x & 255;
    int b = (blockIdx.x >> 8) & 1;
    int blk = blockIdx.x >> 9;
    int e = threadIdx.x;
    int h = pix >> 4, w = pix & 15;
    const float* wp = wgt + (size_t)blk * kI * 9;
    float wv[9];
    #pragma unroll
    for (int t9 = 0; t9 < 9; t9++) wv[t9] = wp[e * 9 + t9];
    float best = -1e30f;
    #pragma unroll
    for (int c = 0; c < 2; c++) {
        float s = 0.f;
        #pragma unroll
        for (int dh = -1; dh <= 1; dh++)
            #pragma unroll
            for (int dw = -1; dw <= 1; dw++) {
                int hh = h + dh, ww = w + dw;
                if (hh < 0 || hh > 15 || ww < 0 || ww > 15) continue;
                s += v[(((size_t)(blk * kB + b) * kC + c) * kCtok + hh * 16 + ww) * kI + e]
                     * wv[(dh + 1) * 3 + (dw + 1)];
            }
        best = fmaxf(best, s);
    }
    out[((size_t)(blk * kB + b) * kCtok + pix) * kI + e] = best + bias[(size_t)blk * kI + e];
}

// ---------------- bilinear x2 upsample -> bf16 (both blocks) ----------------
__global__ void upsample_k(const float* __restrict__ vd, __nv_bfloat16* __restrict__ vtok)
{
    int opix = blockIdx.x & 1023;
    int bb = blockIdx.x >> 10;
    int e = threadIdx.x;
    int y = opix >> 5, x = opix & 31;
    int py = y >> 1, px = x >> 1;
    int y0, y1, x0, x1; float wy0, wy1, wx0, wx1;
    if (y & 1) { y0 = py; y1 = min(py + 1, 15); wy0 = 0.75f; wy1 = 0.25f; }
    else       { y0 = max(py - 1, 0); y1 = py;  wy0 = 0.25f; wy1 = 0.75f; }
    if (x & 1) { x0 = px; x1 = min(px + 1, 15); wx0 = 0.75f; wx1 = 0.25f; }
    else       { x0 = max(px - 1, 0); x1 = px;  wx0 = 0.25f; wx1 = 0.75f; }
    const float* base = vd + (size_t)bb * kCtok * kI;
    float r = wy0 * wx0 * base[(size_t)(y0 * 16 + x0) * kI + e]
            + wy0 * wx1 * base[(size_t)(y0 * 16 + x1) * kI + e]
            + wy1 * wx0 * base[(size_t)(y1 * 16 + x0) * kI + e]
            + wy1 * wx1 * base[(size_t)(y1 * 16 + x1) * kI + e];
    vtok[((size_t)bb * kN + opix) * kI + e] = __float2bfloat16(r);
}

// ---------------- launch ----------------
extern "C" void kernel_launch(void* const* d_in, const int* in_sizes, int n_in,
                              void* d_out, int out_size)
{
    const float* hidden     = (const float*)d_in[0];
    const float* context    = (const float*)d_in[1];
    const float* pose       = (const float*)d_in[2];
    const float* Wq         = (const float*)d_in[3];
    const float* Wk         = (const float*)d_in[4];
    const float* Wv         = (const float*)d_in[5];
    const float* Wa         = (const float*)d_in[6];
    const float* agent_bias = (const float*)d_in[7];
    const float* query_bias = (const float*)d_in[8];
    const float* dwc_w      = (const float*)d_in[9];
    const float* dwc_b      = (const float*)d_in[10];
    const float* Wo         = (const float*)d_in[11];
    const float* norm_w     = (const float*)d_in[12];
    const float* norm_b     = (const float*)d_in[13];
    const float* ffln_w     = (const float*)d_in[14];
    const float* ffln_b     = (const float*)d_in[15];
    const float* ff_w1      = (const float*)d_in[16];
    const float* ff_b1      = (const float*)d_in[17];
    const float* ff_w2      = (const float*)d_in[18];
    const float* ff_b2      = (const float*)d_in[19];

    float *hs, *vP, *scoresP, *akvP, *vdP, *vtokWoP, *aqP, *ffb1iP;
    cudaGetSymbolAddress((void**)&hs, g_hs);
    cudaGetSymbolAddress((void**)&vP, g_v);
    cudaGetSymbolAddress((void**)&scoresP, g_scores);
    cudaGetSymbolAddress((void**)&akvP, g_akv);
    cudaGetSymbolAddress((void**)&vdP, g_vdmax);
    cudaGetSymbolAddress((void**)&vtokWoP, g_vtokWo);
    cudaGetSymbolAddress((void**)&aqP, g_aq);
    cudaGetSymbolAddress((void**)&ffb1iP, g_ffb1i);

    __nv_bfloat16 *posetB, *ctxpermB, *ctxB, *WkT, *WvT, *WaN, *WqP, *WoT, *fw1T, *fw2T,
                  *kPB, *vTB, *SB, *GTB, *UB, *scoresB, *akvB, *akvWoT, *aqB, *vtokB, *nhB, *ggB;
    cudaGetSymbolAddress((void**)&posetB, b_poset);
    cudaGetSymbolAddress((void**)&ctxpermB, b_ctxperm);
    cudaGetSymbolAddress((void**)&ctxB, b_ctx);
    cudaGetSymbolAddress((void**)&WkT, b_WkT);
    cudaGetSymbolAddress((void**)&WvT, b_WvT);
    cudaGetSymbolAddress((void**)&WaN, b_Wanat);
    cudaGetSymbolAddress((void**)&WqP, b_Wqpad);
    cudaGetSymbolAddress((void**)&WoT, b_WoT);
    cudaGetSymbolAddress((void**)&fw1T, b_ffw1T);
    cudaGetSymbolAddress((void**)&fw2T, b_ffw2T);
    cudaGetSymbolAddress((void**)&kPB, b_kP);
    cudaGetSymbolAddress((void**)&vTB, b_vT);
    cudaGetSymbolAddress((void**)&SB, b_S);
    cudaGetSymbolAddress((void**)&GTB, b_GT);
    cudaGetSymbolAddress((void**)&UB, b_U);
    cudaGetSymbolAddress((void**)&scoresB, b_scores);
    cudaGetSymbolAddress((void**)&akvB, b_akv);
    cudaGetSymbolAddress((void**)&akvWoT, b_akvWoT);
    cudaGetSymbolAddress((void**)&aqB, b_aq);
    cudaGetSymbolAddress((void**)&vtokB, b_vtok);
    cudaGetSymbolAddress((void**)&nhB, b_nh);
    cudaGetSymbolAddress((void**)&ggB, b_gg);

    const float SCALE = 0.125f;
    auto cdiv = [](long a, long b) { return (int)((a + b - 1) / b); };

    // ===== shared prologue =====
    pcperm_k<<<cdiv(P1_S2, 256), 256>>>(hidden, pose, context, hs, posetB, ctxpermB);
    prep_k<<<cdiv(Q_S8, 256), 256>>>(context, Wk, Wa, Wv, Wq, Wo, ff_w1, ff_b1, ff_w2,
                                     ctxB, WkT, WaN, WvT, WqP, WoT, fw1T, ffb1iP, fw2T);

    // fork: stream 2 runs the hs-side blk0 chain
    cudaEventRecord(g_e0, 0);
    cudaStreamWaitEvent(g_s2, g_e0, 0);

    gemm(WqP, WaN, nullptr, nullptr, nullptr, GTB,
         384, kQ, kI, kI, kI, 0, 384, 0,
         (long)384 * kI, (long)kQ * kI, 0, (long)kQ * 384, 0, 1, 2, 1.f, 16 | 32, g_s2);
    ln_k<<<(int)(kTOK / 8), 256, 0, g_s2>>>(hs, norm_w, norm_b, nhB);
    gemm(nhB, GTB, nullptr, nullptr, nullptr, UB,
         (int)kTOK, kQ, kQ, kQ, 384, 0, kQ, 0,
         0, 0, 0, 0, 0, 1, 1, 1.f, 8 | 32, g_s2);
    gemm(UB, posetB, nullptr, nullptr, aqP, nullptr,
         kN, kN, kQ, kQ, kQ, kN, 0, 0,
         (long)kN * kQ, (long)kN * kQ, (long)kN * kN, 0, 0, 1, kB * kT, SCALE, 0, g_s2);
    softmax_aq_k<<<(int)kTOK, 256, 0, g_s2>>>(aqP, query_bias, aqB);
    cudaEventRecord(g_e1, g_s2);

    // ===== main stream: kv side, both blocks batched =====
    gemm(ctxpermB, WkT, nullptr, nullptr, nullptr, kPB,
         512, kI, kCD, kCD, kCD, 0, kI, 0,
         512L * kCD, (long)kI * kCD, 0, 512L * kI, 2, 2, 4, 1.f, 8 | 32);
    gemm(kPB, WaN, nullptr, nullptr, nullptr, SB,
         512, kQ, kI, kI, kI, 0, kQ, 0,
         512L * kI, (long)kQ * kI, 0, 512L * kQ, 0, 2, 4, 1.f, 8 | 32);
    gemm(posetB, SB, nullptr, nullptr, scoresP, nullptr,
         kN, 512, kQ, kQ, kQ, 512, 0, 0,
         (long)kN * kQ, 512L * kQ, (long)kN * 512, 0, 32, 16, 64, SCALE, 0);
    softmax_kv_k<<<dim3(2 * (int)kTOK, 2), 256>>>(scoresP, agent_bias, scoresB);
    gemm(ctxB, WvT, nullptr, nullptr, vP, vTB,
         kCtok, kI, kCD, kCD, kCD, kI, kCtok, 0,
         (long)kCtok * kCD, (long)kI * kCD, (long)kCtok * kI, (long)kI * kCtok, 4, 4, 8, 1.f, 16);
    gemm(scoresB, vTB, nullptr, nullptr, akvP, nullptr,
         kN, kI, kCtok, 512, kCtok, kI, 0, 0,
         (long)kN * 512, (long)kC * kI * kCtok, (long)kN * kI, 0, 0, 16, 64, 1.f, 0);
    gemm(scoresB + 256, vTB + (size_t)kI * kCtok, nullptr, nullptr, akvP, akvB,
         kN, kI, kCtok, 512, kCtok, kI, kI, 0,
         (long)kN * 512, (long)kC * kI * kCtok, (long)kN * kI, (long)kN * kI, 0, 16, 64,
         1.f, 2 | 8 | 32);
    gemm(akvB, WoT, nullptr, nullptr, akvP, akvWoT,
         kN, kQ, kI, kI, kI, kQ, kN, 0,
         (long)kN * kI, (long)kQ * kI, 0, (long)kQ * kN, 0, 32, 64, 1.f, 16 | 32);
    dwconv_k<<<2 * kB * kCtok, kI>>>(vP, dwc_w, dwc_b, vdP);
    upsample_k<<<2 * kB * kN, kI>>>(vdP, vtokB);
    gemm(vtokB, WoT, nullptr, nullptr, vtokWoP, nullptr,
         kN, kQ, kI, kI, kI, kQ, 0, 0,
         (long)kN * kI, (long)kQ * kI, (long)kN * kQ, 0, 0, 2, 4, 1.f, 0);

    // join
    cudaStreamWaitEvent(0, g_e1, 0);

    // ===== Phase B blk0 final, then full blk1 chain =====
    gemm(aqB, akvWoT, nullptr, vtokWoP, hs, nullptr,
         kN, kQ, kN, kN, kN, kQ, 0, kQ,
         (long)kN * kN, (long)kQ * kN, (long)kN * kQ, 0, 0, 1, kB * kT,
         1.f, 1 | 256);

    {
        const __nv_bfloat16* GT_b = GTB + (size_t)kQ * 384;
        const float* qb_b = query_bias + (size_t)kN * kN;
        ln_k<<<(int)(kTOK / 8), 256>>>(hs, norm_w, norm_b, nhB);
        gemm(nhB, GT_b, nullptr, nullptr, nullptr, UB,
             (int)kTOK, kQ, kQ, kQ, 384, 0, kQ, 0,
             0, 0, 0, 0, 0, 1, 1, 1.f, 8 | 32);
        gemm(UB, posetB, nullptr, nullptr, aqP, nullptr,
             kN, kN, kQ, kQ, kQ, kN, 0, 0,
             (long)kN * kQ, (long)kN * kQ, (long)kN * kN, 0, 0, 1, kB * kT, SCALE, 0);
        softmax_aq_k<<<(int)kTOK, 256>>>(aqP, qb_b, aqB);
        gemm(aqB, akvWoT + (size_t)kB * kT * kQ * kN, nullptr,
             vtokWoP + (size_t)kB * kN * kQ, hs, nullptr,
             kN, kQ, kN, kN, kN, kQ, 0, kQ,
             (long)kN * kN, (long)kQ * kN, (long)kN * kQ, 0, 0, 1, kB * kT,
             1.f, 1 | 256);
    }

    // ---- FF: LN -> fused FF1+GEGLU -> FF2 writes d_out directly ----
    ln_k<<<(int)(kTOK / 8), 256>>>(hs, ffln_w, ffln_b, nhB);
    gemm(nhB, fw1T, ffb1iP, nullptr, nullptr, ggB,
         (int)kTOK, 2 * kFF, kQ, kQ, kQ, 0, kFF, 0,
         0, 0, 0, 0, 0, 1, 1, 1.f, 4 | 32 | 512);
    gemm(ggB, fw2T, ff_b2, nullptr, hs, nullptr,
         (int)kTOK, kQ, kFF, kFF, kFF, kQ, 0, 0,
         0, 0, 0, 0, 0, 1, 1, 1.f, 1 | 4 | 1024, 0, (float*)d_out);
}

// round 16
// speedup vs baseline: 1.3113x; 1.0105x over previous
#include <cuda_runtime.h>
#include <cuda_bf16.h>
#include <math.h>
#include <stdint.h>

// ---------------- problem constants ----------------
constexpr int kB = 2;
constexpr int kT = 16;
constexpr int kN = 1024;
constexpr int kC = 2;
constexpr int kCtok = 256;
constexpr int kQ = 320;
constexpr int kI = 512;
constexpr int kCD = 1024;
constexpr int kFF = 1280;
constexpr long kHS = (long)kB * kT * kN * kQ;
constexpr long kTOK = (long)kB * kT * kN;        // 32768

// ---------------- streams/events (created once at program init) ----------------
static cudaStream_t g_s2 = [] { cudaStream_t s; cudaStreamCreate(&s); return s; }();
static cudaEvent_t g_e0 = [] { cudaEvent_t e; cudaEventCreateWithFlags(&e, cudaEventDisableTiming); return e; }();
static cudaEvent_t g_e1 = [] { cudaEvent_t e; cudaEventCreateWithFlags(&e, cudaEventDisableTiming); return e; }();

// ---------------- fp32 scratch ----------------
static __device__ float g_hs[kHS];
static __device__ float g_v[(long)2 * kB * kC * kCtok * kI];
static __device__ float g_scores[(long)2 * kTOK * kI];
static __device__ float g_akv[(long)2 * kTOK * kI];
static __device__ float g_vdmax[(long)2 * kB * kCtok * kI];
static __device__ float g_vtokWo[(long)2 * kB * kN * kQ];
static __device__ float g_aq[kTOK * kN];
static __device__ float g_ffb1i[2 * kFF];

// ---------------- bf16 scratch ----------------
static __device__ __nv_bfloat16 b_poset[kHS];
static __device__ __nv_bfloat16 b_ctxperm[(long)kB * 512 * kCD];
static __device__ __nv_bfloat16 b_ctx[(long)kB * kC * kCtok * kCD];
static __device__ __nv_bfloat16 b_WkT[(long)2 * kI * kCD];
static __device__ __nv_bfloat16 b_WvT[(long)2 * kI * kCD];
static __device__ __nv_bfloat16 b_Wanat[(long)2 * kQ * kI];
static __device__ __nv_bfloat16 b_Wqpad[(long)2 * 384 * kI];
static __device__ __nv_bfloat16 b_WoT[(long)2 * kQ * kI];
static __device__ __nv_bfloat16 b_ffw1T[(long)2 * kFF * kQ];
static __device__ __nv_bfloat16 b_ffw2T[(long)kQ * kFF];
static __device__ __nv_bfloat16 b_kP[(long)2 * kB * 512 * kI];
static __device__ __nv_bfloat16 b_vT[(long)2 * kB * kC * kI * kCtok];
static __device__ __nv_bfloat16 b_S[(long)2 * kB * 512 * kQ];
static __device__ __nv_bfloat16 b_GT[(long)2 * kQ * 384];
static __device__ __nv_bfloat16 b_U[kTOK * kQ];
static __device__ __nv_bfloat16 b_scores[(long)2 * kTOK * kI];
static __device__ __nv_bfloat16 b_akv[(long)2 * kTOK * kI];
static __device__ __nv_bfloat16 b_akvWoT[(long)2 * kB * kT * kQ * kN];
static __device__ __nv_bfloat16 b_aq[kTOK * kN];
static __device__ __nv_bfloat16 b_vtok[(long)2 * kB * kN * kI];
static __device__ __nv_bfloat16 b_nh[kHS];
static __device__ __nv_bfloat16 b_gg[kTOK * kFF];

// ---------------- PTX helpers ----------------
__device__ __forceinline__ uint32_t smem_u32(const void* p) {
    return (uint32_t)__cvta_generic_to_shared(p);
}
__device__ __forceinline__ void cp16(uint32_t dst, const void* src, int src_bytes) {
    asm volatile("cp.async.cg.shared.global [%0], [%1], 16, %2;\n"
                 :: "r"(dst), "l"(src), "r"(src_bytes));
}
__device__ __forceinline__ void cp_commit() { asm volatile("cp.async.commit_group;\n"); }
template<int W> __device__ __forceinline__ void cp_wait() {
    asm volatile("cp.async.wait_group %0;\n" :: "n"(W));
}
__device__ __forceinline__ void ldsm4(uint32_t& r0, uint32_t& r1, uint32_t& r2, uint32_t& r3,
                                      uint32_t addr) {
    asm volatile("ldmatrix.sync.aligned.m8n8.x4.shared.b16 {%0,%1,%2,%3}, [%4];"
                 : "=r"(r0), "=r"(r1), "=r"(r2), "=r"(r3) : "r"(addr));
}
__device__ __forceinline__ void mma16(float* d, const uint32_t* a, const uint32_t* b) {
    asm volatile(
        "mma.sync.aligned.m16n8k16.row.col.f32.bf16.bf16.f32 "
        "{%0,%1,%2,%3},{%4,%5,%6,%7},{%8,%9},{%0,%1,%2,%3};"
        : "+f"(d[0]), "+f"(d[1]), "+f"(d[2]), "+f"(d[3])
        : "r"(a[0]), "r"(a[1]), "r"(a[2]), "r"(a[3]), "r"(b[0]), "r"(b[1]));
}

// ---------------- bf16 NT tensor-core GEMM (XOR swizzle + ldmatrix, 3-slot ring, 1 sync) ----------------
// C(MxN) = alpha * A(MxK,bf16,row) * B(NxK,bf16,row)^T + epilogues.
// Batch: A index = aMod ? (z % aMod) : z ;  B index = z / bDiv ; C/Cb index = z.
// flags: 1 += C ; 2 max C ; 4 += bias[col] ; 8 bf16 natural Cb ; 16 bf16 transposed Cb ;
//        32 suppress fp32 write ; 256 += aux[((z>>4)*1024+row)*ldaux+col] ;
//        512 GEGLU pair epilogue ; 1024 write fp32 result to C2 (not Cp)
// smem: per k-tile row r (128 rows), 32 bf16 = four 16B chunks; chunk c at c ^ ((r>>1)&3).
constexpr int ROWE = 32;
constexpr int SLOT = 128 * ROWE;   // elements per operand slot

__global__ __launch_bounds__(256, 2)
void bgemm_k(const __nv_bfloat16* __restrict__ A, const __nv_bfloat16* __restrict__ Bm,
             const float* __restrict__ bias, const float* __restrict__ aux,
             float* __restrict__ C, __nv_bfloat16* __restrict__ Cb,
             float* __restrict__ C2,
             int M, int N, int K, int lda, int ldb, int ldc, int ldcb, int ldaux,
             long strA, long strB, long strC, long strCb,
             int aMod, int bDiv, float alpha, int flags)
{
    __shared__ __align__(16) __nv_bfloat16 sA[3 * SLOT];
    __shared__ __align__(16) __nv_bfloat16 sB[3 * SLOT];

    const int z = blockIdx.z;
    const int za = aMod ? (z % aMod) : z;
    const __nv_bfloat16* Ap = A + (size_t)za * strA;
    const __nv_bfloat16* Bp = Bm + (size_t)(z / bDiv) * strB;
    float* Cp = C + (size_t)z * strC;
    __nv_bfloat16* Cbp = Cb + (size_t)z * strCb;
    const int m0 = blockIdx.y * 128, n0 = blockIdx.x * 128;
    const int tid = threadIdx.x;
    const int lane = tid & 31, warp = tid >> 5;
    const int wm = warp & 1, wn = warp >> 1;      // 2x4 warps; warp tile 64x32
    const int gid = lane >> 2, tig = lane & 3;

    // ldmatrix lane coordinates
    const int a_r = lane & 15;
    const int a_ch = lane >> 4;
    const int b_r = ((lane >> 4) & 1) * 8 + (lane & 7);
    const int b_ch = (lane >> 3) & 1;

    const uint32_t aAddr0 = smem_u32(sA);
    const uint32_t bAddr0 = smem_u32(sB);

    float acc[4][4][4];
    #pragma unroll
    for (int i = 0; i < 4; i++)
        #pragma unroll
        for (int j = 0; j < 4; j++)
            #pragma unroll
            for (int r = 0; r < 4; r++) acc[i][j][r] = 0.f;

    const int kTiles = K >> 5;

    auto load_tile = [&](int slot, int kt) {
        const int k0 = kt << 5;
        __nv_bfloat16* sa = sA + slot * SLOT;
        __nv_bfloat16* sb = sB + slot * SLOT;
        #pragma unroll
        for (int j = 0; j < 2; j++) {
            int i = tid + 256 * j;
            int r = i >> 2, c = i & 3;
            int dc = c ^ ((r >> 1) & 3);
            cp16(smem_u32(&sa[r * ROWE + dc * 8]),
                 Ap + (size_t)(m0 + r) * lda + k0 + c * 8, 16);
        }
        #pragma unroll
        for (int j = 0; j < 2; j++) {
            int i = tid + 256 * j;
            int r = i >> 2, c = i & 3;
            int dc = c ^ ((r >> 1) & 3);
            int gn = n0 + r;
            cp16(smem_u32(&sb[r * ROWE + dc * 8]),
                 Bp + (size_t)gn * ldb + k0 + c * 8, gn < N ? 16 : 0);
        }
        cp_commit();
    };

    auto compute_tile = [&](int slot) {
        const uint32_t aBase = aAddr0 + (uint32_t)slot * SLOT * 2;
        const uint32_t bBase = bAddr0 + (uint32_t)slot * SLOT * 2;
        #pragma unroll
        for (int s = 0; s < 2; s++) {
            const int kc = s * 2;
            uint32_t af[4][4], bf[4][2];
            #pragma unroll
            for (int mt = 0; mt < 4; mt++) {
                int row = wm * 64 + mt * 16 + a_r;
                int ch = (kc + a_ch) ^ ((row >> 1) & 3);
                uint32_t addr = aBase + (uint32_t)((row * ROWE + ch * 8) * 2);
                ldsm4(af[mt][0], af[mt][1], af[mt][2], af[mt][3], addr);
            }
            #pragma unroll
            for (int j = 0; j < 2; j++) {
                int row = wn * 32 + j * 16 + b_r;
                int ch = (kc + b_ch) ^ ((row >> 1) & 3);
                uint32_t addr = bBase + (uint32_t)((row * ROWE + ch * 8) * 2);
                ldsm4(bf[2 * j][0], bf[2 * j][1], bf[2 * j + 1][0], bf[2 * j + 1][1], addr);
            }
            #pragma unroll
            for (int mt = 0; mt < 4; mt++)
                #pragma unroll
                for (int nt = 0; nt < 4; nt++)
                    mma16(acc[mt][nt], af[mt], bf[nt]);
        }
    };

    load_tile(0, 0);
    load_tile(1, 1);
    for (int kt = 0; kt < kTiles; kt++) {
        if (kt + 1 < kTiles) cp_wait<1>(); else cp_wait<0>();
        __syncthreads();
        if (kt + 2 < kTiles) load_tile((kt + 2) % 3, kt + 2);
        compute_tile(kt % 3);
    }

    #pragma unroll
    for (int mt = 0; mt < 4; mt++) {
        #pragma unroll
        for (int nt = 0; nt < 4; nt++) {
            int row0 = m0 + wm * 64 + mt * 16 + gid;
            int col0 = n0 + wn * 32 + nt * 8 + tig * 2;
            if (flags & 512) {
                float ba = bias[col0], bg = bias[col0 + 1];
                #pragma unroll
                for (int h = 0; h < 2; h++) {
                    int rr = row0 + h * 8;
                    float a = alpha * acc[mt][nt][2 * h] + ba;
                    float g = alpha * acc[mt][nt][2 * h + 1] + bg;
                    float gg = a * 0.5f * g * (1.f + erff(g * 0.70710678118654752f));
                    Cbp[(size_t)rr * ldcb + (col0 >> 1)] = __float2bfloat16(gg);
                }
                continue;
            }
            #pragma unroll
            for (int r = 0; r < 4; r++) {
                int rr = row0 + (r >> 1) * 8;
                int cc = col0 + (r & 1);
                if (cc >= N) continue;
                float vv = alpha * acc[mt][nt][r];
                size_t off = (size_t)rr * ldc + cc;
                if (flags & 4)   vv += bias[cc];
                if (flags & 256) vv += aux[(((size_t)(z >> 4)) * 1024 + rr) * ldaux + cc];
                if (flags & 1) vv += Cp[off];
                if (flags & 2) vv = fmaxf(vv, Cp[off]);
                if (flags & 1024) C2[off] = vv;
                else if (!(flags & 32)) Cp[off] = vv;
                if (flags & 8)  Cbp[(size_t)rr * ldcb + cc] = __float2bfloat16(vv);
                if (flags & 16) Cbp[(size_t)cc * ldcb + rr] = __float2bfloat16(vv);
            }
        }
    }
}

static void gemm(const __nv_bfloat16* A, const __nv_bfloat16* B, const float* bias,
                 const float* aux, float* C, __nv_bfloat16* Cb,
                 int M, int N, int K, int lda, int ldb, int ldc, int ldcb, int ldaux,
                 long sA, long sB, long sC, long sCb, int aMod, int bDiv, int batch,
                 float alpha, int flags, cudaStream_t st = 0, float* C2 = nullptr)
{
    dim3 gr((N + 127) / 128, M / 128, batch);
    bgemm_k<<<gr, 256, 0, st>>>(A, B, bias, aux, C, Cb, C2, M, N, K,
                                lda, ldb, ldc, ldcb, ldaux,
                                sA, sB, sC, sCb, aMod, bDiv, alpha, flags);
}

// ---------------- merged prologue 1 ----------------
constexpr long P1_S0 = kHS;
constexpr long P1_S1 = P1_S0 + kHS;
constexpr long P1_S2 = P1_S1 + (long)kB * 512 * kCD;
__global__ void pcperm_k(const float* __restrict__ hidden, const float* __restrict__ pose,
                         const float* __restrict__ ctx,
                         float* __restrict__ hs, __nv_bfloat16* __restrict__ poset,
                         __nv_bfloat16* __restrict__ ctxperm)
{
    long idx = (long)blockIdx.x * blockDim.x + threadIdx.x;
    if (idx < P1_S0) {
        hs[idx] = hidden[idx];
    } else if (idx < P1_S1) {
        long i = idx - P1_S0;
        int d = (int)(i % kQ);
        long r = i / kQ;
        int n = (int)(r % kN); r /= kN;
        int t = (int)(r % kT); int b = (int)(r / kT);
        int h = n >> 5, w = n & 31;
        poset[i] = __float2bfloat16(pose[(((((size_t)b * kQ + d) * kT + t) * 32 + h) * 32) + w]);
    } else if (idx < P1_S2) {
        long i = idx - P1_S1;
        int k = (int)(i % kCD);
        long r0 = i / kCD;
        int r = (int)(r0 % 512); int b = (int)(r0 / 512);
        int n = ((r & 255) << 1) | (r >> 8);
        ctxperm[i] = __float2bfloat16(ctx[(((size_t)b * kC + (n >> 8)) * kCtok + (n & 255)) * kCD + k]);
    }
}

// ---------------- merged prologue 2 ----------------
constexpr long Q_S0 = (long)kB * kC * kCtok * kCD;
constexpr long Q_S1 = Q_S0 + (long)2 * kCD * kI;
constexpr long Q_S2 = Q_S1 + (long)2 * kQ * kI;
constexpr long Q_S3 = Q_S2 + (long)2 * kCD * kI;
constexpr long Q_S4 = Q_S3 + (long)2 * 384 * kI;
constexpr long Q_S5 = Q_S4 + (long)2 * kI * kQ;
constexpr long Q_S6 = Q_S5 + (long)2 * kFF * kQ;
constexpr long Q_S7 = Q_S6 + 2 * kFF;
constexpr long Q_S8 = Q_S7 + (long)kFF * kQ;
__global__ void prep_k(const float* __restrict__ ctx, const float* __restrict__ Wk,
                       const float* __restrict__ Wa, const float* __restrict__ Wv,
                       const float* __restrict__ Wq, const float* __restrict__ Wo,
                       const float* __restrict__ ffw1, const float* __restrict__ ffb1,
                       const float* __restrict__ ffw2,
                       __nv_bfloat16* __restrict__ ctxB, __nv_bfloat16* __restrict__ WkT,
                       __nv_bfloat16* __restrict__ WaN, __nv_bfloat16* __restrict__ WvT,
                       __nv_bfloat16* __restrict__ WqP, __nv_bfloat16* __restrict__ WoT,
                       __nv_bfloat16* __restrict__ fw1T, float* __restrict__ ffb1i,
                       __nv_bfloat16* __restrict__ fw2T)
{
    long idx = (long)blockIdx.x * blockDim.x + threadIdx.x;
    if (idx < Q_S0) {
        ctxB[idx] = __float2bfloat16(ctx[idx]);
    } else if (idx < Q_S1) {
        long i = idx - Q_S0;
        int r = (int)(i % kCD);
        long q = i / kCD;
        int c = (int)(q % kI);
        int b = (int)(q / kI);
        WkT[i] = __float2bfloat16(Wk[((size_t)b * kCD + r) * kI + c]);
    } else if (idx < Q_S2) {
        long i = idx - Q_S1;
        WaN[i] = __float2bfloat16(Wa[i]);
    } else if (idx < Q_S3) {
        long i = idx - Q_S2;
        int r = (int)(i % kCD);
        long q = i / kCD;
        int c = (int)(q % kI);
        int b = (int)(q / kI);
        WvT[i] = __float2bfloat16(Wv[((size_t)b * kCD + r) * kI + c]);
    } else if (idx < Q_S4) {
        long i = idx - Q_S3;
        int c = (int)(i % kI);
        long q = i / kI;
        int r = (int)(q % 384);
        int blk = (int)(q / 384);
        WqP[i] = (r < kQ) ? __float2bfloat16(Wq[((size_t)blk * kQ + r) * kI + c])
                          : __float2bfloat16(0.f);
    } else if (idx < Q_S5) {
        long i = idx - Q_S4;
        int r = (int)(i % kI);
        long q = i / kI;
        int c = (int)(q % kQ);
        int b = (int)(q / kQ);
        WoT[i] = __float2bfloat16(Wo[((size_t)b * kI + r) * kQ + c]);
    } else if (idx < Q_S6) {
        long i = idx - Q_S5;
        int k = (int)(i % kQ);
        int e = (int)(i / kQ);
        int oc = (e & 1) ? (kFF + (e >> 1)) : (e >> 1);
        fw1T[i] = __float2bfloat16(ffw1[(size_t)k * (2 * kFF) + oc]);
    } else if (idx < Q_S7) {
        int e = (int)(idx - Q_S6);
        int oc = (e & 1) ? (kFF + (e >> 1)) : (e >> 1);
        ffb1i[e] = ffb1[oc];
    } else if (idx < Q_S8) {
        long i = idx - Q_S7;
        int r = (int)(i % kFF);
        int c = (int)(i / kFF);
        fw2T[i] = __float2bfloat16(ffw2[(size_t)r * kQ + c]);
    }
}

// ---------------- LayerNorm: warp-per-row, float4 I/O ----------------
__global__ void ln_k(const float* __restrict__ x, const float* __restrict__ w,
                     const float* __restrict__ b, __nv_bfloat16* __restrict__ y)
{
    int row = blockIdx.x * 8 + (threadIdx.x >> 5);
    int lane = threadIdx.x & 31;
    const float4* xp = (const float4*)(x + (size_t)row * kQ);
    float4 v[3];
    float s1 = 0.f, s2 = 0.f;
    #pragma unroll
    for (int i = 0; i < 3; i++) {
        int idx = lane + 32 * i;
        if (idx < 80) {
            v[i] = xp[idx];
            s1 += v[i].x + v[i].y + v[i].z + v[i].w;
            s2 += v[i].x * v[i].x + v[i].y * v[i].y + v[i].z * v[i].z + v[i].w * v[i].w;
        }
    }
    #pragma unroll
    for (int o = 16; o; o >>= 1) {
        s1 += __shfl_xor_sync(0xffffffffu, s1, o);
        s2 += __shfl_xor_sync(0xffffffffu, s2, o);
    }
    float mean = s1 / kQ;
    float rstd = rsqrtf(s2 / kQ - mean * mean + 1e-5f);
    __nv_bfloat162* yp = (__nv_bfloat162*)(y + (size_t)row * kQ);
    const float4* wp = (const float4*)w;
    const float4* bp = (const float4*)b;
    #pragma unroll
    for (int i = 0; i < 3; i++) {
        int idx = lane + 32 * i;
        if (idx < 80) {
            float4 wv = wp[idx], bv = bp[idx];
            float o0 = (v[i].x - mean) * rstd * wv.x + bv.x;
            float o1 = (v[i].y - mean) * rstd * wv.y + bv.y;
            float o2 = (v[i].z - mean) * rstd * wv.z + bv.z;
            float o3 = (v[i].w - mean) * rstd * wv.w + bv.w;
            yp[idx * 2]     = __floats2bfloat162_rn(o0, o1);
            yp[idx * 2 + 1] = __floats2bfloat162_rn(o2, o3);
        }
    }
}

// ---------------- softmax kv groups, both blocks ----------------
__global__ void softmax_kv_k(const float* __restrict__ s, const float* __restrict__ abias,
                             __nv_bfloat16* __restrict__ ob)
{
    int gr = blockIdx.x;
    int c2 = blockIdx.y;
    int blk = gr >> 15;
    int m = gr & 1023;
    const float* p = s + (size_t)gr * 512 + c2 * 256;
    __nv_bfloat16* po = ob + (size_t)gr * 512 + c2 * 256;
    int tid = threadIdx.x;
    float v = p[tid] + abias[((size_t)blk * kN + m) * 256 + tid];
    __shared__ float red[256];
    red[tid] = v; __syncthreads();
    for (int st = 128; st; st >>= 1) { if (tid < st) red[tid] = fmaxf(red[tid], red[tid + st]); __syncthreads(); }
    float mx = red[0]; __syncthreads();
    float e = __expf(v - mx);
    red[tid] = e; __syncthreads();
    for (int st = 128; st; st >>= 1) { if (tid < st) red[tid] += red[tid + st]; __syncthreads(); }
    po[tid] = __float2bfloat16(e / red[0]);
}

// ---------------- softmax query rows ----------------
__global__ void softmax_aq_k(const float* __restrict__ s, const float* __restrict__ qbias,
                             __nv_bfloat16* __restrict__ ob)
{
    int gr = blockIdx.x;
    int n = gr & 1023;
    const float* p = s + (size_t)gr * 1024;
    __nv_bfloat16* po = ob + (size_t)gr * 1024;
    const float* bp = qbias + (size_t)n * 1024;
    int tid = threadIdx.x;
    float v[4];
    float mx = -1e30f;
    #pragma unroll
    for (int k = 0; k < 4; k++) { v[k] = p[tid + k * 256] + bp[tid + k * 256]; mx = fmaxf(mx, v[k]); }
    __shared__ float red[256];
    red[tid] = mx; __syncthreads();
    for (int st = 128; st; st >>= 1) { if (tid < st) red[tid] = fmaxf(red[tid], red[tid + st]); __syncthreads(); }
    mx = red[0]; __syncthreads();
    float sum = 0.f;
    #pragma unroll
    for (int k = 0; k < 4; k++) { v[k] = __expf(v[k] - mx); sum += v[k]; }
    red[tid] = sum; __syncthreads();
    for (int st = 128; st; st >>= 1) { if (tid < st) red[tid] += red[tid + st]; __syncthreads(); }
    float inv = 1.f / red[0];
    #pragma unroll
    for (int k = 0; k < 4; k++) po[tid + k * 256] = __float2bfloat16(v[k] * inv);
}

// ---------------- dwconv (both blocks) ----------------
__global__ void dwconv_k(const float* __restrict__ v, const float* __restrict__ wgt,
                         const float* __restrict__ bias, float* __restrict__ out)
{
    int pix = blockIdx.x & 255;
    int b = (blockIdx.x >> 8) & 1;
    int blk = blockIdx.x >> 9;
    int e = threadIdx.x;
    int h = pix >> 4, w = pix & 15;
    const float* wp = wgt + (size_t)blk * kI * 9;
    float wv[9];
    #pragma unroll
    for (int t9 = 0; t9 < 9; t9++) wv[t9] = wp[e * 9 + t9];
    float best = -1e30f;
    #pragma unroll
    for (int c = 0; c < 2; c++) {
        float s = 0.f;
        #pragma unroll
        for (int dh = -1; dh <= 1; dh++)
            #pragma unroll
            for (int dw = -1; dw <= 1; dw++) {
                int hh = h + dh, ww = w + dw;
                if (hh < 0 || hh > 15 || ww < 0 || ww > 15) continue;
                s += v[(((size_t)(blk * kB + b) * kC + c) * kCtok + hh * 16 + ww) * kI + e]
                     * wv[(dh + 1) * 3 + (dw + 1)];
            }
        best = fmaxf(best, s);
    }
    out[((size_t)(blk * kB + b) * kCtok + pix) * kI + e] = best + bias[(size_t)blk * kI + e];
}

// ---------------- bilinear x2 upsample -> bf16 (both blocks) ----------------
__global__ void upsample_k(const float* __restrict__ vd, __nv_bfloat16* __restrict__ vtok)
{
    int opix = blockIdx.x & 1023;
    int bb = blockIdx.x >> 10;
    int e = threadIdx.x;
    int y = opix >> 5, x = opix & 31;
    int py = y >> 1, px = x >> 1;
    int y0, y1, x0, x1; float wy0, wy1, wx0, wx1;
    if (y & 1) { y0 = py; y1 = min(py + 1, 15); wy0 = 0.75f; wy1 = 0.25f; }
    else       { y0 = max(py - 1, 0); y1 = py;  wy0 = 0.25f; wy1 = 0.75f; }
    if (x & 1) { x0 = px; x1 = min(px + 1, 15); wx0 = 0.75f; wx1 = 0.25f; }
    else       { x0 = max(px - 1, 0); x1 = px;  wx0 = 0.25f; wx1 = 0.75f; }
    const float* base = vd + (size_t)bb * kCtok * kI;
    float r = wy0 * wx0 * base[(size_t)(y0 * 16 + x0) * kI + e]
            + wy0 * wx1 * base[(size_t)(y0 * 16 + x1) * kI + e]
            + wy1 * wx0 * base[(size_t)(y1 * 16 + x0) * kI + e]
            + wy1 * wx1 * base[(size_t)(y1 * 16 + x1) * kI + e];
    vtok[((size_t)bb * kN + opix) * kI + e] = __float2bfloat16(r);
}

// ---------------- launch ----------------
extern "C" void kernel_launch(void* const* d_in, const int* in_sizes, int n_in,
                              void* d_out, int out_size)
{
    const float* hidden     = (const float*)d_in[0];
    const float* context    = (const float*)d_in[1];
    const float* pose       = (const float*)d_in[2];
    const float* Wq         = (const float*)d_in[3];
    const float* Wk         = (const float*)d_in[4];
    const float* Wv         = (const float*)d_in[5];
    const float* Wa         = (const float*)d_in[6];
    const float* agent_bias = (const float*)d_in[7];
    const float* query_bias = (const float*)d_in[8];
    const float* dwc_w      = (const float*)d_in[9];
    const float* dwc_b      = (const float*)d_in[10];
    const float* Wo         = (const float*)d_in[11];
    const float* norm_w     = (const float*)d_in[12];
    const float* norm_b     = (const float*)d_in[13];
    const float* ffln_w     = (const float*)d_in[14];
    const float* ffln_b     = (const float*)d_in[15];
    const float* ff_w1      = (const float*)d_in[16];
    const float* ff_b1      = (const float*)d_in[17];
    const float* ff_w2      = (const float*)d_in[18];
    const float* ff_b2      = (const float*)d_in[19];

    float *hs, *vP, *scoresP, *akvP, *vdP, *vtokWoP, *aqP, *ffb1iP;
    cudaGetSymbolAddress((void**)&hs, g_hs);
    cudaGetSymbolAddress((void**)&vP, g_v);
    cudaGetSymbolAddress((void**)&scoresP, g_scores);
    cudaGetSymbolAddress((void**)&akvP, g_akv);
    cudaGetSymbolAddress((void**)&vdP, g_vdmax);
    cudaGetSymbolAddress((void**)&vtokWoP, g_vtokWo);
    cudaGetSymbolAddress((void**)&aqP, g_aq);
    cudaGetSymbolAddress((void**)&ffb1iP, g_ffb1i);

    __nv_bfloat16 *posetB, *ctxpermB, *ctxB, *WkT, *WvT, *WaN, *WqP, *WoT, *fw1T, *fw2T,
                  *kPB, *vTB, *SB, *GTB, *UB, *scoresB, *akvB, *akvWoT, *aqB, *vtokB, *nhB, *ggB;
    cudaGetSymbolAddress((void**)&posetB, b_poset);
    cudaGetSymbolAddress((void**)&ctxpermB, b_ctxperm);
    cudaGetSymbolAddress((void**)&ctxB, b_ctx);
    cudaGetSymbolAddress((void**)&WkT, b_WkT);
    cudaGetSymbolAddress((void**)&WvT, b_WvT);
    cudaGetSymbolAddress((void**)&WaN, b_Wanat);
    cudaGetSymbolAddress((void**)&WqP, b_Wqpad);
    cudaGetSymbolAddress((void**)&WoT, b_WoT);
    cudaGetSymbolAddress((void**)&fw1T, b_ffw1T);
    cudaGetSymbolAddress((void**)&fw2T, b_ffw2T);
    cudaGetSymbolAddress((void**)&kPB, b_kP);
    cudaGetSymbolAddress((void**)&vTB, b_vT);
    cudaGetSymbolAddress((void**)&SB, b_S);
    cudaGetSymbolAddress((void**)&GTB, b_GT);
    cudaGetSymbolAddress((void**)&UB, b_U);
    cudaGetSymbolAddress((void**)&scoresB, b_scores);
    cudaGetSymbolAddress((void**)&akvB, b_akv);
    cudaGetSymbolAddress((void**)&akvWoT, b_akvWoT);
    cudaGetSymbolAddress((void**)&aqB, b_aq);
    cudaGetSymbolAddress((void**)&vtokB, b_vtok);
    cudaGetSymbolAddress((void**)&nhB, b_nh);
    cudaGetSymbolAddress((void**)&ggB, b_gg);

    const float SCALE = 0.125f;
    auto cdiv = [](long a, long b) { return (int)((a + b - 1) / b); };

    // ===== shared prologue =====
    pcperm_k<<<cdiv(P1_S2, 256), 256>>>(hidden, pose, context, hs, posetB, ctxpermB);
    prep_k<<<cdiv(Q_S8, 256), 256>>>(context, Wk, Wa, Wv, Wq, Wo, ff_w1, ff_b1, ff_w2,
                                     ctxB, WkT, WaN, WvT, WqP, WoT, fw1T, ffb1iP, fw2T);

    // fork: stream 2 runs the hs-side blk0 chain
    cudaEventRecord(g_e0, 0);
    cudaStreamWaitEvent(g_s2, g_e0, 0);

    gemm(WqP, WaN, nullptr, nullptr, nullptr, GTB,
         384, kQ, kI, kI, kI, 0, 384, 0,
         (long)384 * kI, (long)kQ * kI, 0, (long)kQ * 384, 0, 1, 2, 1.f, 16 | 32, g_s2);
    ln_k<<<(int)(kTOK / 8), 256, 0, g_s2>>>(hs, norm_w, norm_b, nhB);
    gemm(nhB, GTB, nullptr, nullptr, nullptr, UB,
         (int)kTOK, kQ, kQ, kQ, 384, 0, kQ, 0,
         0, 0, 0, 0, 0, 1, 1, 1.f, 8 | 32, g_s2);
    gemm(UB, posetB, nullptr, nullptr, aqP, nullptr,
         kN, kN, kQ, kQ, kQ, kN, 0, 0,
         (long)kN * kQ, (long)kN * kQ, (long)kN * kN, 0, 0, 1, kB * kT, SCALE, 0, g_s2);
    softmax_aq_k<<<(int)kTOK, 256, 0, g_s2>>>(aqP, query_bias, aqB);
    cudaEventRecord(g_e1, g_s2);

    // ===== main stream: kv side, both blocks batched =====
    gemm(ctxpermB, WkT, nullptr, nullptr, nullptr, kPB,
         512, kI, kCD, kCD, kCD, 0, kI, 0,
         512L * kCD, (long)kI * kCD, 0, 512L * kI, 2, 2, 4, 1.f, 8 | 32);
    gemm(kPB, WaN, nullptr, nullptr, nullptr, SB,
         512, kQ, kI, kI, kI, 0, kQ, 0,
         512L * kI, (long)kQ * kI, 0, 512L * kQ, 0, 2, 4, 1.f, 8 | 32);
    gemm(posetB, SB, nullptr, nullptr, scoresP, nullptr,
         kN, 512, kQ, kQ, kQ, 512, 0, 0,
         (long)kN * kQ, 512L * kQ, (long)kN * 512, 0, 32, 16, 64, SCALE, 0);
    softmax_kv_k<<<dim3(2 * (int)kTOK, 2), 256>>>(scoresP, agent_bias, scoresB);
    gemm(ctxB, WvT, nullptr, nullptr, vP, vTB,
         kCtok, kI, kCD, kCD, kCD, kI, kCtok, 0,
         (long)kCtok * kCD, (long)kI * kCD, (long)kCtok * kI, (long)kI * kCtok, 4, 4, 8, 1.f, 16);
    gemm(scoresB, vTB, nullptr, nullptr, akvP, nullptr,
         kN, kI, kCtok, 512, kCtok, kI, 0, 0,
         (long)kN * 512, (long)kC * kI * kCtok, (long)kN * kI, 0, 0, 16, 64, 1.f, 0);
    gemm(scoresB + 256, vTB + (size_t)kI * kCtok, nullptr, nullptr, akvP, akvB,
         kN, kI, kCtok, 512, kCtok, kI, kI, 0,
         (long)kN * 512, (long)kC * kI * kCtok, (long)kN * kI, (long)kN * kI, 0, 16, 64,
         1.f, 2 | 8 | 32);
    gemm(akvB, WoT, nullptr, nullptr, akvP, akvWoT,
         kN, kQ, kI, kI, kI, kQ, kN, 0,
         (long)kN * kI, (long)kQ * kI, 0, (long)kQ * kN, 0, 32, 64, 1.f, 16 | 32);
    dwconv_k<<<2 * kB * kCtok, kI>>>(vP, dwc_w, dwc_b, vdP);
    upsample_k<<<2 * kB * kN, kI>>>(vdP, vtokB);
    gemm(vtokB, WoT, nullptr, nullptr, vtokWoP, nullptr,
         kN, kQ, kI, kI, kI, kQ, 0, 0,
         (long)kN * kI, (long)kQ * kI, (long)kN * kQ, 0, 0, 2, 4, 1.f, 0);

    // join
    cudaStreamWaitEvent(0, g_e1, 0);

    // ===== Phase B blk0 final, then full blk1 chain =====
    gemm(aqB, akvWoT, nullptr, vtokWoP, hs, nullptr,
         kN, kQ, kN, kN, kN, kQ, 0, kQ,
         (long)kN * kN, (long)kQ * kN, (long)kN * kQ, 0, 0, 1, kB * kT,
         1.f, 1 | 256);

    {
        const __nv_bfloat16* GT_b = GTB + (size_t)kQ * 384;
        const float* qb_b = query_bias + (size_t)kN * kN;
        ln_k<<<(int)(kTOK / 8), 256>>>(hs, norm_w, norm_b, nhB);
        gemm(nhB, GT_b, nullptr, nullptr, nullptr, UB,
             (int)kTOK, kQ, kQ, kQ, 384, 0, kQ, 0,
             0, 0, 0, 0, 0, 1, 1, 1.f, 8 | 32);
        gemm(UB, posetB, nullptr, nullptr, aqP, nullptr,
             kN, kN, kQ, kQ, kQ, kN, 0, 0,
             (long)kN * kQ, (long)kN * kQ, (long)kN * kN, 0, 0, 1, kB * kT, SCALE, 0);
        softmax_aq_k<<<(int)kTOK, 256>>>(aqP, qb_b, aqB);
        gemm(aqB, akvWoT + (size_t)kB * kT * kQ * kN, nullptr,
             vtokWoP + (size_t)kB * kN * kQ, hs, nullptr,
             kN, kQ, kN, kN, kN, kQ, 0, kQ,
             (long)kN * kN, (long)kQ * kN, (long)kN * kQ, 0, 0, 1, kB * kT,
             1.f, 1 | 256);
    }

    // ---- FF: LN -> fused FF1+GEGLU -> FF2 writes d_out directly ----
    ln_k<<<(int)(kTOK / 8), 256>>>(hs, ffln_w, ffln_b, nhB);
    gemm(nhB, fw1T, ffb1iP, nullptr, nullptr, ggB,
         (int)kTOK, 2 * kFF, kQ, kQ, kQ, 0, kFF, 0,
         0, 0, 0, 0, 0, 1, 1, 1.f, 4 | 32 | 512);
    gemm(ggB, fw2T, ff_b2, nullptr, hs, nullptr,
         (int)kTOK, kQ, kFF, kFF, kFF, kQ, 0, 0,
         0, 0, 0, 0, 0, 1, 1, 1.f, 1 | 4 | 1024, 0, (float*)d_out);
}

// round 17
// speedup vs baseline: 1.5141x; 1.1546x over previous
#include <cuda_runtime.h>
#include <cuda_bf16.h>
#include <math.h>
#include <stdint.h>

// ---------------- problem constants ----------------
constexpr int kB = 2;
constexpr int kT = 16;
constexpr int kN = 1024;
constexpr int kC = 2;
constexpr int kCtok = 256;
constexpr int kQ = 320;
constexpr int kI = 512;
constexpr int kCD = 1024;
constexpr int kFF = 1280;
constexpr long kHS = (long)kB * kT * kN * kQ;
constexpr long kTOK = (long)kB * kT * kN;        // 32768

// ---------------- streams/events (created once at program init) ----------------
static cudaStream_t g_s2 = [] { cudaStream_t s; cudaStreamCreate(&s); return s; }();
static cudaEvent_t g_e0 = [] { cudaEvent_t e; cudaEventCreateWithFlags(&e, cudaEventDisableTiming); return e; }();
static cudaEvent_t g_e1 = [] { cudaEvent_t e; cudaEventCreateWithFlags(&e, cudaEventDisableTiming); return e; }();

// ---------------- fp32 scratch ----------------
static __device__ float g_hs[kHS];
static __device__ float g_v[(long)2 * kB * kC * kCtok * kI];
static __device__ float g_scores[(long)2 * kTOK * kI];
static __device__ float g_akv[(long)2 * kTOK * kI];
static __device__ float g_vdmax[(long)2 * kB * kCtok * kI];
static __device__ float g_vtokWo[(long)2 * kB * kN * kQ];
static __device__ float g_aq[kTOK * kN];
static __device__ float g_ffb1i[2 * kFF];

// ---------------- bf16 scratch ----------------
static __device__ __nv_bfloat16 b_poset[kHS];
static __device__ __nv_bfloat16 b_ctxperm[(long)kB * 512 * kCD];
static __device__ __nv_bfloat16 b_ctx[(long)kB * kC * kCtok * kCD];
static __device__ __nv_bfloat16 b_WkT[(long)2 * kI * kCD];
static __device__ __nv_bfloat16 b_WvT[(long)2 * kI * kCD];
static __device__ __nv_bfloat16 b_Wanat[(long)2 * kQ * kI];
static __device__ __nv_bfloat16 b_Wqpad[(long)2 * 384 * kI];
static __device__ __nv_bfloat16 b_WoT[(long)2 * kQ * kI];
static __device__ __nv_bfloat16 b_ffw1T[(long)2 * kFF * kQ];
static __device__ __nv_bfloat16 b_ffw2T[(long)kQ * kFF];
static __device__ __nv_bfloat16 b_kP[(long)2 * kB * 512 * kI];
static __device__ __nv_bfloat16 b_vT[(long)2 * kB * kC * kI * kCtok];
static __device__ __nv_bfloat16 b_S[(long)2 * kB * 512 * kQ];
static __device__ __nv_bfloat16 b_GT[(long)2 * kQ * 384];
static __device__ __nv_bfloat16 b_U[kTOK * kQ];
static __device__ __nv_bfloat16 b_scores[(long)2 * kTOK * kI];
static __device__ __nv_bfloat16 b_akv[(long)2 * kTOK * kI];
static __device__ __nv_bfloat16 b_akvWoT[(long)2 * kB * kT * kQ * kN];
static __device__ __nv_bfloat16 b_aq[kTOK * kN];
static __device__ __nv_bfloat16 b_vtok[(long)2 * kB * kN * kI];
static __device__ __nv_bfloat16 b_nh[kHS];
static __device__ __nv_bfloat16 b_gg[kTOK * kFF];

// ---------------- PTX helpers ----------------
__device__ __forceinline__ uint32_t smem_u32(const void* p) {
    return (uint32_t)__cvta_generic_to_shared(p);
}
__device__ __forceinline__ void cp16(uint32_t dst, const void* src, int src_bytes) {
    asm volatile("cp.async.cg.shared.global [%0], [%1], 16, %2;\n"
                 :: "r"(dst), "l"(src), "r"(src_bytes));
}
__device__ __forceinline__ void cp_commit() { asm volatile("cp.async.commit_group;\n"); }
template<int W> __device__ __forceinline__ void cp_wait() {
    asm volatile("cp.async.wait_group %0;\n" :: "n"(W));
}
__device__ __forceinline__ void ldsm4(uint32_t& r0, uint32_t& r1, uint32_t& r2, uint32_t& r3,
                                      uint32_t addr) {
    asm volatile("ldmatrix.sync.aligned.m8n8.x4.shared.b16 {%0,%1,%2,%3}, [%4];"
                 : "=r"(r0), "=r"(r1), "=r"(r2), "=r"(r3) : "r"(addr));
}
__device__ __forceinline__ void mma16(float* d, const uint32_t* a, const uint32_t* b) {
    asm volatile(
        "mma.sync.aligned.m16n8k16.row.col.f32.bf16.bf16.f32 "
        "{%0,%1,%2,%3},{%4,%5,%6,%7},{%8,%9},{%0,%1,%2,%3};"
        : "+f"(d[0]), "+f"(d[1]), "+f"(d[2]), "+f"(d[3])
        : "r"(a[0]), "r"(a[1]), "r"(a[2]), "r"(a[3]), "r"(b[0]), "r"(b[1]));
}

// ---------------- bf16 NT tensor-core GEMM (XOR swizzle + ldmatrix, 3-slot ring, 1 sync) ----------------
// C(MxN) = alpha * A(MxK,bf16,row) * B(NxK,bf16,row)^T + epilogues.
// Batch: A index = aMod ? (z % aMod) : z ;  B index = z / bDiv ; C/Cb index = z.
// flags: 1 += C ; 2 max C ; 4 += bias[col] ; 8 bf16 natural Cb ; 16 bf16 transposed Cb ;
//        32 suppress fp32 write ; 256 += aux[((z>>4)*1024+row)*ldaux+col] ;
//        512 GEGLU pair epilogue ; 1024 write fp32 result to C2 (not Cp)
constexpr int ROWE = 32;
constexpr int SLOT = 128 * ROWE;

__global__ __launch_bounds__(256, 2)
void bgemm_k(const __nv_bfloat16* __restrict__ A, const __nv_bfloat16* __restrict__ Bm,
             const float* __restrict__ bias, const float* __restrict__ aux,
             float* __restrict__ C, __nv_bfloat16* __restrict__ Cb,
             float* __restrict__ C2,
             int M, int N, int K, int lda, int ldb, int ldc, int ldcb, int ldaux,
             long strA, long strB, long strC, long strCb,
             int aMod, int bDiv, float alpha, int flags)
{
    __shared__ __align__(16) __nv_bfloat16 sA[3 * SLOT];
    __shared__ __align__(16) __nv_bfloat16 sB[3 * SLOT];

    const int z = blockIdx.z;
    const int za = aMod ? (z % aMod) : z;
    const __nv_bfloat16* Ap = A + (size_t)za * strA;
    const __nv_bfloat16* Bp = Bm + (size_t)(z / bDiv) * strB;
    float* Cp = C + (size_t)z * strC;
    __nv_bfloat16* Cbp = Cb + (size_t)z * strCb;
    const int m0 = blockIdx.y * 128, n0 = blockIdx.x * 128;
    const int tid = threadIdx.x;
    const int lane = tid & 31, warp = tid >> 5;
    const int wm = warp & 1, wn = warp >> 1;
    const int gid = lane >> 2, tig = lane & 3;

    const int a_r = lane & 15;
    const int a_ch = lane >> 4;
    const int b_r = ((lane >> 4) & 1) * 8 + (lane & 7);
    const int b_ch = (lane >> 3) & 1;

    const uint32_t aAddr0 = smem_u32(sA);
    const uint32_t bAddr0 = smem_u32(sB);

    float acc[4][4][4];
    #pragma unroll
    for (int i = 0; i < 4; i++)
        #pragma unroll
        for (int j = 0; j < 4; j++)
            #pragma unroll
            for (int r = 0; r < 4; r++) acc[i][j][r] = 0.f;

    const int kTiles = K >> 5;

    auto load_tile = [&](int slot, int kt) {
        const int k0 = kt << 5;
        __nv_bfloat16* sa = sA + slot * SLOT;
        __nv_bfloat16* sb = sB + slot * SLOT;
        #pragma unroll
        for (int j = 0; j < 2; j++) {
            int i = tid + 256 * j;
            int r = i >> 2, c = i & 3;
            int dc = c ^ ((r >> 1) & 3);
            cp16(smem_u32(&sa[r * ROWE + dc * 8]),
                 Ap + (size_t)(m0 + r) * lda + k0 + c * 8, 16);
        }
        #pragma unroll
        for (int j = 0; j < 2; j++) {
            int i = tid + 256 * j;
            int r = i >> 2, c = i & 3;
            int dc = c ^ ((r >> 1) & 3);
            int gn = n0 + r;
            cp16(smem_u32(&sb[r * ROWE + dc * 8]),
                 Bp + (size_t)gn * ldb + k0 + c * 8, gn < N ? 16 : 0);
        }
        cp_commit();
    };

    auto compute_tile = [&](int slot) {
        const uint32_t aBase = aAddr0 + (uint32_t)slot * SLOT * 2;
        const uint32_t bBase = bAddr0 + (uint32_t)slot * SLOT * 2;
        #pragma unroll
        for (int s = 0; s < 2; s++) {
            const int kc = s * 2;
            uint32_t af[4][4], bf[4][2];
            #pragma unroll
            for (int mt = 0; mt < 4; mt++) {
                int row = wm * 64 + mt * 16 + a_r;
                int ch = (kc + a_ch) ^ ((row >> 1) & 3);
                uint32_t addr = aBase + (uint32_t)((row * ROWE + ch * 8) * 2);
                ldsm4(af[mt][0], af[mt][1], af[mt][2], af[mt][3], addr);
            }
            #pragma unroll
            for (int j = 0; j < 2; j++) {
                int row = wn * 32 + j * 16 + b_r;
                int ch = (kc + b_ch) ^ ((row >> 1) & 3);
                uint32_t addr = bBase + (uint32_t)((row * ROWE + ch * 8) * 2);
                ldsm4(bf[2 * j][0], bf[2 * j][1], bf[2 * j + 1][0], bf[2 * j + 1][1], addr);
            }
            #pragma unroll
            for (int mt = 0; mt < 4; mt++)
                #pragma unroll
                for (int nt = 0; nt < 4; nt++)
                    mma16(acc[mt][nt], af[mt], bf[nt]);
        }
    };

    load_tile(0, 0);
    load_tile(1, 1);
    for (int kt = 0; kt < kTiles; kt++) {
        if (kt + 1 < kTiles) cp_wait<1>(); else cp_wait<0>();
        __syncthreads();
        if (kt + 2 < kTiles) load_tile((kt + 2) % 3, kt + 2);
        compute_tile(kt % 3);
    }

    #pragma unroll
    for (int mt = 0; mt < 4; mt++) {
        #pragma unroll
        for (int nt = 0; nt < 4; nt++) {
            int row0 = m0 + wm * 64 + mt * 16 + gid;
            int col0 = n0 + wn * 32 + nt * 8 + tig * 2;
            if (flags & 512) {
                float ba = bias[col0], bg = bias[col0 + 1];
                #pragma unroll
                for (int h = 0; h < 2; h++) {
                    int rr = row0 + h * 8;
                    float a = alpha * acc[mt][nt][2 * h] + ba;
                    float g = alpha * acc[mt][nt][2 * h + 1] + bg;
                    float gg = a * 0.5f * g * (1.f + erff(g * 0.70710678118654752f));
                    Cbp[(size_t)rr * ldcb + (col0 >> 1)] = __float2bfloat16(gg);
                }
                continue;
            }
            #pragma unroll
            for (int r = 0; r < 4; r++) {
                int rr = row0 + (r >> 1) * 8;
                int cc = col0 + (r & 1);
                if (cc >= N) continue;
                float vv = alpha * acc[mt][nt][r];
                size_t off = (size_t)rr * ldc + cc;
                if (flags & 4)   vv += bias[cc];
                if (flags & 256) vv += aux[(((size_t)(z >> 4)) * 1024 + rr) * ldaux + cc];
                if (flags & 1) vv += Cp[off];
                if (flags & 2) vv = fmaxf(vv, Cp[off]);
                if (flags & 1024) C2[off] = vv;
                else if (!(flags & 32)) Cp[off] = vv;
                if (flags & 8)  Cbp[(size_t)rr * ldcb + cc] = __float2bfloat16(vv);
                if (flags & 16) Cbp[(size_t)cc * ldcb + rr] = __float2bfloat16(vv);
            }
        }
    }
}

static void gemm(const __nv_bfloat16* A, const __nv_bfloat16* B, const float* bias,
                 const float* aux, float* C, __nv_bfloat16* Cb,
                 int M, int N, int K, int lda, int ldb, int ldc, int ldcb, int ldaux,
                 long sA, long sB, long sC, long sCb, int aMod, int bDiv, int batch,
                 float alpha, int flags, cudaStream_t st = 0, float* C2 = nullptr)
{
    dim3 gr((N + 127) / 128, M / 128, batch);
    bgemm_k<<<gr, 256, 0, st>>>(A, B, bias, aux, C, Cb, C2, M, N, K,
                                lda, ldb, ldc, ldcb, ldaux,
                                sA, sB, sC, sCb, aMod, bDiv, alpha, flags);
}

// ---------------- merged prologue 1 ----------------
constexpr long P1_S0 = kHS;
constexpr long P1_S1 = P1_S0 + kHS;
constexpr long P1_S2 = P1_S1 + (long)kB * 512 * kCD;
__global__ void pcperm_k(const float* __restrict__ hidden, const float* __restrict__ pose,
                         const float* __restrict__ ctx,
                         float* __restrict__ hs, __nv_bfloat16* __restrict__ poset,
                         __nv_bfloat16* __restrict__ ctxperm)
{
    long idx = (long)blockIdx.x * blockDim.x + threadIdx.x;
    if (idx < P1_S0) {
        hs[idx] = hidden[idx];
    } else if (idx < P1_S1) {
        long i = idx - P1_S0;
        int d = (int)(i % kQ);
        long r = i / kQ;
        int n = (int)(r % kN); r /= kN;
        int t = (int)(r % kT); int b = (int)(r / kT);
        int h = n >> 5, w = n & 31;
        poset[i] = __float2bfloat16(pose[(((((size_t)b * kQ + d) * kT + t) * 32 + h) * 32) + w]);
    } else if (idx < P1_S2) {
        long i = idx - P1_S1;
        int k = (int)(i % kCD);
        long r0 = i / kCD;
        int r = (int)(r0 % 512); int b = (int)(r0 / 512);
        int n = ((r & 255) << 1) | (r >> 8);
        ctxperm[i] = __float2bfloat16(ctx[(((size_t)b * kC + (n >> 8)) * kCtok + (n & 255)) * kCD + k]);
    }
}

// ---------------- merged prologue 2 ----------------
constexpr long Q_S0 = (long)kB * kC * kCtok * kCD;
constexpr long Q_S1 = Q_S0 + (long)2 * kCD * kI;
constexpr long Q_S2 = Q_S1 + (long)2 * kQ * kI;
constexpr long Q_S3 = Q_S2 + (long)2 * kCD * kI;
constexpr long Q_S4 = Q_S3 + (long)2 * 384 * kI;
constexpr long Q_S5 = Q_S4 + (long)2 * kI * kQ;
constexpr long Q_S6 = Q_S5 + (long)2 * kFF * kQ;
constexpr long Q_S7 = Q_S6 + 2 * kFF;
constexpr long Q_S8 = Q_S7 + (long)kFF * kQ;
__global__ void prep_k(const float* __restrict__ ctx, const float* __restrict__ Wk,
                       const float* __restrict__ Wa, const float* __restrict__ Wv,
                       const float* __restrict__ Wq, const float* __restrict__ Wo,
                       const float* __restrict__ ffw1, const float* __restrict__ ffb1,
                       const float* __restrict__ ffw2,
                       __nv_bfloat16* __restrict__ ctxB, __nv_bfloat16* __restrict__ WkT,
                       __nv_bfloat16* __restrict__ WaN, __nv_bfloat16* __restrict__ WvT,
                       __nv_bfloat16* __restrict__ WqP, __nv_bfloat16* __restrict__ WoT,
                       __nv_bfloat16* __restrict__ fw1T, float* __restrict__ ffb1i,
                       __nv_bfloat16* __restrict__ fw2T)
{
    long idx = (long)blockIdx.x * blockDim.x + threadIdx.x;
    if (idx < Q_S0) {
        ctxB[idx] = __float2bfloat16(ctx[idx]);
    } else if (idx < Q_S1) {
        long i = idx - Q_S0;
        int r = (int)(i % kCD);
        long q = i / kCD;
        int c = (int)(q % kI);
        int b = (int)(q / kI);
        WkT[i] = __float2bfloat16(Wk[((size_t)b * kCD + r) * kI + c]);
    } else if (idx < Q_S2) {
        long i = idx - Q_S1;
        WaN[i] = __float2bfloat16(Wa[i]);
    } else if (idx < Q_S3) {
        long i = idx - Q_S2;
        int r = (int)(i % kCD);
        long q = i / kCD;
        int c = (int)(q % kI);
        int b = (int)(q / kI);
        WvT[i] = __float2bfloat16(Wv[((size_t)b * kCD + r) * kI + c]);
    } else if (idx < Q_S4) {
        long i = idx - Q_S3;
        int c = (int)(i % kI);
        long q = i / kI;
        int r = (int)(q % 384);
        int blk = (int)(q / 384);
        WqP[i] = (r < kQ) ? __float2bfloat16(Wq[((size_t)blk * kQ + r) * kI + c])
                          : __float2bfloat16(0.f);
    } else if (idx < Q_S5) {
        long i = idx - Q_S4;
        int r = (int)(i % kI);
        long q = i / kI;
        int c = (int)(q % kQ);
        int b = (int)(q / kQ);
        WoT[i] = __float2bfloat16(Wo[((size_t)b * kI + r) * kQ + c]);
    } else if (idx < Q_S6) {
        long i = idx - Q_S5;
        int k = (int)(i % kQ);
        int e = (int)(i / kQ);
        int oc = (e & 1) ? (kFF + (e >> 1)) : (e >> 1);
        fw1T[i] = __float2bfloat16(ffw1[(size_t)k * (2 * kFF) + oc]);
    } else if (idx < Q_S7) {
        int e = (int)(idx - Q_S6);
        int oc = (e & 1) ? (kFF + (e >> 1)) : (e >> 1);
        ffb1i[e] = ffb1[oc];
    } else if (idx < Q_S8) {
        long i = idx - Q_S7;
        int r = (int)(i % kFF);
        int c = (int)(i / kFF);
        fw2T[i] = __float2bfloat16(ffw2[(size_t)r * kQ + c]);
    }
}

// ---------------- LayerNorm: warp-per-row, float4 I/O ----------------
__global__ void ln_k(const float* __restrict__ x, const float* __restrict__ w,
                     const float* __restrict__ b, __nv_bfloat16* __restrict__ y)
{
    int row = blockIdx.x * 8 + (threadIdx.x >> 5);
    int lane = threadIdx.x & 31;
    const float4* xp = (const float4*)(x + (size_t)row * kQ);
    float4 v[3];
    float s1 = 0.f, s2 = 0.f;
    #pragma unroll
    for (int i = 0; i < 3; i++) {
        int idx = lane + 32 * i;
        if (idx < 80) {
            v[i] = xp[idx];
            s1 += v[i].x + v[i].y + v[i].z + v[i].w;
            s2 += v[i].x * v[i].x + v[i].y * v[i].y + v[i].z * v[i].z + v[i].w * v[i].w;
        }
    }
    #pragma unroll
    for (int o = 16; o; o >>= 1) {
        s1 += __shfl_xor_sync(0xffffffffu, s1, o);
        s2 += __shfl_xor_sync(0xffffffffu, s2, o);
    }
    float mean = s1 / kQ;
    float rstd = rsqrtf(s2 / kQ - mean * mean + 1e-5f);
    __nv_bfloat162* yp = (__nv_bfloat162*)(y + (size_t)row * kQ);
    const float4* wp = (const float4*)w;
    const float4* bp = (const float4*)b;
    #pragma unroll
    for (int i = 0; i < 3; i++) {
        int idx = lane + 32 * i;
        if (idx < 80) {
            float4 wv = wp[idx], bv = bp[idx];
            float o0 = (v[i].x - mean) * rstd * wv.x + bv.x;
            float o1 = (v[i].y - mean) * rstd * wv.y + bv.y;
            float o2 = (v[i].z - mean) * rstd * wv.z + bv.z;
            float o3 = (v[i].w - mean) * rstd * wv.w + bv.w;
            yp[idx * 2]     = __floats2bfloat162_rn(o0, o1);
            yp[idx * 2 + 1] = __floats2bfloat162_rn(o2, o3);
        }
    }
}

// ---------------- softmax kv groups: warp-per-group (256 cols), both blocks ----------------
__global__ void softmax_kv_k(const float* __restrict__ s, const float* __restrict__ abias,
                             __nv_bfloat16* __restrict__ ob)
{
    long g = (long)blockIdx.x * 8 + (threadIdx.x >> 5);   // group id in [0, 2*kTOK*2)
    int lane = threadIdx.x & 31;
    long gr = g >> 1;
    int c2 = (int)(g & 1);
    int blk = (int)(gr >> 15);
    int m = (int)(gr & 1023);
    const float4* p4 = (const float4*)(s + gr * 512 + c2 * 256);
    const float4* b4 = (const float4*)(abias + ((size_t)blk * kN + m) * 256);
    __nv_bfloat162* po = (__nv_bfloat162*)(ob + gr * 512 + c2 * 256);

    float4 v[2];
    float mx = -1e30f;
    #pragma unroll
    for (int j = 0; j < 2; j++) {
        int idx = lane + 32 * j;
        float4 sv = p4[idx];
        float4 bv = b4[c2 * 64 + idx];
        v[j].x = sv.x + bv.x; v[j].y = sv.y + bv.y;
        v[j].z = sv.z + bv.z; v[j].w = sv.w + bv.w;
        mx = fmaxf(mx, fmaxf(fmaxf(v[j].x, v[j].y), fmaxf(v[j].z, v[j].w)));
    }
    #pragma unroll
    for (int o = 16; o; o >>= 1) mx = fmaxf(mx, __shfl_xor_sync(0xffffffffu, mx, o));
    float sum = 0.f;
    #pragma unroll
    for (int j = 0; j < 2; j++) {
        v[j].x = __expf(v[j].x - mx); v[j].y = __expf(v[j].y - mx);
        v[j].z = __expf(v[j].z - mx); v[j].w = __expf(v[j].w - mx);
        sum += v[j].x + v[j].y + v[j].z + v[j].w;
    }
    #pragma unroll
    for (int o = 16; o; o >>= 1) sum += __shfl_xor_sync(0xffffffffu, sum, o);
    float inv = 1.f / sum;
    #pragma unroll
    for (int j = 0; j < 2; j++) {
        int idx = lane + 32 * j;
        po[idx * 2]     = __floats2bfloat162_rn(v[j].x * inv, v[j].y * inv);
        po[idx * 2 + 1] = __floats2bfloat162_rn(v[j].z * inv, v[j].w * inv);
    }
}

// ---------------- softmax query rows: warp-per-row (1024 cols) ----------------
__global__ void softmax_aq_k(const float* __restrict__ s, const float* __restrict__ qbias,
                             __nv_bfloat16* __restrict__ ob)
{
    long row = (long)blockIdx.x * 8 + (threadIdx.x >> 5);
    int lane = threadIdx.x & 31;
    int n = (int)(row & 1023);
    const float4* p4 = (const float4*)(s + row * 1024);
    const float4* b4 = (const float4*)(qbias + (size_t)n * 1024);
    __nv_bfloat162* po = (__nv_bfloat162*)(ob + row * 1024);

    float4 v[8];
    float mx = -1e30f;
    #pragma unroll
    for (int j = 0; j < 8; j++) {
        int idx = lane + 32 * j;
        float4 sv = p4[idx];
        float4 bv = b4[idx];
        v[j].x = sv.x + bv.x; v[j].y = sv.y + bv.y;
        v[j].z = sv.z + bv.z; v[j].w = sv.w + bv.w;
        mx = fmaxf(mx, fmaxf(fmaxf(v[j].x, v[j].y), fmaxf(v[j].z, v[j].w)));
    }
    #pragma unroll
    for (int o = 16; o; o >>= 1) mx = fmaxf(mx, __shfl_xor_sync(0xffffffffu, mx, o));
    float sum = 0.f;
    #pragma unroll
    for (int j = 0; j < 8; j++) {
        v[j].x = __expf(v[j].x - mx); v[j].y = __expf(v[j].y - mx);
        v[j].z = __expf(v[j].z - mx); v[j].w = __expf(v[j].w - mx);
        sum += v[j].x + v[j].y + v[j].z + v[j].w;
    }
    #pragma unroll
    for (int o = 16; o; o >>= 1) sum += __shfl_xor_sync(0xffffffffu, sum, o);
    float inv = 1.f / sum;
    #pragma unroll
    for (int j = 0; j < 8; j++) {
        int idx = lane + 32 * j;
        po[idx * 2]     = __floats2bfloat162_rn(v[j].x * inv, v[j].y * inv);
        po[idx * 2 + 1] = __floats2bfloat162_rn(v[j].z * inv, v[j].w * inv);
    }
}

// ---------------- dwconv (both blocks) ----------------
__global__ void dwconv_k(const float* __restrict__ v, const float* __restrict__ wgt,
                         const float* __restrict__ bias, float* __restrict__ out)
{
    int pix = blockIdx.x & 255;
    int b = (blockIdx.x >> 8) & 1;
    int blk = blockIdx.x >> 9;
    int e = threadIdx.x;
    int h = pix >> 4, w = pix & 15;
    const float* wp = wgt + (size_t)blk * kI * 9;
    float wv[9];
    #pragma unroll
    for (int t9 = 0; t9 < 9; t9++) wv[t9] = wp[e * 9 + t9];
    float best = -1e30f;
    #pragma unroll
    for (int c = 0; c < 2; c++) {
        float s = 0.f;
        #pragma unroll
        for (int dh = -1; dh <= 1; dh++)
            #pragma unroll
            for (int dw = -1; dw <= 1; dw++) {
                int hh = h + dh, ww = w + dw;
                if (hh < 0 || hh > 15 || ww < 0 || ww > 15) continue;
                s += v[(((size_t)(blk * kB + b) * kC + c) * kCtok + hh * 16 + ww) * kI + e]
                     * wv[(dh + 1) * 3 + (dw + 1)];
            }
        best = fmaxf(best, s);
    }
    out[((size_t)(blk * kB + b) * kCtok + pix) * kI + e] = best + bias[(size_t)blk * kI + e];
}

// ---------------- bilinear x2 upsample -> bf16 (both blocks) ----------------
__global__ void upsample_k(const float* __restrict__ vd, __nv_bfloat16* __restrict__ vtok)
{
    int opix = blockIdx.x & 1023;
    int bb = blockIdx.x >> 10;
    int e = threadIdx.x;
    int y = opix >> 5, x = opix & 31;
    int py = y >> 1, px = x >> 1;
    int y0, y1, x0, x1; float wy0, wy1, wx0, wx1;
    if (y & 1) { y0 = py; y1 = min(py + 1, 15); wy0 = 0.75f; wy1 = 0.25f; }
    else       { y0 = max(py - 1, 0); y1 = py;  wy0 = 0.25f; wy1 = 0.75f; }
    if (x & 1) { x0 = px; x1 = min(px + 1, 15); wx0 = 0.75f; wx1 = 0.25f; }
    else       { x0 = max(px - 1, 0); x1 = px;  wx0 = 0.25f; wx1 = 0.75f; }
    const float* base = vd + (size_t)bb * kCtok * kI;
    float r = wy0 * wx0 * base[(size_t)(y0 * 16 + x0) * kI + e]
            + wy0 * wx1 * base[(size_t)(y0 * 16 + x1) * kI + e]
            + wy1 * wx0 * base[(size_t)(y1 * 16 + x0) * kI + e]
            + wy1 * wx1 * base[(size_t)(y1 * 16 + x1) * kI + e];
    vtok[((size_t)bb * kN + opix) * kI + e] = __float2bfloat16(r);
}

// ---------------- launch ----------------
extern "C" void kernel_launch(void* const* d_in, const int* in_sizes, int n_in,
                              void* d_out, int out_size)
{
    const float* hidden     = (const float*)d_in[0];
    const float* context    = (const float*)d_in[1];
    const float* pose       = (const float*)d_in[2];
    const float* Wq         = (const float*)d_in[3];
    const float* Wk         = (const float*)d_in[4];
    const float* Wv         = (const float*)d_in[5];
    const float* Wa         = (const float*)d_in[6];
    const float* agent_bias = (const float*)d_in[7];
    const float* query_bias = (const float*)d_in[8];
    const float* dwc_w      = (const float*)d_in[9];
    const float* dwc_b      = (const float*)d_in[10];
    const float* Wo         = (const float*)d_in[11];
    const float* norm_w     = (const float*)d_in[12];
    const float* norm_b     = (const float*)d_in[13];
    const float* ffln_w     = (const float*)d_in[14];
    const float* ffln_b     = (const float*)d_in[15];
    const float* ff_w1      = (const float*)d_in[16];
    const float* ff_b1      = (const float*)d_in[17];
    const float* ff_w2      = (const float*)d_in[18];
    const float* ff_b2      = (const float*)d_in[19];

    float *hs, *vP, *scoresP, *akvP, *vdP, *vtokWoP, *aqP, *ffb1iP;
    cudaGetSymbolAddress((void**)&hs, g_hs);
    cudaGetSymbolAddress((void**)&vP, g_v);
    cudaGetSymbolAddress((void**)&scoresP, g_scores);
    cudaGetSymbolAddress((void**)&akvP, g_akv);
    cudaGetSymbolAddress((void**)&vdP, g_vdmax);
    cudaGetSymbolAddress((void**)&vtokWoP, g_vtokWo);
    cudaGetSymbolAddress((void**)&aqP, g_aq);
    cudaGetSymbolAddress((void**)&ffb1iP, g_ffb1i);

    __nv_bfloat16 *posetB, *ctxpermB, *ctxB, *WkT, *WvT, *WaN, *WqP, *WoT, *fw1T, *fw2T,
                  *kPB, *vTB, *SB, *GTB, *UB, *scoresB, *akvB, *akvWoT, *aqB, *vtokB, *nhB, *ggB;
    cudaGetSymbolAddress((void**)&posetB, b_poset);
    cudaGetSymbolAddress((void**)&ctxpermB, b_ctxperm);
    cudaGetSymbolAddress((void**)&ctxB, b_ctx);
    cudaGetSymbolAddress((void**)&WkT, b_WkT);
    cudaGetSymbolAddress((void**)&WvT, b_WvT);
    cudaGetSymbolAddress((void**)&WaN, b_Wanat);
    cudaGetSymbolAddress((void**)&WqP, b_Wqpad);
    cudaGetSymbolAddress((void**)&WoT, b_WoT);
    cudaGetSymbolAddress((void**)&fw1T, b_ffw1T);
    cudaGetSymbolAddress((void**)&fw2T, b_ffw2T);
    cudaGetSymbolAddress((void**)&kPB, b_kP);
    cudaGetSymbolAddress((void**)&vTB, b_vT);
    cudaGetSymbolAddress((void**)&SB, b_S);
    cudaGetSymbolAddress((void**)&GTB, b_GT);
    cudaGetSymbolAddress((void**)&UB, b_U);
    cudaGetSymbolAddress((void**)&scoresB, b_scores);
    cudaGetSymbolAddress((void**)&akvB, b_akv);
    cudaGetSymbolAddress((void**)&akvWoT, b_akvWoT);
    cudaGetSymbolAddress((void**)&aqB, b_aq);
    cudaGetSymbolAddress((void**)&vtokB, b_vtok);
    cudaGetSymbolAddress((void**)&nhB, b_nh);
    cudaGetSymbolAddress((void**)&ggB, b_gg);

    const float SCALE = 0.125f;
    auto cdiv = [](long a, long b) { return (int)((a + b - 1) / b); };

    // ===== shared prologue =====
    pcperm_k<<<cdiv(P1_S2, 256), 256>>>(hidden, pose, context, hs, posetB, ctxpermB);
    prep_k<<<cdiv(Q_S8, 256), 256>>>(context, Wk, Wa, Wv, Wq, Wo, ff_w1, ff_b1, ff_w2,
                                     ctxB, WkT, WaN, WvT, WqP, WoT, fw1T, ffb1iP, fw2T);

    // fork: stream 2 runs the hs-side blk0 chain
    cudaEventRecord(g_e0, 0);
    cudaStreamWaitEvent(g_s2, g_e0, 0);

    gemm(WqP, WaN, nullptr, nullptr, nullptr, GTB,
         384, kQ, kI, kI, kI, 0, 384, 0,
         (long)384 * kI, (long)kQ * kI, 0, (long)kQ * 384, 0, 1, 2, 1.f, 16 | 32, g_s2);
    ln_k<<<(int)(kTOK / 8), 256, 0, g_s2>>>(hs, norm_w, norm_b, nhB);
    gemm(nhB, GTB, nullptr, nullptr, nullptr, UB,
         (int)kTOK, kQ, kQ, kQ, 384, 0, kQ, 0,
         0, 0, 0, 0, 0, 1, 1, 1.f, 8 | 32, g_s2);
    gemm(UB, posetB, nullptr, nullptr, aqP, nullptr,
         kN, kN, kQ, kQ, kQ, kN, 0, 0,
         (long)kN * kQ, (long)kN * kQ, (long)kN * kN, 0, 0, 1, kB * kT, SCALE, 0, g_s2);
    softmax_aq_k<<<(int)(kTOK / 8), 256, 0, g_s2>>>(aqP, query_bias, aqB);
    cudaEventRecord(g_e1, g_s2);

    // ===== main stream: kv side, both blocks batched =====
    gemm(ctxpermB, WkT, nullptr, nullptr, nullptr, kPB,
         512, kI, kCD, kCD, kCD, 0, kI, 0,
         512L * kCD, (long)kI * kCD, 0, 512L * kI, 2, 2, 4, 1.f, 8 | 32);
    gemm(kPB, WaN, nullptr, nullptr, nullptr, SB,
         512, kQ, kI, kI, kI, 0, kQ, 0,
         512L * kI, (long)kQ * kI, 0, 512L * kQ, 0, 2, 4, 1.f, 8 | 32);
    gemm(posetB, SB, nullptr, nullptr, scoresP, nullptr,
         kN, 512, kQ, kQ, kQ, 512, 0, 0,
         (long)kN * kQ, 512L * kQ, (long)kN * 512, 0, 32, 16, 64, SCALE, 0);
    softmax_kv_k<<<(int)(2 * kTOK * 2 / 8), 256>>>(scoresP, agent_bias, scoresB);
    gemm(ctxB, WvT, nullptr, nullptr, vP, vTB,
         kCtok, kI, kCD, kCD, kCD, kI, kCtok, 0,
         (long)kCtok * kCD, (long)kI * kCD, (long)kCtok * kI, (long)kI * kCtok, 4, 4, 8, 1.f, 16);
    gemm(scoresB, vTB, nullptr, nullptr, akvP, nullptr,
         kN, kI, kCtok, 512, kCtok, kI, 0, 0,
         (long)kN * 512, (long)kC * kI * kCtok, (long)kN * kI, 0, 0, 16, 64, 1.f, 0);
    gemm(scoresB + 256, vTB + (size_t)kI * kCtok, nullptr, nullptr, akvP, akvB,
         kN, kI, kCtok, 512, kCtok, kI, kI, 0,
         (long)kN * 512, (long)kC * kI * kCtok, (long)kN * kI, (long)kN * kI, 0, 16, 64,
         1.f, 2 | 8 | 32);
    gemm(akvB, WoT, nullptr, nullptr, akvP, akvWoT,
         kN, kQ, kI, kI, kI, kQ, kN, 0,
         (long)kN * kI, (long)kQ * kI, 0, (long)kQ * kN, 0, 32, 64, 1.f, 16 | 32);
    dwconv_k<<<2 * kB * kCtok, kI>>>(vP, dwc_w, dwc_b, vdP);
    upsample_k<<<2 * kB * kN, kI>>>(vdP, vtokB);
    gemm(vtokB, WoT, nullptr, nullptr, vtokWoP, nullptr,
         kN, kQ, kI, kI, kI, kQ, 0, 0,
         (long)kN * kI, (long)kQ * kI, (long)kN * kQ, 0, 0, 2, 4, 1.f, 0);

    // join
    cudaStreamWaitEvent(0, g_e1, 0);

    // ===== Phase B blk0 final, then full blk1 chain =====
    gemm(aqB, akvWoT, nullptr, vtokWoP, hs, nullptr,
         kN, kQ, kN, kN, kN, kQ, 0, kQ,
         (long)kN * kN, (long)kQ * kN, (long)kN * kQ, 0, 0, 1, kB * kT,
         1.f, 1 | 256);

    {
        const __nv_bfloat16* GT_b = GTB + (size_t)kQ * 384;
        const float* qb_b = query_bias + (size_t)kN * kN;
        ln_k<<<(int)(kTOK / 8), 256>>>(hs, norm_w, norm_b, nhB);
        gemm(nhB, GT_b, nullptr, nullptr, nullptr, UB,
             (int)kTOK, kQ, kQ, kQ, 384, 0, kQ, 0,
             0, 0, 0, 0, 0, 1, 1, 1.f, 8 | 32);
        gemm(UB, posetB, nullptr, nullptr, aqP, nullptr,
             kN, kN, kQ, kQ, kQ, kN, 0, 0,
             (long)kN * kQ, (long)kN * kQ, (long)kN * kN, 0, 0, 1, kB * kT, SCALE, 0);
        softmax_aq_k<<<(int)(kTOK / 8), 256>>>(aqP, qb_b, aqB);
        gemm(aqB, akvWoT + (size_t)kB * kT * kQ * kN, nullptr,
             vtokWoP + (size_t)kB * kN * kQ, hs, nullptr,
             kN, kQ, kN, kN, kN, kQ, 0, kQ,
             (long)kN * kN, (long)kQ * kN, (long)kN * kQ, 0, 0, 1, kB * kT,
             1.f, 1 | 256);
    }

    // ---- FF: LN -> fused FF1+GEGLU -> FF2 writes d_out directly ----
    ln_k<<<(int)(kTOK / 8), 256>>>(hs, ffln_w, ffln_b, nhB);
    gemm(nhB, fw1T, ffb1iP, nullptr, nullptr, ggB,
         (int)kTOK, 2 * kFF, kQ, kQ, kQ, 0, kFF, 0,
         0, 0, 0, 0, 0, 1, 1, 1.f, 4 | 32 | 512);
    gemm(ggB, fw2T, ff_b2, nullptr, hs, nullptr,
         (int)kTOK, kQ, kFF, kFF, kFF, kQ, 0, 0,
         0, 0, 0, 0, 0, 1, 1, 1.f, 1 | 4 | 1024, 0, (float*)d_out);
}